// round 6
// baseline (speedup 1.0000x reference)
#include <cuda_runtime.h>
#include <math.h>

#define N_TOK 16384
#define D_MOD 1024
#define H_N   16
#define HK    64
#define M_F   256
#define FF_D  4096
#define S_LEN 4096
#define PHI_SCALE 0.35355339059327373f   // 64^-0.25
#define RSQRT_M  0.0625f                 // 1/sqrt(256)

// ---------------- scratch (device globals; allocation-free) ----------------
__device__ float g_q   [N_TOK * D_MOD];
__device__ float g_k   [N_TOK * D_MOD];
__device__ float g_v   [N_TOK * D_MOD];
__device__ float g_xr  [N_TOK * D_MOD];
__device__ float g_pq  [64 * S_LEN * M_F];
__device__ float g_pk  [64 * S_LEN * M_F];
__device__ float g_kv  [64 * M_F * HK];
__device__ float g_z   [64 * M_F];
__device__ float g_attn[N_TOK * D_MOD];
__device__ float g_y   [N_TOK * D_MOD];
__device__ float g_x1  [N_TOK * D_MOD];
__device__ float g_act [N_TOK * FF_D];
__device__ float g_wqT [D_MOD * D_MOD];
__device__ float g_wkT [D_MOD * D_MOD];
__device__ float g_wvT [D_MOD * D_MOD];
__device__ float g_woT [D_MOD * D_MOD];
__device__ float g_w1T [D_MOD * FF_D];
__device__ float g_w2T [D_MOD * FF_D];

__device__ __forceinline__ unsigned smem_u32(const void* p) {
    unsigned a;
    asm("{ .reg .u64 t; cvta.to.shared.u64 t, %1; cvt.u32.u64 %0, t; }" : "=r"(a) : "l"(p));
    return a;
}
__device__ __forceinline__ float rn_tf32(float f) {
    unsigned u;
    asm("cvt.rn.tf32.f32 %0, %1;" : "=r"(u) : "f"(f));
    return __uint_as_float(u);
}

__device__ __forceinline__ void mma_tf32(float* d, const unsigned* a, const unsigned* b) {
    asm volatile(
        "mma.sync.aligned.m16n8k8.row.col.f32.tf32.tf32.f32 "
        "{%0,%1,%2,%3}, {%4,%5,%6,%7}, {%8,%9}, {%0,%1,%2,%3};"
        : "+f"(d[0]), "+f"(d[1]), "+f"(d[2]), "+f"(d[3])
        : "r"(a[0]), "r"(a[1]), "r"(a[2]), "r"(a[3]), "r"(b[0]), "r"(b[1]));
}

#define CP16(dst, src) \
    asm volatile("cp.async.ca.shared.global [%0], [%1], 16;" :: "r"(dst), "l"(src))
#define CP_COMMIT() asm volatile("cp.async.commit_group;" ::: "memory")
#define CP_WAIT2()  asm volatile("cp.async.wait_group 2;" ::: "memory")
#define CP_WAIT0()  asm volatile("cp.async.wait_group 0;" ::: "memory")

// ---------------- warp-MMA tf32 GEMM: C[M,N] = A[M,Kd] @ BT[N,Kd]^T ----------
// 128x128 CTA tile, 4 warps (warp tile 64x64), K-chunk 32, 3-stage cp.async.
// SMEM stride 36 floats => bank-conflict-free fragment loads.
// EPI: 0 none, 1 +res, 2 gelu(x+bias) [rounded], 3 +bias+res
#define TSTR   36
#define TILEB  (128 * TSTR * 4)          // 18432
#define STAGEB (2 * TILEB)               // 36864
#define SM_DYN (3 * STAGEB)              // 110592

template<int EPI>
__global__ __launch_bounds__(128, 2)
void tc_gemm(const float* __restrict__ A, const float* __restrict__ BT,
             const float* __restrict__ bias, const float* __restrict__ R,
             float* __restrict__ C, int Kd, int NC)
{
    extern __shared__ char sm[];
    unsigned smu = smem_u32(sm);
    int tid = threadIdx.x, wid = tid >> 5, lane = tid & 31;
    int r0 = blockIdx.y * 128, c0 = blockIdx.x * 128;
    int wm = wid & 1, wn = wid >> 1;     // warp tile: rows wm*64, cols wn*64

    const float* Ab = A + (size_t)r0 * Kd;
    const float* Bb = BT + (size_t)c0 * Kd;

    // per-thread copy mapping: u = tid + 128*i ; row = u>>3, seg = u&7 (16B)
    int crow[8], cseg[8];
    unsigned cdst[8];
    #pragma unroll
    for (int i = 0; i < 8; i++) {
        int u = tid + 128 * i;
        crow[i] = u >> 3; cseg[i] = u & 7;
        cdst[i] = smu + (unsigned)(crow[i] * TSTR + cseg[i] * 4) * 4;
    }

    float acc[4][8][4];
    #pragma unroll
    for (int mi = 0; mi < 4; mi++)
        #pragma unroll
        for (int ni = 0; ni < 8; ni++)
            #pragma unroll
            for (int j = 0; j < 4; j++) acc[mi][ni][j] = 0.f;

    int nk = Kd >> 5;

    // prologue: stages 0..2 in flight
    #pragma unroll
    for (int s = 0; s < 3; s++) {
        if (s < nk) {
            const float* Ac = Ab + s * 32;
            const float* Bc = Bb + s * 32;
            unsigned so = s * STAGEB;
            #pragma unroll
            for (int i = 0; i < 8; i++) {
                CP16(cdst[i] + so,         Ac + (size_t)crow[i] * Kd + cseg[i] * 4);
                CP16(cdst[i] + so + TILEB, Bc + (size_t)crow[i] * Kd + cseg[i] * 4);
            }
        }
        CP_COMMIT();
    }

    int kfrag = lane & 3;
    int mrow = wm * 64 + (lane >> 2);
    int nrow = wn * 64 + (lane >> 2);

    int p = 0;
    for (int c = 0; c < nk; c++) {
        CP_WAIT2();
        __syncthreads();

        const unsigned* As = (const unsigned*)(sm + p * STAGEB);
        const unsigned* Bs = (const unsigned*)(sm + p * STAGEB + TILEB);

        #pragma unroll
        for (int ks = 0; ks < 4; ks++) {
            int kk = ks * 8 + kfrag;
            unsigned afr[4][4], bfr[8][2];
            #pragma unroll
            for (int mi = 0; mi < 4; mi++) {
                const unsigned* ap = As + (mrow + mi * 16) * TSTR + kk;
                afr[mi][0] = ap[0];
                afr[mi][1] = ap[8 * TSTR];
                afr[mi][2] = ap[4];
                afr[mi][3] = ap[8 * TSTR + 4];
            }
            #pragma unroll
            for (int ni = 0; ni < 8; ni++) {
                const unsigned* bp = Bs + (nrow + ni * 8) * TSTR + kk;
                bfr[ni][0] = bp[0];
                bfr[ni][1] = bp[4];
            }
            #pragma unroll
            for (int mi = 0; mi < 4; mi++)
                #pragma unroll
                for (int ni = 0; ni < 8; ni++)
                    mma_tf32(acc[mi][ni], afr[mi], bfr[ni]);
        }
        __syncthreads();

        if (c + 3 < nk) {
            const float* Ac = Ab + (c + 3) * 32;
            const float* Bc = Bb + (c + 3) * 32;
            unsigned so = p * STAGEB;
            #pragma unroll
            for (int i = 0; i < 8; i++) {
                CP16(cdst[i] + so,         Ac + (size_t)crow[i] * Kd + cseg[i] * 4);
                CP16(cdst[i] + so + TILEB, Bc + (size_t)crow[i] * Kd + cseg[i] * 4);
            }
        }
        CP_COMMIT();
        p = (p == 2) ? 0 : p + 1;
    }
    CP_WAIT0();
    __syncthreads();

    // epilogue: acc frags -> SMEM stage (stride 132) -> coalesced STG
    float* stage = (float*)sm;
    #pragma unroll
    for (int mi = 0; mi < 4; mi++)
        #pragma unroll
        for (int ni = 0; ni < 8; ni++) {
            int row = wm * 64 + mi * 16 + (lane >> 2);
            int col = wn * 64 + ni * 8 + (lane & 3) * 2;
            *(float2*)(stage + row * 132 + col) =
                make_float2(acc[mi][ni][0], acc[mi][ni][1]);
            *(float2*)(stage + (row + 8) * 132 + col) =
                make_float2(acc[mi][ni][2], acc[mi][ni][3]);
        }
    __syncthreads();

    #pragma unroll
    for (int i = 0; i < 32; i++) {
        int u = tid + 128 * i;
        int row = u >> 5, c4 = u & 31;
        float4 v = *(const float4*)(stage + row * 132 + c4 * 4);
        size_t base = (size_t)(r0 + row) * NC + c0 + c4 * 4;
        float vv[4] = {v.x, v.y, v.z, v.w};
        #pragma unroll
        for (int j = 0; j < 4; j++) {
            int col = c0 + c4 * 4 + j;
            if (EPI == 1) vv[j] += R[base + j];
            else if (EPI == 2) {
                float t = vv[j] + bias[col];
                vv[j] = rn_tf32(0.5f * t * (1.0f + erff(t * 0.70710678118654752f)));
            } else if (EPI == 3) vv[j] += bias[col] + R[base + j];
        }
        *(float4*)(C + base) = make_float4(vv[0], vv[1], vv[2], vv[3]);
    }
}

// ---------------- transpose + tf32-RN round: out[C][R] = rn(in[R][C]^T) ------
__global__ void transpose_k(const float* __restrict__ in, float* __restrict__ out,
                            int R, int Cc)
{
    __shared__ float t[32][33];
    int x = blockIdx.x * 32 + threadIdx.x;
    int y = blockIdx.y * 32 + threadIdx.y;
    #pragma unroll
    for (int j = 0; j < 4; j++)
        t[threadIdx.y + j * 8][threadIdx.x] = in[(size_t)(y + j * 8) * Cc + x];
    __syncthreads();
    int ox = blockIdx.y * 32 + threadIdx.x;
    int oy = blockIdx.x * 32 + threadIdx.y;
    #pragma unroll
    for (int j = 0; j < 4; j++)
        out[(size_t)(oy + j * 8) * R + ox] = rn_tf32(t[threadIdx.x][threadIdx.y + j * 8]);
}

// ---------------- tf32-RN rounding copy ----------------
__global__ void round_kernel(const float* __restrict__ in, float* __restrict__ out, int n4)
{
    int i = blockIdx.x * blockDim.x + threadIdx.x;
    if (i < n4) {
        float4 v = ((const float4*)in)[i];
        ((float4*)out)[i] = make_float4(rn_tf32(v.x), rn_tf32(v.y),
                                        rn_tf32(v.z), rn_tf32(v.w));
    }
}

// ---------------- FAVOR+ feature map (warp per 4 rows) ----------------
__global__ __launch_bounds__(256)
void phi_kernel(const float* __restrict__ src, const float* __restrict__ omega,
                float* __restrict__ dst)
{
    __shared__ float om[64 * 256];   // [k][m]
    int tid = threadIdx.x, wid = tid >> 5, lane = tid & 31;
    for (int i = tid; i < 16384; i += 256) {
        int m = i >> 6, k = i & 63;
        om[k * 256 + m] = omega[i];
    }
    __syncthreads();

    int rowBase = blockIdx.x * 128 + wid * 16;
    for (int g = 0; g < 4; g++) {
        int r0 = rowBase + g * 4;
        float u0[4], u1[4], sq[4];
        #pragma unroll
        for (int rr = 0; rr < 4; rr++) {
            int r = r0 + rr, n = r >> 4, h = r & 15;
            float2 t = *(const float2*)(src + (size_t)n * D_MOD + h * 64 + lane * 2);
            u0[rr] = t.x * PHI_SCALE;
            u1[rr] = t.y * PHI_SCALE;
            float s = u0[rr] * u0[rr] + u1[rr] * u1[rr];
            #pragma unroll
            for (int o = 16; o; o >>= 1) s += __shfl_xor_sync(0xFFFFFFFFu, s, o);
            sq[rr] = 0.5f * s;
        }
        float acc[4][8];
        #pragma unroll
        for (int rr = 0; rr < 4; rr++)
            #pragma unroll
            for (int j = 0; j < 8; j++) acc[rr][j] = 0.f;

        #pragma unroll 4
        for (int k2 = 0; k2 < 32; k2++) {
            float4 wa0 = *(const float4*)&om[(2 * k2) * 256 + lane * 8];
            float4 wa1 = *(const float4*)&om[(2 * k2) * 256 + lane * 8 + 4];
            float4 wb0 = *(const float4*)&om[(2 * k2 + 1) * 256 + lane * 8];
            float4 wb1 = *(const float4*)&om[(2 * k2 + 1) * 256 + lane * 8 + 4];
            #pragma unroll
            for (int rr = 0; rr < 4; rr++) {
                float ua = __shfl_sync(0xFFFFFFFFu, u0[rr], k2);
                float ub = __shfl_sync(0xFFFFFFFFu, u1[rr], k2);
                acc[rr][0] += ua * wa0.x + ub * wb0.x;
                acc[rr][1] += ua * wa0.y + ub * wb0.y;
                acc[rr][2] += ua * wa0.z + ub * wb0.z;
                acc[rr][3] += ua * wa0.w + ub * wb0.w;
                acc[rr][4] += ua * wa1.x + ub * wb1.x;
                acc[rr][5] += ua * wa1.y + ub * wb1.y;
                acc[rr][6] += ua * wa1.z + ub * wb1.z;
                acc[rr][7] += ua * wa1.w + ub * wb1.w;
            }
        }
        #pragma unroll
        for (int rr = 0; rr < 4; rr++) {
            int r = r0 + rr, n = r >> 4, h = r & 15;
            int b = n >> 12, s = n & 4095;
            float mx = acc[rr][0];
            #pragma unroll
            for (int j = 1; j < 8; j++) mx = fmaxf(mx, acc[rr][j]);
            #pragma unroll
            for (int o = 16; o; o >>= 1) mx = fmaxf(mx, __shfl_xor_sync(0xFFFFFFFFu, mx, o));
            float out[8];
            #pragma unroll
            for (int j = 0; j < 8; j++)
                out[j] = __expf(acc[rr][j] - sq[rr] - mx) * RSQRT_M + 1e-6f;
            float* d = dst + (((size_t)(b * H_N + h)) * S_LEN + s) * M_F + lane * 8;
            *(float4*)(d)     = make_float4(out[0], out[1], out[2], out[3]);
            *(float4*)(d + 4) = make_float4(out[4], out[5], out[6], out[7]);
        }
    }
}

// ---------------- kv[m][k] = sum_s pk[s][m] v[s][k]; z[m] = sum_s pk[s][m] ----
__global__ __launch_bounds__(256)
void kv_kernel(const float* __restrict__ pk, const float* __restrict__ v,
               float* __restrict__ kv, float* __restrict__ z)
{
    int bh = blockIdx.x >> 2;
    int chunk = blockIdx.x & 3;
    int b = bh >> 4, h = bh & 15;
    int tid = threadIdx.x;

    __shared__ float pk_s[8][256];
    __shared__ float v_s[8][64];

    float acc[64];
    #pragma unroll
    for (int i = 0; i < 64; i++) acc[i] = 0.f;
    float az = 0.f;

    const float* pkb = pk + ((size_t)bh * S_LEN + chunk * 1024) * M_F;
    const float* vb  = v + ((size_t)(b * S_LEN + chunk * 1024)) * D_MOD + h * 64;

    for (int s0 = 0; s0 < 1024; s0 += 8) {
        #pragma unroll
        for (int i = 0; i < 8; i++)
            pk_s[i][tid] = pkb[(size_t)(s0 + i) * M_F + tid];
        if (tid < 128) {
            int i = tid >> 4, c4 = tid & 15;
            *(float4*)&v_s[i][c4 * 4] =
                *(const float4*)(vb + (size_t)(s0 + i) * D_MOD + c4 * 4);
        }
        __syncthreads();
        #pragma unroll
        for (int i = 0; i < 8; i++) {
            float p = pk_s[i][tid];
            az += p;
            #pragma unroll
            for (int k4 = 0; k4 < 16; k4++) {
                float4 vv = *(const float4*)&v_s[i][k4 * 4];
                acc[k4*4+0] += p * vv.x;
                acc[k4*4+1] += p * vv.y;
                acc[k4*4+2] += p * vv.z;
                acc[k4*4+3] += p * vv.w;
            }
        }
        __syncthreads();
    }

    float* kvp = kv + (size_t)bh * (M_F * HK) + tid * 64;
    #pragma unroll
    for (int k = 0; k < 64; k++) atomicAdd(kvp + k, acc[k]);
    atomicAdd(z + bh * M_F + tid, az);
}

// ---------------- num/den + normalize + head-concat (tf32-rounded out) ------
__global__ __launch_bounds__(256)
void numden_kernel(const float* __restrict__ pq, const float* __restrict__ kvg,
                   const float* __restrict__ zg, float* __restrict__ attn)
{
    extern __shared__ float smf[];
    float* kv_s = smf;
    float* z_s  = smf + 16384;
    float* pq_s = smf + 16640;

    int bh = blockIdx.x >> 4;
    int chunk = blockIdx.x & 15;
    int b = bh >> 4, h = bh & 15;
    int tid = threadIdx.x;

    const float4* kvsrc = (const float4*)(kvg + (size_t)bh * (M_F * HK));
    #pragma unroll
    for (int i = 0; i < 16; i++)
        ((float4*)kv_s)[tid + 256 * i] = kvsrc[tid + 256 * i];
    if (tid < 64)
        ((float4*)z_s)[tid] = ((const float4*)(zg + bh * M_F))[tid];
    __syncthreads();

    int r = tid >> 6, k = tid & 63;
    const float* pqb = pq + ((size_t)bh * S_LEN + chunk * 256) * M_F;

    for (int sg = 0; sg < 64; sg++) {
        ((float4*)pq_s)[tid] =
            *(const float4*)(pqb + (size_t)(sg * 4 + (tid >> 6)) * M_F + (tid & 63) * 4);
        __syncthreads();

        float num = 0.f, den = 0.f;
        const float* prow = pq_s + r * 256;
        #pragma unroll 8
        for (int m4 = 0; m4 < 64; m4++) {
            float4 p  = ((const float4*)prow)[m4];
            float4 zz = ((const float4*)z_s)[m4];
            int mb = m4 * 4;
            num += p.x * kv_s[(mb+0)*64 + k] + p.y * kv_s[(mb+1)*64 + k]
                 + p.z * kv_s[(mb+2)*64 + k] + p.w * kv_s[(mb+3)*64 + k];
            den += p.x * zz.x + p.y * zz.y + p.z * zz.z + p.w * zz.w;
        }
        int s = chunk * 256 + sg * 4 + r;
        attn[((size_t)(b * S_LEN + s)) * D_MOD + h * 64 + k] = rn_tf32(num / den);
        __syncthreads();
    }
}

// ---------------- LayerNorm (RND: tf32-round the output) ----------------
template<int RND>
__global__ void ln_kernel(const float* __restrict__ X, const float* __restrict__ g,
                          const float* __restrict__ bv, float* __restrict__ out)
{
    int row = blockIdx.x, tid = threadIdx.x;
    float4 v = ((const float4*)(X + (size_t)row * D_MOD))[tid];
    float s = v.x + v.y + v.z + v.w;
    __shared__ float ws[8];
    #pragma unroll
    for (int o = 16; o; o >>= 1) s += __shfl_xor_sync(0xFFFFFFFFu, s, o);
    if ((tid & 31) == 0) ws[tid >> 5] = s;
    __syncthreads();
    float tot = 0.f;
    #pragma unroll
    for (int w = 0; w < 8; w++) tot += ws[w];
    float mu = tot * (1.f / 1024.f);
    float dx = v.x - mu, dy = v.y - mu, dz = v.z - mu, dw = v.w - mu;
    float sqv = dx*dx + dy*dy + dz*dz + dw*dw;
    __syncthreads();
    #pragma unroll
    for (int o = 16; o; o >>= 1) sqv += __shfl_xor_sync(0xFFFFFFFFu, sqv, o);
    if ((tid & 31) == 0) ws[tid >> 5] = sqv;
    __syncthreads();
    float tot2 = 0.f;
    #pragma unroll
    for (int w = 0; w < 8; w++) tot2 += ws[w];
    float rs = rsqrtf(tot2 * (1.f / 1024.f) + 1e-6f);
    float4 gg = ((const float4*)g)[tid];
    float4 bb = ((const float4*)bv)[tid];
    float4 o4 = make_float4(dx*rs*gg.x + bb.x, dy*rs*gg.y + bb.y,
                            dz*rs*gg.z + bb.z, dw*rs*gg.w + bb.w);
    if (RND) o4 = make_float4(rn_tf32(o4.x), rn_tf32(o4.y), rn_tf32(o4.z), rn_tf32(o4.w));
    ((float4*)(out + (size_t)row * D_MOD))[tid] = o4;
}

__global__ void zero_kernel(float* p, int n)
{
    int i = blockIdx.x * blockDim.x + threadIdx.x;
    if (i < n) p[i] = 0.f;
}

// ---------------- orchestration ----------------
extern "C" void kernel_launch(void* const* d_in, const int* in_sizes, int n_in,
                              void* d_out, int out_size)
{
    const float* x     = (const float*)d_in[0];
    const float* wq    = (const float*)d_in[1];
    const float* wk    = (const float*)d_in[2];
    const float* wv    = (const float*)d_in[3];
    const float* wo    = (const float*)d_in[4];
    const float* omega = (const float*)d_in[5];
    const float* ln1g  = (const float*)d_in[6];
    const float* ln1b  = (const float*)d_in[7];
    const float* w1    = (const float*)d_in[8];
    const float* b1    = (const float*)d_in[9];
    const float* w2    = (const float*)d_in[10];
    const float* b2    = (const float*)d_in[11];
    const float* ln2g  = (const float*)d_in[12];
    const float* ln2b  = (const float*)d_in[13];
    float* out = (float*)d_out;

    float *q, *k, *v, *xr, *pq, *pk, *kv, *z, *attn, *y, *x1, *act;
    float *wqT, *wkT, *wvT, *woT, *w1T, *w2T;
    cudaGetSymbolAddress((void**)&q,    g_q);
    cudaGetSymbolAddress((void**)&k,    g_k);
    cudaGetSymbolAddress((void**)&v,    g_v);
    cudaGetSymbolAddress((void**)&xr,   g_xr);
    cudaGetSymbolAddress((void**)&pq,   g_pq);
    cudaGetSymbolAddress((void**)&pk,   g_pk);
    cudaGetSymbolAddress((void**)&kv,   g_kv);
    cudaGetSymbolAddress((void**)&z,    g_z);
    cudaGetSymbolAddress((void**)&attn, g_attn);
    cudaGetSymbolAddress((void**)&y,    g_y);
    cudaGetSymbolAddress((void**)&x1,   g_x1);
    cudaGetSymbolAddress((void**)&act,  g_act);
    cudaGetSymbolAddress((void**)&wqT,  g_wqT);
    cudaGetSymbolAddress((void**)&wkT,  g_wkT);
    cudaGetSymbolAddress((void**)&wvT,  g_wvT);
    cudaGetSymbolAddress((void**)&woT,  g_woT);
    cudaGetSymbolAddress((void**)&w1T,  g_w1T);
    cudaGetSymbolAddress((void**)&w2T,  g_w2T);

    cudaFuncSetAttribute(numden_kernel, cudaFuncAttributeMaxDynamicSharedMemorySize, 70656);
    cudaFuncSetAttribute(tc_gemm<0>, cudaFuncAttributeMaxDynamicSharedMemorySize, SM_DYN);
    cudaFuncSetAttribute(tc_gemm<1>, cudaFuncAttributeMaxDynamicSharedMemorySize, SM_DYN);
    cudaFuncSetAttribute(tc_gemm<2>, cudaFuncAttributeMaxDynamicSharedMemorySize, SM_DYN);
    cudaFuncSetAttribute(tc_gemm<3>, cudaFuncAttributeMaxDynamicSharedMemorySize, SM_DYN);

    dim3 tb(32, 8);
    transpose_k<<<dim3(32, 32),   tb>>>(wq, wqT, 1024, 1024);
    transpose_k<<<dim3(32, 32),   tb>>>(wk, wkT, 1024, 1024);
    transpose_k<<<dim3(32, 32),   tb>>>(wv, wvT, 1024, 1024);
    transpose_k<<<dim3(32, 32),   tb>>>(wo, woT, 1024, 1024);
    transpose_k<<<dim3(128, 32),  tb>>>(w1, w1T, 1024, 4096);
    transpose_k<<<dim3(32, 128),  tb>>>(w2, w2T, 4096, 1024);
    round_kernel<<<(N_TOK * D_MOD / 4 + 255) / 256, 256>>>(x, xr, N_TOK * D_MOD / 4);

    dim3 gD(D_MOD / 128, N_TOK / 128);   // (8, 128)
    dim3 gF(FF_D / 128, N_TOK / 128);    // (32, 128)

    tc_gemm<0><<<gD, 128, SM_DYN>>>(xr, wqT, nullptr, nullptr, q, D_MOD, D_MOD);
    tc_gemm<0><<<gD, 128, SM_DYN>>>(xr, wkT, nullptr, nullptr, k, D_MOD, D_MOD);
    tc_gemm<0><<<gD, 128, SM_DYN>>>(xr, wvT, nullptr, nullptr, v, D_MOD, D_MOD);

    phi_kernel<<<2048, 256>>>(q, omega, pq);
    phi_kernel<<<2048, 256>>>(k, omega, pk);

    zero_kernel<<<(64 * M_F * HK + 255) / 256, 256>>>(kv, 64 * M_F * HK);
    zero_kernel<<<(64 * M_F + 255) / 256, 256>>>(z, 64 * M_F);
    kv_kernel<<<256, 256>>>(pk, v, kv, z);

    numden_kernel<<<1024, 256, 70656>>>(pq, kv, z, attn);

    tc_gemm<1><<<gD, 128, SM_DYN>>>(attn, woT, nullptr, x, y, D_MOD, D_MOD);
    ln_kernel<1><<<N_TOK, 256>>>(y, ln1g, ln1b, x1);

    tc_gemm<2><<<gF, 128, SM_DYN>>>(x1, w1T, b1, nullptr, act, D_MOD, FF_D);
    tc_gemm<3><<<gD, 128, SM_DYN>>>(act, w2T, b2, x1, y, FF_D, D_MOD);
    ln_kernel<0><<<N_TOK, 256>>>(y, ln2g, ln2b, out);
}

// round 7
// speedup vs baseline: 1.0653x; 1.0653x over previous
#include <cuda_runtime.h>
#include <math.h>

#define N_TOK 16384
#define D_MOD 1024
#define H_N   16
#define HK    64
#define M_F   256
#define FF_D  4096
#define S_LEN 4096
#define PHI_SCALE 0.35355339059327373f   // 64^-0.25
#define RSQRT_M  0.0625f                 // 1/sqrt(256)

// ---------------- scratch (device globals; allocation-free) ----------------
__device__ float g_q   [N_TOK * D_MOD];
__device__ float g_k   [N_TOK * D_MOD];
__device__ float g_v   [N_TOK * D_MOD];
__device__ float g_xr  [N_TOK * D_MOD];
__device__ float g_pq  [64 * S_LEN * M_F];
__device__ float g_pk  [64 * S_LEN * M_F];
__device__ float g_kv  [64 * M_F * HK];
__device__ float g_z   [64 * M_F];
__device__ float g_attn[N_TOK * D_MOD];
__device__ float g_y   [N_TOK * D_MOD];
__device__ float g_x1  [N_TOK * D_MOD];
__device__ float g_act [N_TOK * FF_D];
__device__ float g_wqT [D_MOD * D_MOD];
__device__ float g_wkT [D_MOD * D_MOD];
__device__ float g_wvT [D_MOD * D_MOD];
__device__ float g_woT [D_MOD * D_MOD];
__device__ float g_w1T [D_MOD * FF_D];
__device__ float g_w2T [D_MOD * FF_D];

__device__ __forceinline__ unsigned smem_u32(const void* p) {
    unsigned a;
    asm("{ .reg .u64 t; cvta.to.shared.u64 t, %1; cvt.u32.u64 %0, t; }" : "=r"(a) : "l"(p));
    return a;
}
__device__ __forceinline__ float rn_tf32(float f) {
    unsigned u;
    asm("cvt.rn.tf32.f32 %0, %1;" : "=r"(u) : "f"(f));
    return __uint_as_float(u);
}

__device__ __forceinline__ void mma_tf32(float* d, const unsigned* a, const unsigned* b) {
    asm volatile(
        "mma.sync.aligned.m16n8k8.row.col.f32.tf32.tf32.f32 "
        "{%0,%1,%2,%3}, {%4,%5,%6,%7}, {%8,%9}, {%0,%1,%2,%3};"
        : "+f"(d[0]), "+f"(d[1]), "+f"(d[2]), "+f"(d[3])
        : "r"(a[0]), "r"(a[1]), "r"(a[2]), "r"(a[3]), "r"(b[0]), "r"(b[1]));
}

#define CP16(dst, src) \
    asm volatile("cp.async.ca.shared.global [%0], [%1], 16;" :: "r"(dst), "l"(src))
#define CP_COMMIT() asm volatile("cp.async.commit_group;" ::: "memory")
#define CP_WAIT2()  asm volatile("cp.async.wait_group 2;" ::: "memory")
#define CP_WAIT0()  asm volatile("cp.async.wait_group 0;" ::: "memory")

// ---------------- warp-MMA tf32 GEMM: C[M,N] = A[M,Kd] @ BT[N,Kd]^T ----------
// 128x128 CTA tile, 8 warps (warp tile 64x32), K-chunk 32, 3-stage cp.async.
// EPI: 0 none, 1 +res, 2 gelu(x+bias) [rounded], 3 +bias+res
#define TSTR   36
#define TILEB  (128 * TSTR * 4)          // 18432
#define STAGEB (2 * TILEB)               // 36864
#define SM_DYN (3 * STAGEB)              // 110592

template<int EPI>
__global__ __launch_bounds__(256, 2)
void tc_gemm(const float* __restrict__ A, const float* __restrict__ BT,
             const float* __restrict__ bias, const float* __restrict__ R,
             float* __restrict__ C, int Kd, int NC)
{
    extern __shared__ char sm[];
    unsigned smu = smem_u32(sm);
    int tid = threadIdx.x, wid = tid >> 5, lane = tid & 31;
    int r0 = blockIdx.y * 128, c0 = blockIdx.x * 128;
    int wm = wid & 1, wn = wid >> 1;     // warp tile: rows wm*64, cols wn*32

    const float* Ab = A + (size_t)r0 * Kd;
    const float* Bb = BT + (size_t)c0 * Kd;

    int crow[4], cseg[4];
    unsigned cdst[4];
    #pragma unroll
    for (int i = 0; i < 4; i++) {
        int u = tid + 256 * i;
        crow[i] = u >> 3; cseg[i] = u & 7;
        cdst[i] = smu + (unsigned)(crow[i] * TSTR + cseg[i] * 4) * 4;
    }

    float acc[4][4][4];
    #pragma unroll
    for (int mi = 0; mi < 4; mi++)
        #pragma unroll
        for (int ni = 0; ni < 4; ni++)
            #pragma unroll
            for (int j = 0; j < 4; j++) acc[mi][ni][j] = 0.f;

    int nk = Kd >> 5;

    #pragma unroll
    for (int s = 0; s < 3; s++) {
        if (s < nk) {
            const float* Ac = Ab + s * 32;
            const float* Bc = Bb + s * 32;
            unsigned so = s * STAGEB;
            #pragma unroll
            for (int i = 0; i < 4; i++) {
                CP16(cdst[i] + so,         Ac + (size_t)crow[i] * Kd + cseg[i] * 4);
                CP16(cdst[i] + so + TILEB, Bc + (size_t)crow[i] * Kd + cseg[i] * 4);
            }
        }
        CP_COMMIT();
    }

    int kfrag = lane & 3;
    int mrow = wm * 64 + (lane >> 2);
    int nrow = wn * 32 + (lane >> 2);

    int p = 0;
    for (int c = 0; c < nk; c++) {
        CP_WAIT2();
        __syncthreads();

        const unsigned* As = (const unsigned*)(sm + p * STAGEB);
        const unsigned* Bs = (const unsigned*)(sm + p * STAGEB + TILEB);

        #pragma unroll
        for (int ks = 0; ks < 4; ks++) {
            int kk = ks * 8 + kfrag;
            unsigned afr[4][4], bfr[4][2];
            #pragma unroll
            for (int mi = 0; mi < 4; mi++) {
                const unsigned* ap = As + (mrow + mi * 16) * TSTR + kk;
                afr[mi][0] = ap[0];
                afr[mi][1] = ap[8 * TSTR];
                afr[mi][2] = ap[4];
                afr[mi][3] = ap[8 * TSTR + 4];
            }
            #pragma unroll
            for (int ni = 0; ni < 4; ni++) {
                const unsigned* bp = Bs + (nrow + ni * 8) * TSTR + kk;
                bfr[ni][0] = bp[0];
                bfr[ni][1] = bp[4];
            }
            #pragma unroll
            for (int mi = 0; mi < 4; mi++)
                #pragma unroll
                for (int ni = 0; ni < 4; ni++)
                    mma_tf32(acc[mi][ni], afr[mi], bfr[ni]);
        }
        __syncthreads();

        if (c + 3 < nk) {
            const float* Ac = Ab + (c + 3) * 32;
            const float* Bc = Bb + (c + 3) * 32;
            unsigned so = p * STAGEB;
            #pragma unroll
            for (int i = 0; i < 4; i++) {
                CP16(cdst[i] + so,         Ac + (size_t)crow[i] * Kd + cseg[i] * 4);
                CP16(cdst[i] + so + TILEB, Bc + (size_t)crow[i] * Kd + cseg[i] * 4);
            }
        }
        CP_COMMIT();
        p = (p == 2) ? 0 : p + 1;
    }
    CP_WAIT0();
    __syncthreads();

    float* stage = (float*)sm;
    #pragma unroll
    for (int mi = 0; mi < 4; mi++)
        #pragma unroll
        for (int ni = 0; ni < 4; ni++) {
            int row = wm * 64 + mi * 16 + (lane >> 2);
            int col = wn * 32 + ni * 8 + (lane & 3) * 2;
            *(float2*)(stage + row * 132 + col) =
                make_float2(acc[mi][ni][0], acc[mi][ni][1]);
            *(float2*)(stage + (row + 8) * 132 + col) =
                make_float2(acc[mi][ni][2], acc[mi][ni][3]);
        }
    __syncthreads();

    #pragma unroll
    for (int i = 0; i < 16; i++) {
        int u = tid + 256 * i;
        int row = u >> 5, c4 = u & 31;
        float4 v = *(const float4*)(stage + row * 132 + c4 * 4);
        size_t base = (size_t)(r0 + row) * NC + c0 + c4 * 4;
        float vv[4] = {v.x, v.y, v.z, v.w};
        #pragma unroll
        for (int j = 0; j < 4; j++) {
            int col = c0 + c4 * 4 + j;
            if (EPI == 1) vv[j] += R[base + j];
            else if (EPI == 2) {
                float t = vv[j] + bias[col];
                vv[j] = rn_tf32(0.5f * t * (1.0f + erff(t * 0.70710678118654752f)));
            } else if (EPI == 3) vv[j] += bias[col] + R[base + j];
        }
        *(float4*)(C + base) = make_float4(vv[0], vv[1], vv[2], vv[3]);
    }
}

// ---------------- transpose + tf32-RN round ----------------
__global__ void transpose_k(const float* __restrict__ in, float* __restrict__ out,
                            int R, int Cc)
{
    __shared__ float t[32][33];
    int x = blockIdx.x * 32 + threadIdx.x;
    int y = blockIdx.y * 32 + threadIdx.y;
    #pragma unroll
    for (int j = 0; j < 4; j++)
        t[threadIdx.y + j * 8][threadIdx.x] = in[(size_t)(y + j * 8) * Cc + x];
    __syncthreads();
    int ox = blockIdx.y * 32 + threadIdx.x;
    int oy = blockIdx.x * 32 + threadIdx.y;
    #pragma unroll
    for (int j = 0; j < 4; j++)
        out[(size_t)(oy + j * 8) * R + ox] = rn_tf32(t[threadIdx.x][threadIdx.y + j * 8]);
}

__global__ void round_kernel(const float* __restrict__ in, float* __restrict__ out, int n4)
{
    int i = blockIdx.x * blockDim.x + threadIdx.x;
    if (i < n4) {
        float4 v = ((const float4*)in)[i];
        ((float4*)out)[i] = make_float4(rn_tf32(v.x), rn_tf32(v.y),
                                        rn_tf32(v.z), rn_tf32(v.w));
    }
}

// ---------------- tensorized FAVOR+: proj via MMA, exp epilogue --------------
// CTA: 128 rows x all 256 m-cols, K=64. 512 threads, 16 warps (32x64 tiles).
// SMEM: A[128][68] u32 | B[256][68] u32 ; epilogue stage[128][260] f32 aliases; sq at end.
#define PASTR 68
#define PHI_A_OFF 0
#define PHI_B_OFF (128 * PASTR * 4)                 // 34816
#define PHI_STAGE_W 260
#define PHI_SQ_OFF  (128 * PHI_STAGE_W * 4)         // 133120
#define PHI_SM      (PHI_SQ_OFF + 128 * 4)          // 133632

__global__ __launch_bounds__(512, 1)
void phi_mma(const float* __restrict__ src, const float* __restrict__ omega,
             float* __restrict__ dst)
{
    extern __shared__ char sm[];
    unsigned* As = (unsigned*)(sm + PHI_A_OFF);
    unsigned* Bs = (unsigned*)(sm + PHI_B_OFF);
    float* stage = (float*)sm;
    float* sqv   = (float*)(sm + PHI_SQ_OFF);

    int tid = threadIdx.x, wid = tid >> 5, lane = tid & 31;
    int rbase = blockIdx.x * 128;

    // fill A: u = rn(q*scale), row-major [128][68]; sq[row] = 0.5*sum(u^2)
    {
        int row = tid >> 2, qtr = tid & 3;
        int r = rbase + row, n = r >> 4, h = r & 15;
        const float* srow = src + (size_t)n * D_MOD + h * 64 + qtr * 16;
        float ps = 0.f;
        #pragma unroll
        for (int j = 0; j < 4; j++) {
            float4 v = ((const float4*)srow)[j];
            float ux = rn_tf32(v.x * PHI_SCALE);
            float uy = rn_tf32(v.y * PHI_SCALE);
            float uz = rn_tf32(v.z * PHI_SCALE);
            float uw = rn_tf32(v.w * PHI_SCALE);
            ps += ux * ux + uy * uy + uz * uz + uw * uw;
            *(uint4*)(As + row * PASTR + qtr * 16 + j * 4) = make_uint4(
                __float_as_uint(ux), __float_as_uint(uy),
                __float_as_uint(uz), __float_as_uint(uw));
        }
        ps += __shfl_xor_sync(0xFFFFFFFFu, ps, 1);
        ps += __shfl_xor_sync(0xFFFFFFFFu, ps, 2);
        if (qtr == 0) sqv[row] = 0.5f * ps;
    }
    // fill B: rn(omega[m][k]), row-major [256][68]
    {
        int m = tid >> 1, half = tid & 1;
        const float* orow = omega + m * 64 + half * 32;
        #pragma unroll
        for (int j = 0; j < 8; j++) {
            float4 v = ((const float4*)orow)[j];
            *(uint4*)(Bs + m * PASTR + half * 32 + j * 4) = make_uint4(
                __float_as_uint(rn_tf32(v.x)), __float_as_uint(rn_tf32(v.y)),
                __float_as_uint(rn_tf32(v.z)), __float_as_uint(rn_tf32(v.w)));
        }
    }
    __syncthreads();

    // mma: warp (wid&3) -> rows (wid&3)*32 ; (wid>>2) -> cols (wid>>2)*64
    float acc[2][8][4];
    #pragma unroll
    for (int mi = 0; mi < 2; mi++)
        #pragma unroll
        for (int ni = 0; ni < 8; ni++)
            #pragma unroll
            for (int j = 0; j < 4; j++) acc[mi][ni][j] = 0.f;

    int kfrag = lane & 3;
    int mrow = (wid & 3) * 32 + (lane >> 2);
    int nrow = (wid >> 2) * 64 + (lane >> 2);

    #pragma unroll
    for (int ks = 0; ks < 8; ks++) {
        int kk = ks * 8 + kfrag;
        unsigned afr[2][4], bfr[8][2];
        #pragma unroll
        for (int mi = 0; mi < 2; mi++) {
            const unsigned* ap = As + (mrow + mi * 16) * PASTR + kk;
            afr[mi][0] = ap[0];
            afr[mi][1] = ap[8 * PASTR];
            afr[mi][2] = ap[4];
            afr[mi][3] = ap[8 * PASTR + 4];
        }
        #pragma unroll
        for (int ni = 0; ni < 8; ni++) {
            const unsigned* bp = Bs + (nrow + ni * 8) * PASTR + kk;
            bfr[ni][0] = bp[0];
            bfr[ni][1] = bp[4];
        }
        #pragma unroll
        for (int mi = 0; mi < 2; mi++)
            #pragma unroll
            for (int ni = 0; ni < 8; ni++)
                mma_tf32(acc[mi][ni], afr[mi], bfr[ni]);
    }
    __syncthreads();   // A/B dead; stage aliases them

    #pragma unroll
    for (int mi = 0; mi < 2; mi++)
        #pragma unroll
        for (int ni = 0; ni < 8; ni++) {
            int row = (wid & 3) * 32 + mi * 16 + (lane >> 2);
            int col = (wid >> 2) * 64 + ni * 8 + (lane & 3) * 2;
            *(float2*)(stage + row * PHI_STAGE_W + col) =
                make_float2(acc[mi][ni][0], acc[mi][ni][1]);
            *(float2*)(stage + (row + 8) * PHI_STAGE_W + col) =
                make_float2(acc[mi][ni][2], acc[mi][ni][3]);
        }
    __syncthreads();

    // epilogue: 4 threads per row, 64 cols each: row max, exp, store
    {
        int row = tid >> 2, seg = (tid & 3) * 64;
        const float* srow = stage + row * PHI_STAGE_W + seg;
        float mx = -1e30f;
        #pragma unroll
        for (int j = 0; j < 16; j++) {
            float4 v = ((const float4*)srow)[j];
            mx = fmaxf(mx, fmaxf(fmaxf(v.x, v.y), fmaxf(v.z, v.w)));
        }
        mx = fmaxf(mx, __shfl_xor_sync(0xFFFFFFFFu, mx, 1));
        mx = fmaxf(mx, __shfl_xor_sync(0xFFFFFFFFu, mx, 2));
        float sb = sqv[row] + mx;

        int r = rbase + row, n = r >> 4, h = r & 15;
        int b = n >> 12, s = n & 4095;
        float* drow = dst + (((size_t)(b * H_N + h)) * S_LEN + s) * M_F + seg;
        #pragma unroll
        for (int j = 0; j < 16; j++) {
            float4 v = ((const float4*)srow)[j];
            ((float4*)drow)[j] = make_float4(
                __expf(v.x - sb) * RSQRT_M + 1e-6f,
                __expf(v.y - sb) * RSQRT_M + 1e-6f,
                __expf(v.z - sb) * RSQRT_M + 1e-6f,
                __expf(v.w - sb) * RSQRT_M + 1e-6f);
        }
    }
}

// ---------------- kv[m][k] = sum_s pk[s][m] v[s][k]; z[m] = sum_s pk[s][m] ----
__global__ __launch_bounds__(256)
void kv_kernel(const float* __restrict__ pk, const float* __restrict__ v,
               float* __restrict__ kv, float* __restrict__ z)
{
    int bh = blockIdx.x >> 2;
    int chunk = blockIdx.x & 3;
    int b = bh >> 4, h = bh & 15;
    int tid = threadIdx.x;

    __shared__ float pk_s[8][256];
    __shared__ float v_s[8][64];

    float acc[64];
    #pragma unroll
    for (int i = 0; i < 64; i++) acc[i] = 0.f;
    float az = 0.f;

    const float* pkb = pk + ((size_t)bh * S_LEN + chunk * 1024) * M_F;
    const float* vb  = v + ((size_t)(b * S_LEN + chunk * 1024)) * D_MOD + h * 64;

    for (int s0 = 0; s0 < 1024; s0 += 8) {
        #pragma unroll
        for (int i = 0; i < 8; i++)
            pk_s[i][tid] = pkb[(size_t)(s0 + i) * M_F + tid];
        if (tid < 128) {
            int i = tid >> 4, c4 = tid & 15;
            *(float4*)&v_s[i][c4 * 4] =
                *(const float4*)(vb + (size_t)(s0 + i) * D_MOD + c4 * 4);
        }
        __syncthreads();
        #pragma unroll
        for (int i = 0; i < 8; i++) {
            float p = pk_s[i][tid];
            az += p;
            #pragma unroll
            for (int k4 = 0; k4 < 16; k4++) {
                float4 vv = *(const float4*)&v_s[i][k4 * 4];
                acc[k4*4+0] += p * vv.x;
                acc[k4*4+1] += p * vv.y;
                acc[k4*4+2] += p * vv.z;
                acc[k4*4+3] += p * vv.w;
            }
        }
        __syncthreads();
    }

    float* kvp = kv + (size_t)bh * (M_F * HK) + tid * 64;
    #pragma unroll
    for (int k = 0; k < 64; k++) atomicAdd(kvp + k, acc[k]);
    atomicAdd(z + bh * M_F + tid, az);
}

// ---------------- num/den + normalize + head-concat (tf32-rounded out) ------
__global__ __launch_bounds__(256)
void numden_kernel(const float* __restrict__ pq, const float* __restrict__ kvg,
                   const float* __restrict__ zg, float* __restrict__ attn)
{
    extern __shared__ float smf[];
    float* kv_s = smf;
    float* z_s  = smf + 16384;
    float* pq_s = smf + 16640;

    int bh = blockIdx.x >> 4;
    int chunk = blockIdx.x & 15;
    int b = bh >> 4, h = bh & 15;
    int tid = threadIdx.x;

    const float4* kvsrc = (const float4*)(kvg + (size_t)bh * (M_F * HK));
    #pragma unroll
    for (int i = 0; i < 16; i++)
        ((float4*)kv_s)[tid + 256 * i] = kvsrc[tid + 256 * i];
    if (tid < 64)
        ((float4*)z_s)[tid] = ((const float4*)(zg + bh * M_F))[tid];
    __syncthreads();

    int r = tid >> 6, k = tid & 63;
    const float* pqb = pq + ((size_t)bh * S_LEN + chunk * 256) * M_F;

    for (int sg = 0; sg < 64; sg++) {
        ((float4*)pq_s)[tid] =
            *(const float4*)(pqb + (size_t)(sg * 4 + (tid >> 6)) * M_F + (tid & 63) * 4);
        __syncthreads();

        float num = 0.f, den = 0.f;
        const float* prow = pq_s + r * 256;
        #pragma unroll 8
        for (int m4 = 0; m4 < 64; m4++) {
            float4 p  = ((const float4*)prow)[m4];
            float4 zz = ((const float4*)z_s)[m4];
            int mb = m4 * 4;
            num += p.x * kv_s[(mb+0)*64 + k] + p.y * kv_s[(mb+1)*64 + k]
                 + p.z * kv_s[(mb+2)*64 + k] + p.w * kv_s[(mb+3)*64 + k];
            den += p.x * zz.x + p.y * zz.y + p.z * zz.z + p.w * zz.w;
        }
        int s = chunk * 256 + sg * 4 + r;
        attn[((size_t)(b * S_LEN + s)) * D_MOD + h * 64 + k] = rn_tf32(num / den);
        __syncthreads();
    }
}

// ---------------- LayerNorm ----------------
template<int RND>
__global__ void ln_kernel(const float* __restrict__ X, const float* __restrict__ g,
                          const float* __restrict__ bv, float* __restrict__ out)
{
    int row = blockIdx.x, tid = threadIdx.x;
    float4 v = ((const float4*)(X + (size_t)row * D_MOD))[tid];
    float s = v.x + v.y + v.z + v.w;
    __shared__ float ws[8];
    #pragma unroll
    for (int o = 16; o; o >>= 1) s += __shfl_xor_sync(0xFFFFFFFFu, s, o);
    if ((tid & 31) == 0) ws[tid >> 5] = s;
    __syncthreads();
    float tot = 0.f;
    #pragma unroll
    for (int w = 0; w < 8; w++) tot += ws[w];
    float mu = tot * (1.f / 1024.f);
    float dx = v.x - mu, dy = v.y - mu, dz = v.z - mu, dw = v.w - mu;
    float sqvv = dx*dx + dy*dy + dz*dz + dw*dw;
    __syncthreads();
    #pragma unroll
    for (int o = 16; o; o >>= 1) sqvv += __shfl_xor_sync(0xFFFFFFFFu, sqvv, o);
    if ((tid & 31) == 0) ws[tid >> 5] = sqvv;
    __syncthreads();
    float tot2 = 0.f;
    #pragma unroll
    for (int w = 0; w < 8; w++) tot2 += ws[w];
    float rs = rsqrtf(tot2 * (1.f / 1024.f) + 1e-6f);
    float4 gg = ((const float4*)g)[tid];
    float4 bb = ((const float4*)bv)[tid];
    float4 o4 = make_float4(dx*rs*gg.x + bb.x, dy*rs*gg.y + bb.y,
                            dz*rs*gg.z + bb.z, dw*rs*gg.w + bb.w);
    if (RND) o4 = make_float4(rn_tf32(o4.x), rn_tf32(o4.y), rn_tf32(o4.z), rn_tf32(o4.w));
    ((float4*)(out + (size_t)row * D_MOD))[tid] = o4;
}

__global__ void zero_kernel(float* p, int n)
{
    int i = blockIdx.x * blockDim.x + threadIdx.x;
    if (i < n) p[i] = 0.f;
}

// ---------------- orchestration ----------------
extern "C" void kernel_launch(void* const* d_in, const int* in_sizes, int n_in,
                              void* d_out, int out_size)
{
    const float* x     = (const float*)d_in[0];
    const float* wq    = (const float*)d_in[1];
    const float* wk    = (const float*)d_in[2];
    const float* wv    = (const float*)d_in[3];
    const float* wo    = (const float*)d_in[4];
    const float* omega = (const float*)d_in[5];
    const float* ln1g  = (const float*)d_in[6];
    const float* ln1b  = (const float*)d_in[7];
    const float* w1    = (const float*)d_in[8];
    const float* b1    = (const float*)d_in[9];
    const float* w2    = (const float*)d_in[10];
    const float* b2    = (const float*)d_in[11];
    const float* ln2g  = (const float*)d_in[12];
    const float* ln2b  = (const float*)d_in[13];
    float* out = (float*)d_out;

    float *q, *k, *v, *xr, *pq, *pk, *kv, *z, *attn, *y, *x1, *act;
    float *wqT, *wkT, *wvT, *woT, *w1T, *w2T;
    cudaGetSymbolAddress((void**)&q,    g_q);
    cudaGetSymbolAddress((void**)&k,    g_k);
    cudaGetSymbolAddress((void**)&v,    g_v);
    cudaGetSymbolAddress((void**)&xr,   g_xr);
    cudaGetSymbolAddress((void**)&pq,   g_pq);
    cudaGetSymbolAddress((void**)&pk,   g_pk);
    cudaGetSymbolAddress((void**)&kv,   g_kv);
    cudaGetSymbolAddress((void**)&z,    g_z);
    cudaGetSymbolAddress((void**)&attn, g_attn);
    cudaGetSymbolAddress((void**)&y,    g_y);
    cudaGetSymbolAddress((void**)&x1,   g_x1);
    cudaGetSymbolAddress((void**)&act,  g_act);
    cudaGetSymbolAddress((void**)&wqT,  g_wqT);
    cudaGetSymbolAddress((void**)&wkT,  g_wkT);
    cudaGetSymbolAddress((void**)&wvT,  g_wvT);
    cudaGetSymbolAddress((void**)&woT,  g_woT);
    cudaGetSymbolAddress((void**)&w1T,  g_w1T);
    cudaGetSymbolAddress((void**)&w2T,  g_w2T);

    cudaFuncSetAttribute(numden_kernel, cudaFuncAttributeMaxDynamicSharedMemorySize, 70656);
    cudaFuncSetAttribute(phi_mma, cudaFuncAttributeMaxDynamicSharedMemorySize, PHI_SM);
    cudaFuncSetAttribute(tc_gemm<0>, cudaFuncAttributeMaxDynamicSharedMemorySize, SM_DYN);
    cudaFuncSetAttribute(tc_gemm<1>, cudaFuncAttributeMaxDynamicSharedMemorySize, SM_DYN);
    cudaFuncSetAttribute(tc_gemm<2>, cudaFuncAttributeMaxDynamicSharedMemorySize, SM_DYN);
    cudaFuncSetAttribute(tc_gemm<3>, cudaFuncAttributeMaxDynamicSharedMemorySize, SM_DYN);

    dim3 tb(32, 8);
    transpose_k<<<dim3(32, 32),   tb>>>(wq, wqT, 1024, 1024);
    transpose_k<<<dim3(32, 32),   tb>>>(wk, wkT, 1024, 1024);
    transpose_k<<<dim3(32, 32),   tb>>>(wv, wvT, 1024, 1024);
    transpose_k<<<dim3(32, 32),   tb>>>(wo, woT, 1024, 1024);
    transpose_k<<<dim3(128, 32),  tb>>>(w1, w1T, 1024, 4096);
    transpose_k<<<dim3(32, 128),  tb>>>(w2, w2T, 4096, 1024);
    round_kernel<<<(N_TOK * D_MOD / 4 + 255) / 256, 256>>>(x, xr, N_TOK * D_MOD / 4);

    dim3 gD(D_MOD / 128, N_TOK / 128);   // (8, 128)
    dim3 gF(FF_D / 128, N_TOK / 128);    // (32, 128)

    tc_gemm<0><<<gD, 256, SM_DYN>>>(xr, wqT, nullptr, nullptr, q, D_MOD, D_MOD);
    tc_gemm<0><<<gD, 256, SM_DYN>>>(xr, wkT, nullptr, nullptr, k, D_MOD, D_MOD);
    tc_gemm<0><<<gD, 256, SM_DYN>>>(xr, wvT, nullptr, nullptr, v, D_MOD, D_MOD);

    phi_mma<<<2048, 512, PHI_SM>>>(q, omega, pq);
    phi_mma<<<2048, 512, PHI_SM>>>(k, omega, pk);

    zero_kernel<<<(64 * M_F * HK + 255) / 256, 256>>>(kv, 64 * M_F * HK);
    zero_kernel<<<(64 * M_F + 255) / 256, 256>>>(z, 64 * M_F);
    kv_kernel<<<256, 256>>>(pk, v, kv, z);

    numden_kernel<<<1024, 256, 70656>>>(pq, kv, z, attn);

    tc_gemm<1><<<gD, 256, SM_DYN>>>(attn, woT, nullptr, x, y, D_MOD, D_MOD);
    ln_kernel<1><<<N_TOK, 256>>>(y, ln1g, ln1b, x1);

    tc_gemm<2><<<gF, 256, SM_DYN>>>(x1, w1T, b1, nullptr, act, D_MOD, FF_D);
    tc_gemm<3><<<gD, 256, SM_DYN>>>(act, w2T, b2, x1, y, FF_D, D_MOD);
    ln_kernel<0><<<N_TOK, 256>>>(y, ln2g, ln2b, out);
}

// round 8
// speedup vs baseline: 1.2987x; 1.2191x over previous
#include <cuda_runtime.h>
#include <math.h>

#define N_TOK 16384
#define D_MOD 1024
#define H_N   16
#define HK    64
#define M_F   256
#define FF_D  4096
#define S_LEN 4096
#define PHI_SCALE 0.35355339059327373f   // 64^-0.25
#define RSQRT_M  0.0625f                 // 1/sqrt(256)

// ---------------- scratch (device globals; allocation-free) ----------------
__device__ float g_q   [N_TOK * D_MOD];
__device__ float g_k   [N_TOK * D_MOD];
__device__ float g_v   [N_TOK * D_MOD];
__device__ float g_xr  [N_TOK * D_MOD];
__device__ float g_pq  [64 * S_LEN * M_F];
__device__ float g_pk  [64 * S_LEN * M_F];
__device__ float g_kv  [64 * M_F * HK];
__device__ float g_z   [64 * M_F];
__device__ float g_attn[N_TOK * D_MOD];
__device__ float g_y   [N_TOK * D_MOD];
__device__ float g_x1  [N_TOK * D_MOD];
__device__ float g_act [N_TOK * FF_D];
__device__ float g_wqT [D_MOD * D_MOD];
__device__ float g_wkT [D_MOD * D_MOD];
__device__ float g_wvT [D_MOD * D_MOD];
__device__ float g_woT [D_MOD * D_MOD];
__device__ float g_w1T [D_MOD * FF_D];
__device__ float g_w2T [D_MOD * FF_D];

__device__ __forceinline__ unsigned smem_u32(const void* p) {
    unsigned a;
    asm("{ .reg .u64 t; cvta.to.shared.u64 t, %1; cvt.u32.u64 %0, t; }" : "=r"(a) : "l"(p));
    return a;
}
__device__ __forceinline__ float rn_tf32(float f) {
    unsigned u;
    asm("cvt.rn.tf32.f32 %0, %1;" : "=r"(u) : "f"(f));
    return __uint_as_float(u);
}

__device__ __forceinline__ void mma_tf32(float* d, const unsigned* a, const unsigned* b) {
    asm volatile(
        "mma.sync.aligned.m16n8k8.row.col.f32.tf32.tf32.f32 "
        "{%0,%1,%2,%3}, {%4,%5,%6,%7}, {%8,%9}, {%0,%1,%2,%3};"
        : "+f"(d[0]), "+f"(d[1]), "+f"(d[2]), "+f"(d[3])
        : "r"(a[0]), "r"(a[1]), "r"(a[2]), "r"(a[3]), "r"(b[0]), "r"(b[1]));
}

#define CP16(dst, src) \
    asm volatile("cp.async.ca.shared.global [%0], [%1], 16;" :: "r"(dst), "l"(src))
#define CP_COMMIT() asm volatile("cp.async.commit_group;" ::: "memory")
#define CP_WAIT1()  asm volatile("cp.async.wait_group 1;" ::: "memory")
#define CP_WAIT0()  asm volatile("cp.async.wait_group 0;" ::: "memory")

// ---------------- warp-MMA tf32 GEMM: C[M,N] = A[M,Kd] @ BT[N,Kd]^T ----------
// 128x128 CTA tile, 8 warps (64x32 warp tile), K-chunk 32.
// 3 buffers, prefetch depth 2, ONE sync per chunk.
#define TSTR   36
#define TILEB  (128 * TSTR * 4)          // 18432
#define STAGEB (2 * TILEB)               // 36864
#define SM_DYN (3 * STAGEB)              // 110592

template<int EPI>
__global__ __launch_bounds__(256, 2)
void tc_gemm(const float* __restrict__ A, const float* __restrict__ BT,
             const float* __restrict__ bias, const float* __restrict__ R,
             float* __restrict__ C, int Kd, int NC)
{
    extern __shared__ char sm[];
    unsigned smu = smem_u32(sm);
    int tid = threadIdx.x, wid = tid >> 5, lane = tid & 31;
    int r0 = blockIdx.y * 128, c0 = blockIdx.x * 128;
    int wm = wid & 1, wn = wid >> 1;

    const float* Ab = A + (size_t)r0 * Kd;
    const float* Bb = BT + (size_t)c0 * Kd;

    int crow[4], cseg[4];
    unsigned cdst[4];
    #pragma unroll
    for (int i = 0; i < 4; i++) {
        int u = tid + 256 * i;
        crow[i] = u >> 3; cseg[i] = u & 7;
        cdst[i] = smu + (unsigned)(crow[i] * TSTR + cseg[i] * 4) * 4;
    }

    float acc[4][4][4];
    #pragma unroll
    for (int mi = 0; mi < 4; mi++)
        #pragma unroll
        for (int ni = 0; ni < 4; ni++)
            #pragma unroll
            for (int j = 0; j < 4; j++) acc[mi][ni][j] = 0.f;

    int nk = Kd >> 5;

    // prologue: chunks 0,1 into slots 0,1
    #pragma unroll
    for (int s = 0; s < 2; s++) {
        const float* Ac = Ab + s * 32;
        const float* Bc = Bb + s * 32;
        unsigned so = s * STAGEB;
        #pragma unroll
        for (int i = 0; i < 4; i++) {
            CP16(cdst[i] + so,         Ac + (size_t)crow[i] * Kd + cseg[i] * 4);
            CP16(cdst[i] + so + TILEB, Bc + (size_t)crow[i] * Kd + cseg[i] * 4);
        }
        CP_COMMIT();
    }

    int kfrag = lane & 3;
    int mrow = wm * 64 + (lane >> 2);
    int nrow = wn * 32 + (lane >> 2);

    int p = 0, pn = 2;
    for (int c = 0; c < nk; c++) {
        CP_WAIT1();
        __syncthreads();

        // issue copy for chunk c+2 into slot (c+2)%3 (free: computed at iter c-1)
        if (c + 2 < nk) {
            const float* Ac = Ab + (c + 2) * 32;
            const float* Bc = Bb + (c + 2) * 32;
            unsigned so = pn * STAGEB;
            #pragma unroll
            for (int i = 0; i < 4; i++) {
                CP16(cdst[i] + so,         Ac + (size_t)crow[i] * Kd + cseg[i] * 4);
                CP16(cdst[i] + so + TILEB, Bc + (size_t)crow[i] * Kd + cseg[i] * 4);
            }
        }
        CP_COMMIT();

        const unsigned* As = (const unsigned*)(sm + p * STAGEB);
        const unsigned* Bs = (const unsigned*)(sm + p * STAGEB + TILEB);

        #pragma unroll
        for (int ks = 0; ks < 4; ks++) {
            int kk = ks * 8 + kfrag;
            unsigned afr[4][4], bfr[4][2];
            #pragma unroll
            for (int mi = 0; mi < 4; mi++) {
                const unsigned* ap = As + (mrow + mi * 16) * TSTR + kk;
                afr[mi][0] = ap[0];
                afr[mi][1] = ap[8 * TSTR];
                afr[mi][2] = ap[4];
                afr[mi][3] = ap[8 * TSTR + 4];
            }
            #pragma unroll
            for (int ni = 0; ni < 4; ni++) {
                const unsigned* bp = Bs + (nrow + ni * 8) * TSTR + kk;
                bfr[ni][0] = bp[0];
                bfr[ni][1] = bp[4];
            }
            #pragma unroll
            for (int mi = 0; mi < 4; mi++)
                #pragma unroll
                for (int ni = 0; ni < 4; ni++)
                    mma_tf32(acc[mi][ni], afr[mi], bfr[ni]);
        }
        p = (p == 2) ? 0 : p + 1;
        pn = (pn == 2) ? 0 : pn + 1;
    }
    CP_WAIT0();
    __syncthreads();

    float* stage = (float*)sm;
    #pragma unroll
    for (int mi = 0; mi < 4; mi++)
        #pragma unroll
        for (int ni = 0; ni < 4; ni++) {
            int row = wm * 64 + mi * 16 + (lane >> 2);
            int col = wn * 32 + ni * 8 + (lane & 3) * 2;
            *(float2*)(stage + row * 132 + col) =
                make_float2(acc[mi][ni][0], acc[mi][ni][1]);
            *(float2*)(stage + (row + 8) * 132 + col) =
                make_float2(acc[mi][ni][2], acc[mi][ni][3]);
        }
    __syncthreads();

    #pragma unroll
    for (int i = 0; i < 16; i++) {
        int u = tid + 256 * i;
        int row = u >> 5, c4 = u & 31;
        float4 v = *(const float4*)(stage + row * 132 + c4 * 4);
        size_t base = (size_t)(r0 + row) * NC + c0 + c4 * 4;
        float vv[4] = {v.x, v.y, v.z, v.w};
        #pragma unroll
        for (int j = 0; j < 4; j++) {
            int col = c0 + c4 * 4 + j;
            if (EPI == 1) vv[j] += R[base + j];
            else if (EPI == 2) {
                float t = vv[j] + bias[col];
                vv[j] = rn_tf32(0.5f * t * (1.0f + erff(t * 0.70710678118654752f)));
            } else if (EPI == 3) vv[j] += bias[col] + R[base + j];
        }
        *(float4*)(C + base) = make_float4(vv[0], vv[1], vv[2], vv[3]);
    }
}

// ---------------- transpose + tf32-RN round ----------------
__global__ void transpose_k(const float* __restrict__ in, float* __restrict__ out,
                            int R, int Cc)
{
    __shared__ float t[32][33];
    int x = blockIdx.x * 32 + threadIdx.x;
    int y = blockIdx.y * 32 + threadIdx.y;
    #pragma unroll
    for (int j = 0; j < 4; j++)
        t[threadIdx.y + j * 8][threadIdx.x] = in[(size_t)(y + j * 8) * Cc + x];
    __syncthreads();
    int ox = blockIdx.y * 32 + threadIdx.x;
    int oy = blockIdx.x * 32 + threadIdx.y;
    #pragma unroll
    for (int j = 0; j < 4; j++)
        out[(size_t)(oy + j * 8) * R + ox] = rn_tf32(t[threadIdx.x][threadIdx.y + j * 8]);
}

__global__ void round_kernel(const float* __restrict__ in, float* __restrict__ out, int n4)
{
    int i = blockIdx.x * blockDim.x + threadIdx.x;
    if (i < n4) {
        float4 v = ((const float4*)in)[i];
        ((float4*)out)[i] = make_float4(rn_tf32(v.x), rn_tf32(v.y),
                                        rn_tf32(v.z), rn_tf32(v.w));
    }
}

// ---------------- tensorized FAVOR+ (output RN-rounded to tf32) -------------
#define PASTR 68
#define PHI_A_OFF 0
#define PHI_B_OFF (128 * PASTR * 4)
#define PHI_STAGE_W 260
#define PHI_SQ_OFF  (128 * PHI_STAGE_W * 4)
#define PHI_SM      (PHI_SQ_OFF + 128 * 4)

__global__ __launch_bounds__(512, 1)
void phi_mma(const float* __restrict__ src, const float* __restrict__ omega,
             float* __restrict__ dst)
{
    extern __shared__ char sm[];
    unsigned* As = (unsigned*)(sm + PHI_A_OFF);
    unsigned* Bs = (unsigned*)(sm + PHI_B_OFF);
    float* stage = (float*)sm;
    float* sqv   = (float*)(sm + PHI_SQ_OFF);

    int tid = threadIdx.x, wid = tid >> 5, lane = tid & 31;
    int rbase = blockIdx.x * 128;

    {
        int row = tid >> 2, qtr = tid & 3;
        int r = rbase + row, n = r >> 4, h = r & 15;
        const float* srow = src + (size_t)n * D_MOD + h * 64 + qtr * 16;
        float ps = 0.f;
        #pragma unroll
        for (int j = 0; j < 4; j++) {
            float4 v = ((const float4*)srow)[j];
            float ux = rn_tf32(v.x * PHI_SCALE);
            float uy = rn_tf32(v.y * PHI_SCALE);
            float uz = rn_tf32(v.z * PHI_SCALE);
            float uw = rn_tf32(v.w * PHI_SCALE);
            ps += ux * ux + uy * uy + uz * uz + uw * uw;
            *(uint4*)(As + row * PASTR + qtr * 16 + j * 4) = make_uint4(
                __float_as_uint(ux), __float_as_uint(uy),
                __float_as_uint(uz), __float_as_uint(uw));
        }
        ps += __shfl_xor_sync(0xFFFFFFFFu, ps, 1);
        ps += __shfl_xor_sync(0xFFFFFFFFu, ps, 2);
        if (qtr == 0) sqv[row] = 0.5f * ps;
    }
    {
        int m = tid >> 1, half = tid & 1;
        const float* orow = omega + m * 64 + half * 32;
        #pragma unroll
        for (int j = 0; j < 8; j++) {
            float4 v = ((const float4*)orow)[j];
            *(uint4*)(Bs + m * PASTR + half * 32 + j * 4) = make_uint4(
                __float_as_uint(rn_tf32(v.x)), __float_as_uint(rn_tf32(v.y)),
                __float_as_uint(rn_tf32(v.z)), __float_as_uint(rn_tf32(v.w)));
        }
    }
    __syncthreads();

    float acc[2][8][4];
    #pragma unroll
    for (int mi = 0; mi < 2; mi++)
        #pragma unroll
        for (int ni = 0; ni < 8; ni++)
            #pragma unroll
            for (int j = 0; j < 4; j++) acc[mi][ni][j] = 0.f;

    int kfrag = lane & 3;
    int mrow = (wid & 3) * 32 + (lane >> 2);
    int nrow = (wid >> 2) * 64 + (lane >> 2);

    #pragma unroll
    for (int ks = 0; ks < 8; ks++) {
        int kk = ks * 8 + kfrag;
        unsigned afr[2][4], bfr[8][2];
        #pragma unroll
        for (int mi = 0; mi < 2; mi++) {
            const unsigned* ap = As + (mrow + mi * 16) * PASTR + kk;
            afr[mi][0] = ap[0];
            afr[mi][1] = ap[8 * PASTR];
            afr[mi][2] = ap[4];
            afr[mi][3] = ap[8 * PASTR + 4];
        }
        #pragma unroll
        for (int ni = 0; ni < 8; ni++) {
            const unsigned* bp = Bs + (nrow + ni * 8) * PASTR + kk;
            bfr[ni][0] = bp[0];
            bfr[ni][1] = bp[4];
        }
        #pragma unroll
        for (int mi = 0; mi < 2; mi++)
            #pragma unroll
            for (int ni = 0; ni < 8; ni++)
                mma_tf32(acc[mi][ni], afr[mi], bfr[ni]);
    }
    __syncthreads();

    #pragma unroll
    for (int mi = 0; mi < 2; mi++)
        #pragma unroll
        for (int ni = 0; ni < 8; ni++) {
            int row = (wid & 3) * 32 + mi * 16 + (lane >> 2);
            int col = (wid >> 2) * 64 + ni * 8 + (lane & 3) * 2;
            *(float2*)(stage + row * PHI_STAGE_W + col) =
                make_float2(acc[mi][ni][0], acc[mi][ni][1]);
            *(float2*)(stage + (row + 8) * PHI_STAGE_W + col) =
                make_float2(acc[mi][ni][2], acc[mi][ni][3]);
        }
    __syncthreads();

    {
        int row = tid >> 2, seg = (tid & 3) * 64;
        const float* srow = stage + row * PHI_STAGE_W + seg;
        float mx = -1e30f;
        #pragma unroll
        for (int j = 0; j < 16; j++) {
            float4 v = ((const float4*)srow)[j];
            mx = fmaxf(mx, fmaxf(fmaxf(v.x, v.y), fmaxf(v.z, v.w)));
        }
        mx = fmaxf(mx, __shfl_xor_sync(0xFFFFFFFFu, mx, 1));
        mx = fmaxf(mx, __shfl_xor_sync(0xFFFFFFFFu, mx, 2));
        float sb = sqv[row] + mx;

        int r = rbase + row, n = r >> 4, h = r & 15;
        int b = n >> 12, s = n & 4095;
        float* drow = dst + (((size_t)(b * H_N + h)) * S_LEN + s) * M_F + seg;
        #pragma unroll
        for (int j = 0; j < 16; j++) {
            float4 v = ((const float4*)srow)[j];
            ((float4*)drow)[j] = make_float4(
                rn_tf32(__expf(v.x - sb) * RSQRT_M + 1e-6f),
                rn_tf32(__expf(v.y - sb) * RSQRT_M + 1e-6f),
                rn_tf32(__expf(v.z - sb) * RSQRT_M + 1e-6f),
                rn_tf32(__expf(v.w - sb) * RSQRT_M + 1e-6f));
        }
    }
}

// ---------------- kv[m][k] = sum_s pk[s][m] v[s][k]; z[m] = sum_s pk[s][m] ----
__global__ __launch_bounds__(256)
void kv_kernel(const float* __restrict__ pk, const float* __restrict__ v,
               float* __restrict__ kv, float* __restrict__ z)
{
    int bh = blockIdx.x >> 2;
    int chunk = blockIdx.x & 3;
    int b = bh >> 4, h = bh & 15;
    int tid = threadIdx.x;

    __shared__ float pk_s[8][256];
    __shared__ float v_s[8][64];

    float acc[64];
    #pragma unroll
    for (int i = 0; i < 64; i++) acc[i] = 0.f;
    float az = 0.f;

    const float* pkb = pk + ((size_t)bh * S_LEN + chunk * 1024) * M_F;
    const float* vb  = v + ((size_t)(b * S_LEN + chunk * 1024)) * D_MOD + h * 64;

    for (int s0 = 0; s0 < 1024; s0 += 8) {
        #pragma unroll
        for (int i = 0; i < 8; i++)
            pk_s[i][tid] = pkb[(size_t)(s0 + i) * M_F + tid];
        if (tid < 128) {
            int i = tid >> 4, c4 = tid & 15;
            *(float4*)&v_s[i][c4 * 4] =
                *(const float4*)(vb + (size_t)(s0 + i) * D_MOD + c4 * 4);
        }
        __syncthreads();
        #pragma unroll
        for (int i = 0; i < 8; i++) {
            float p = pk_s[i][tid];
            az += p;
            #pragma unroll
            for (int k4 = 0; k4 < 16; k4++) {
                float4 vv = *(const float4*)&v_s[i][k4 * 4];
                acc[k4*4+0] += p * vv.x;
                acc[k4*4+1] += p * vv.y;
                acc[k4*4+2] += p * vv.z;
                acc[k4*4+3] += p * vv.w;
            }
        }
        __syncthreads();
    }

    float* kvp = kv + (size_t)bh * (M_F * HK) + tid * 64;
    #pragma unroll
    for (int k = 0; k < 64; k++) atomicAdd(kvp + k, acc[k]);
    atomicAdd(z + bh * M_F + tid, az);
}

// ---------------- tensorized num/den: attn = (pq @ kv) / (pq @ z) ------------
// grid = (bh 64) x (s-chunk 32); CTA 128 rows x 64 cols, K=256, 8 warps.
#define ND_BSTR  260
#define ND_B_OFF 0
#define ND_Z_OFF (64 * ND_BSTR * 4)              // 66560
#define ND_A_OFF (ND_Z_OFF + 1024)               // 67584
#define ND_SM    (ND_A_OFF + 2 * TILEB)          // 104448

__global__ __launch_bounds__(256, 2)
void numden_mma(const float* __restrict__ pq, const float* __restrict__ kvg,
                const float* __restrict__ zg, float* __restrict__ attn)
{
    extern __shared__ char sm[];
    unsigned smu = smem_u32(sm);
    float* Bsf   = (float*)(sm + ND_B_OFF);
    float* z_s   = (float*)(sm + ND_Z_OFF);
    float* den_s = (float*)(sm + ND_B_OFF);      // aliases Bs after MMA
    float* stage = (float*)(sm + ND_A_OFF);      // aliases As after MMA

    int bh = blockIdx.x >> 5;
    int chunk = blockIdx.x & 31;
    int b = bh >> 4, h = bh & 15;
    int tid = threadIdx.x, wid = tid >> 5, lane = tid & 31;
    int s0 = chunk * 128;

    const float* pqb = pq + ((size_t)bh * S_LEN + s0) * M_F;

    // A cp.async mapping (chunk = [128 rows][32 floats])
    int crow = tid >> 1, cseg = (tid & 1) * 4;   // 2 threads/row, 2x16B each? no:
    // use the 4-iter mapping like tc_gemm: u = tid + 256*i, row=u>>3, seg=u&7
    int arow[4], aseg[4];
    unsigned adst[4];
    #pragma unroll
    for (int i = 0; i < 4; i++) {
        int u = tid + 256 * i;
        arow[i] = u >> 3; aseg[i] = u & 7;
        adst[i] = smu + ND_A_OFF + (unsigned)(arow[i] * TSTR + aseg[i] * 4) * 4;
    }
    (void)crow; (void)cseg;

    // prologue: A chunks 0,1
    #pragma unroll
    for (int s = 0; s < 2; s++) {
        const float* Ac = pqb + s * 32;
        unsigned so = s * TILEB;
        #pragma unroll
        for (int i = 0; i < 4; i++)
            CP16(adst[i] + so, Ac + (size_t)arow[i] * M_F + aseg[i] * 4);
        CP_COMMIT();
    }

    // fill Bs = rn(kv^T) [64 k][256 m], z_s
    {
        const float* kvb = kvg + (size_t)bh * (M_F * HK);
        for (int i = tid; i < M_F * HK; i += 256) {
            int m = i >> 6, k = i & 63;
            Bsf[k * ND_BSTR + m] = rn_tf32(kvb[i]);
        }
        z_s[tid] = zg[bh * M_F + tid];
    }

    float acc[2][4][4];
    #pragma unroll
    for (int mi = 0; mi < 2; mi++)
        #pragma unroll
        for (int ni = 0; ni < 4; ni++)
            #pragma unroll
            for (int j = 0; j < 4; j++) acc[mi][ni][j] = 0.f;

    int kfrag = lane & 3;
    int mrow = (wid & 3) * 32 + (lane >> 2);
    int nrow = (wid >> 2) * 32 + (lane >> 2);
    const unsigned* Bsu = (const unsigned*)Bsf;

    for (int c = 0; c < 8; c++) {
        int p = c & 1;
        CP_WAIT1();
        __syncthreads();

        const unsigned* As = (const unsigned*)(sm + ND_A_OFF + p * TILEB);
        #pragma unroll
        for (int ks = 0; ks < 4; ks++) {
            int kk = ks * 8 + kfrag;
            unsigned afr[2][4], bfr[4][2];
            #pragma unroll
            for (int mi = 0; mi < 2; mi++) {
                const unsigned* ap = As + (mrow + mi * 16) * TSTR + kk;
                afr[mi][0] = ap[0];
                afr[mi][1] = ap[8 * TSTR];
                afr[mi][2] = ap[4];
                afr[mi][3] = ap[8 * TSTR + 4];
            }
            #pragma unroll
            for (int ni = 0; ni < 4; ni++) {
                const unsigned* bp = Bsu + (nrow + ni * 8) * ND_BSTR + c * 32 + kk;
                bfr[ni][0] = bp[0];
                bfr[ni][1] = bp[4];
            }
            #pragma unroll
            for (int mi = 0; mi < 2; mi++)
                #pragma unroll
                for (int ni = 0; ni < 4; ni++)
                    mma_tf32(acc[mi][ni], afr[mi], bfr[ni]);
        }
        __syncthreads();

        if (c + 2 < 8) {
            const float* Ac = pqb + (c + 2) * 32;
            unsigned so = p * TILEB;
            #pragma unroll
            for (int i = 0; i < 4; i++)
                CP16(adst[i] + so, Ac + (size_t)arow[i] * M_F + aseg[i] * 4);
        }
        CP_COMMIT();
    }
    CP_WAIT0();
    __syncthreads();   // all MMA reads done: As & Bs free for aliasing

    // stage acc (width 68) into As region
    #pragma unroll
    for (int mi = 0; mi < 2; mi++)
        #pragma unroll
        for (int ni = 0; ni < 4; ni++) {
            int row = (wid & 3) * 32 + mi * 16 + (lane >> 2);
            int col = (wid >> 2) * 32 + ni * 8 + (lane & 3) * 2;
            *(float2*)(stage + row * 68 + col) =
                make_float2(acc[mi][ni][0], acc[mi][ni][1]);
            *(float2*)(stage + (row + 8) * 68 + col) =
                make_float2(acc[mi][ni][2], acc[mi][ni][3]);
        }

    // den: 2 threads/row, 128 m each, from global pq (L2-hot) + z_s
    {
        int row = tid >> 1, half = tid & 1;
        const float* prow = pqb + (size_t)row * M_F + half * 128;
        const float* zr = z_s + half * 128;
        float dp = 0.f;
        #pragma unroll 8
        for (int j = 0; j < 32; j++) {
            float4 pv = ((const float4*)prow)[j];
            float4 zv = ((const float4*)zr)[j];
            dp += pv.x * zv.x + pv.y * zv.y + pv.z * zv.z + pv.w * zv.w;
        }
        dp += __shfl_xor_sync(0xFFFFFFFFu, dp, 1);
        if (half == 0) den_s[row] = dp;
    }
    __syncthreads();

    // normalize + store (rounded for the wo GEMM)
    #pragma unroll
    for (int i = 0; i < 8; i++) {
        int u = tid + 256 * i;
        int row = u >> 4, c4 = u & 15;
        float4 v = *(const float4*)(stage + row * 68 + c4 * 4);
        float rd = 1.0f / den_s[row];
        float* dst = attn + ((size_t)(b * S_LEN + s0 + row)) * D_MOD + h * 64 + c4 * 4;
        *(float4*)dst = make_float4(rn_tf32(v.x * rd), rn_tf32(v.y * rd),
                                    rn_tf32(v.z * rd), rn_tf32(v.w * rd));
    }
}

// ---------------- LayerNorm ----------------
template<int RND>
__global__ void ln_kernel(const float* __restrict__ X, const float* __restrict__ g,
                          const float* __restrict__ bv, float* __restrict__ out)
{
    int row = blockIdx.x, tid = threadIdx.x;
    float4 v = ((const float4*)(X + (size_t)row * D_MOD))[tid];
    float s = v.x + v.y + v.z + v.w;
    __shared__ float ws[8];
    #pragma unroll
    for (int o = 16; o; o >>= 1) s += __shfl_xor_sync(0xFFFFFFFFu, s, o);
    if ((tid & 31) == 0) ws[tid >> 5] = s;
    __syncthreads();
    float tot = 0.f;
    #pragma unroll
    for (int w = 0; w < 8; w++) tot += ws[w];
    float mu = tot * (1.f / 1024.f);
    float dx = v.x - mu, dy = v.y - mu, dz = v.z - mu, dw = v.w - mu;
    float sqvv = dx*dx + dy*dy + dz*dz + dw*dw;
    __syncthreads();
    #pragma unroll
    for (int o = 16; o; o >>= 1) sqvv += __shfl_xor_sync(0xFFFFFFFFu, sqvv, o);
    if ((tid & 31) == 0) ws[tid >> 5] = sqvv;
    __syncthreads();
    float tot2 = 0.f;
    #pragma unroll
    for (int w = 0; w < 8; w++) tot2 += ws[w];
    float rs = rsqrtf(tot2 * (1.f / 1024.f) + 1e-6f);
    float4 gg = ((const float4*)g)[tid];
    float4 bb = ((const float4*)bv)[tid];
    float4 o4 = make_float4(dx*rs*gg.x + bb.x, dy*rs*gg.y + bb.y,
                            dz*rs*gg.z + bb.z, dw*rs*gg.w + bb.w);
    if (RND) o4 = make_float4(rn_tf32(o4.x), rn_tf32(o4.y), rn_tf32(o4.z), rn_tf32(o4.w));
    ((float4*)(out + (size_t)row * D_MOD))[tid] = o4;
}

__global__ void zero_kernel(float* p, int n)
{
    int i = blockIdx.x * blockDim.x + threadIdx.x;
    if (i < n) p[i] = 0.f;
}

// ---------------- orchestration ----------------
extern "C" void kernel_launch(void* const* d_in, const int* in_sizes, int n_in,
                              void* d_out, int out_size)
{
    const float* x     = (const float*)d_in[0];
    const float* wq    = (const float*)d_in[1];
    const float* wk    = (const float*)d_in[2];
    const float* wv    = (const float*)d_in[3];
    const float* wo    = (const float*)d_in[4];
    const float* omega = (const float*)d_in[5];
    const float* ln1g  = (const float*)d_in[6];
    const float* ln1b  = (const float*)d_in[7];
    const float* w1    = (const float*)d_in[8];
    const float* b1    = (const float*)d_in[9];
    const float* w2    = (const float*)d_in[10];
    const float* b2    = (const float*)d_in[11];
    const float* ln2g  = (const float*)d_in[12];
    const float* ln2b  = (const float*)d_in[13];
    float* out = (float*)d_out;

    float *q, *k, *v, *xr, *pq, *pk, *kv, *z, *attn, *y, *x1, *act;
    float *wqT, *wkT, *wvT, *woT, *w1T, *w2T;
    cudaGetSymbolAddress((void**)&q,    g_q);
    cudaGetSymbolAddress((void**)&k,    g_k);
    cudaGetSymbolAddress((void**)&v,    g_v);
    cudaGetSymbolAddress((void**)&xr,   g_xr);
    cudaGetSymbolAddress((void**)&pq,   g_pq);
    cudaGetSymbolAddress((void**)&pk,   g_pk);
    cudaGetSymbolAddress((void**)&kv,   g_kv);
    cudaGetSymbolAddress((void**)&z,    g_z);
    cudaGetSymbolAddress((void**)&attn, g_attn);
    cudaGetSymbolAddress((void**)&y,    g_y);
    cudaGetSymbolAddress((void**)&x1,   g_x1);
    cudaGetSymbolAddress((void**)&act,  g_act);
    cudaGetSymbolAddress((void**)&wqT,  g_wqT);
    cudaGetSymbolAddress((void**)&wkT,  g_wkT);
    cudaGetSymbolAddress((void**)&wvT,  g_wvT);
    cudaGetSymbolAddress((void**)&woT,  g_woT);
    cudaGetSymbolAddress((void**)&w1T,  g_w1T);
    cudaGetSymbolAddress((void**)&w2T,  g_w2T);

    cudaFuncSetAttribute(numden_mma, cudaFuncAttributeMaxDynamicSharedMemorySize, ND_SM);
    cudaFuncSetAttribute(phi_mma, cudaFuncAttributeMaxDynamicSharedMemorySize, PHI_SM);
    cudaFuncSetAttribute(tc_gemm<0>, cudaFuncAttributeMaxDynamicSharedMemorySize, SM_DYN);
    cudaFuncSetAttribute(tc_gemm<1>, cudaFuncAttributeMaxDynamicSharedMemorySize, SM_DYN);
    cudaFuncSetAttribute(tc_gemm<2>, cudaFuncAttributeMaxDynamicSharedMemorySize, SM_DYN);
    cudaFuncSetAttribute(tc_gemm<3>, cudaFuncAttributeMaxDynamicSharedMemorySize, SM_DYN);

    dim3 tb(32, 8);
    transpose_k<<<dim3(32, 32),   tb>>>(wq, wqT, 1024, 1024);
    transpose_k<<<dim3(32, 32),   tb>>>(wk, wkT, 1024, 1024);
    transpose_k<<<dim3(32, 32),   tb>>>(wv, wvT, 1024, 1024);
    transpose_k<<<dim3(32, 32),   tb>>>(wo, woT, 1024, 1024);
    transpose_k<<<dim3(128, 32),  tb>>>(w1, w1T, 1024, 4096);
    transpose_k<<<dim3(32, 128),  tb>>>(w2, w2T, 4096, 1024);
    round_kernel<<<(N_TOK * D_MOD / 4 + 255) / 256, 256>>>(x, xr, N_TOK * D_MOD / 4);

    dim3 gD(D_MOD / 128, N_TOK / 128);   // (8, 128)
    dim3 gF(FF_D / 128, N_TOK / 128);    // (32, 128)

    tc_gemm<0><<<gD, 256, SM_DYN>>>(xr, wqT, nullptr, nullptr, q, D_MOD, D_MOD);
    tc_gemm<0><<<gD, 256, SM_DYN>>>(xr, wkT, nullptr, nullptr, k, D_MOD, D_MOD);
    tc_gemm<0><<<gD, 256, SM_DYN>>>(xr, wvT, nullptr, nullptr, v, D_MOD, D_MOD);

    phi_mma<<<2048, 512, PHI_SM>>>(q, omega, pq);
    phi_mma<<<2048, 512, PHI_SM>>>(k, omega, pk);

    zero_kernel<<<(64 * M_F * HK + 255) / 256, 256>>>(kv, 64 * M_F * HK);
    zero_kernel<<<(64 * M_F + 255) / 256, 256>>>(z, 64 * M_F);
    kv_kernel<<<256, 256>>>(pk, v, kv, z);

    numden_mma<<<2048, 256, ND_SM>>>(pq, kv, z, attn);

    tc_gemm<1><<<gD, 256, SM_DYN>>>(attn, woT, nullptr, x, y, D_MOD, D_MOD);
    ln_kernel<1><<<N_TOK, 256>>>(y, ln1g, ln1b, x1);

    tc_gemm<2><<<gF, 256, SM_DYN>>>(x1, w1T, b1, nullptr, act, D_MOD, FF_D);
    tc_gemm<3><<<gD, 256, SM_DYN>>>(act, w2T, b2, x1, y, FF_D, D_MOD);
    ln_kernel<0><<<N_TOK, 256>>>(y, ln2g, ln2b, out);
}

// round 10
// speedup vs baseline: 1.3890x; 1.0695x over previous
#include <cuda_runtime.h>
#include <math.h>

#define N_TOK 16384
#define D_MOD 1024
#define H_N   16
#define HK    64
#define M_F   256
#define FF_D  4096
#define S_LEN 4096
#define PHI_SCALE 0.35355339059327373f   // 64^-0.25
#define RSQRT_M  0.0625f                 // 1/sqrt(256)

// ---------------- scratch (device globals; allocation-free) ----------------
__device__ float g_q   [N_TOK * D_MOD];
__device__ float g_k   [N_TOK * D_MOD];
__device__ float g_v   [N_TOK * D_MOD];
__device__ float g_xr  [N_TOK * D_MOD];
__device__ float g_pq  [64 * S_LEN * M_F];
__device__ float g_pk  [64 * S_LEN * M_F];
__device__ float g_kv  [64 * M_F * HK];
__device__ float g_z   [64 * M_F];
__device__ float g_kvp [512 * 256 * 72];
__device__ float g_attn[N_TOK * D_MOD];
__device__ float g_y   [N_TOK * D_MOD];
__device__ float g_x1  [N_TOK * D_MOD];
__device__ float g_act [N_TOK * FF_D];
__device__ float g_wqT [D_MOD * D_MOD];
__device__ float g_wkT [D_MOD * D_MOD];
__device__ float g_wvT [D_MOD * D_MOD];
__device__ float g_woT [D_MOD * D_MOD];
__device__ float g_w1T [D_MOD * FF_D];
__device__ float g_w2T [D_MOD * FF_D];

__device__ __forceinline__ unsigned smem_u32(const void* p) {
    unsigned a;
    asm("{ .reg .u64 t; cvta.to.shared.u64 t, %1; cvt.u32.u64 %0, t; }" : "=r"(a) : "l"(p));
    return a;
}
__device__ __forceinline__ float rn_tf32(float f) {
    unsigned u;
    asm("cvt.rn.tf32.f32 %0, %1;" : "=r"(u) : "f"(f));
    return __uint_as_float(u);
}

__device__ __forceinline__ void mma_tf32(float* d, const unsigned* a, const unsigned* b) {
    asm volatile(
        "mma.sync.aligned.m16n8k8.row.col.f32.tf32.tf32.f32 "
        "{%0,%1,%2,%3}, {%4,%5,%6,%7}, {%8,%9}, {%0,%1,%2,%3};"
        : "+f"(d[0]), "+f"(d[1]), "+f"(d[2]), "+f"(d[3])
        : "r"(a[0]), "r"(a[1]), "r"(a[2]), "r"(a[3]), "r"(b[0]), "r"(b[1]));
}

#define CP16(dst, src) \
    asm volatile("cp.async.ca.shared.global [%0], [%1], 16;" :: "r"(dst), "l"(src))
#define CP_COMMIT() asm volatile("cp.async.commit_group;" ::: "memory")
#define CP_WAIT1()  asm volatile("cp.async.wait_group 1;" ::: "memory")
#define CP_WAIT0()  asm volatile("cp.async.wait_group 0;" ::: "memory")

// ---------------- warp-MMA tf32 GEMM: C[M,N] = A[M,Kd] @ BT[N,Kd]^T ----------
// 128x128 CTA tile, 8 warps (64x32), K-chunk 32, 3 slots, single sync/chunk.
// EPI: 0 none, 1 +res, 2 gelu(x+bias)[rnd], 3 +bias+res, 4 rnd
#define TSTR   36
#define TILEB  (128 * TSTR * 4)          // 18432
#define STAGEB (2 * TILEB)               // 36864
#define SM_DYN (3 * STAGEB)              // 110592

template<int EPI>
__global__ __launch_bounds__(256, 2)
void tc_gemm(const float* __restrict__ A, const float* __restrict__ BT,
             const float* __restrict__ bias, const float* __restrict__ R,
             float* __restrict__ C, int Kd, int NC)
{
    extern __shared__ char sm[];
    unsigned smu = smem_u32(sm);
    int tid = threadIdx.x, wid = tid >> 5, lane = tid & 31;
    int r0 = blockIdx.y * 128, c0 = blockIdx.x * 128;
    int wm = wid & 1, wn = wid >> 1;

    const float* Ab = A + (size_t)r0 * Kd;
    const float* Bb = BT + (size_t)c0 * Kd;

    int crow[4], cseg[4];
    unsigned cdst[4];
    #pragma unroll
    for (int i = 0; i < 4; i++) {
        int u = tid + 256 * i;
        crow[i] = u >> 3; cseg[i] = u & 7;
        cdst[i] = smu + (unsigned)(crow[i] * TSTR + cseg[i] * 4) * 4;
    }

    float acc[4][4][4];
    #pragma unroll
    for (int mi = 0; mi < 4; mi++)
        #pragma unroll
        for (int ni = 0; ni < 4; ni++)
            #pragma unroll
            for (int j = 0; j < 4; j++) acc[mi][ni][j] = 0.f;

    int nk = Kd >> 5;

    #pragma unroll
    for (int s = 0; s < 2; s++) {
        const float* Ac = Ab + s * 32;
        const float* Bc = Bb + s * 32;
        unsigned so = s * STAGEB;
        #pragma unroll
        for (int i = 0; i < 4; i++) {
            CP16(cdst[i] + so,         Ac + (size_t)crow[i] * Kd + cseg[i] * 4);
            CP16(cdst[i] + so + TILEB, Bc + (size_t)crow[i] * Kd + cseg[i] * 4);
        }
        CP_COMMIT();
    }

    int kfrag = lane & 3;
    int mrow = wm * 64 + (lane >> 2);
    int nrow = wn * 32 + (lane >> 2);

    int p = 0, pn = 2;
    for (int c = 0; c < nk; c++) {
        CP_WAIT1();
        __syncthreads();

        if (c + 2 < nk) {
            const float* Ac = Ab + (c + 2) * 32;
            const float* Bc = Bb + (c + 2) * 32;
            unsigned so = pn * STAGEB;
            #pragma unroll
            for (int i = 0; i < 4; i++) {
                CP16(cdst[i] + so,         Ac + (size_t)crow[i] * Kd + cseg[i] * 4);
                CP16(cdst[i] + so + TILEB, Bc + (size_t)crow[i] * Kd + cseg[i] * 4);
            }
        }
        CP_COMMIT();

        const unsigned* As = (const unsigned*)(sm + p * STAGEB);
        const unsigned* Bs = (const unsigned*)(sm + p * STAGEB + TILEB);

        #pragma unroll
        for (int ks = 0; ks < 4; ks++) {
            int kk = ks * 8 + kfrag;
            unsigned afr[4][4], bfr[4][2];
            #pragma unroll
            for (int mi = 0; mi < 4; mi++) {
                const unsigned* ap = As + (mrow + mi * 16) * TSTR + kk;
                afr[mi][0] = ap[0];
                afr[mi][1] = ap[8 * TSTR];
                afr[mi][2] = ap[4];
                afr[mi][3] = ap[8 * TSTR + 4];
            }
            #pragma unroll
            for (int ni = 0; ni < 4; ni++) {
                const unsigned* bp = Bs + (nrow + ni * 8) * TSTR + kk;
                bfr[ni][0] = bp[0];
                bfr[ni][1] = bp[4];
            }
            #pragma unroll
            for (int mi = 0; mi < 4; mi++)
                #pragma unroll
                for (int ni = 0; ni < 4; ni++)
                    mma_tf32(acc[mi][ni], afr[mi], bfr[ni]);
        }
        p = (p == 2) ? 0 : p + 1;
        pn = (pn == 2) ? 0 : pn + 1;
    }
    CP_WAIT0();
    __syncthreads();

    float* stage = (float*)sm;
    #pragma unroll
    for (int mi = 0; mi < 4; mi++)
        #pragma unroll
        for (int ni = 0; ni < 4; ni++) {
            int row = wm * 64 + mi * 16 + (lane >> 2);
            int col = wn * 32 + ni * 8 + (lane & 3) * 2;
            *(float2*)(stage + row * 132 + col) =
                make_float2(acc[mi][ni][0], acc[mi][ni][1]);
            *(float2*)(stage + (row + 8) * 132 + col) =
                make_float2(acc[mi][ni][2], acc[mi][ni][3]);
        }
    __syncthreads();

    #pragma unroll
    for (int i = 0; i < 16; i++) {
        int u = tid + 256 * i;
        int row = u >> 5, c4 = u & 31;
        float4 v = *(const float4*)(stage + row * 132 + c4 * 4);
        size_t base = (size_t)(r0 + row) * NC + c0 + c4 * 4;
        float vv[4] = {v.x, v.y, v.z, v.w};
        #pragma unroll
        for (int j = 0; j < 4; j++) {
            int col = c0 + c4 * 4 + j;
            if (EPI == 1) vv[j] += R[base + j];
            else if (EPI == 2) {
                float t = vv[j] + bias[col];
                vv[j] = rn_tf32(0.5f * t * (1.0f + erff(t * 0.70710678118654752f)));
            } else if (EPI == 3) vv[j] += bias[col] + R[base + j];
            else if (EPI == 4) vv[j] = rn_tf32(vv[j]);
        }
        *(float4*)(C + base) = make_float4(vv[0], vv[1], vv[2], vv[3]);
    }
}

// ---------------- transpose + tf32-RN round ----------------
__global__ void transpose_k(const float* __restrict__ in, float* __restrict__ out,
                            int R, int Cc)
{
    __shared__ float t[32][33];
    int x = blockIdx.x * 32 + threadIdx.x;
    int y = blockIdx.y * 32 + threadIdx.y;
    #pragma unroll
    for (int j = 0; j < 4; j++)
        t[threadIdx.y + j * 8][threadIdx.x] = in[(size_t)(y + j * 8) * Cc + x];
    __syncthreads();
    int ox = blockIdx.y * 32 + threadIdx.x;
    int oy = blockIdx.x * 32 + threadIdx.y;
    #pragma unroll
    for (int j = 0; j < 4; j++)
        out[(size_t)(oy + j * 8) * R + ox] = rn_tf32(t[threadIdx.x][threadIdx.y + j * 8]);
}

__global__ void round_kernel(const float* __restrict__ in, float* __restrict__ out, int n4)
{
    int i = blockIdx.x * blockDim.x + threadIdx.x;
    if (i < n4) {
        float4 v = ((const float4*)in)[i];
        ((float4*)out)[i] = make_float4(rn_tf32(v.x), rn_tf32(v.y),
                                        rn_tf32(v.z), rn_tf32(v.w));
    }
}

// ---------------- tensorized FAVOR+ (output RN-rounded to tf32) -------------
#define PASTR 68
#define PHI_A_OFF 0
#define PHI_B_OFF (128 * PASTR * 4)
#define PHI_STAGE_W 260
#define PHI_SQ_OFF  (128 * PHI_STAGE_W * 4)
#define PHI_SM      (PHI_SQ_OFF + 128 * 4)

__global__ __launch_bounds__(512, 1)
void phi_mma(const float* __restrict__ src, const float* __restrict__ omega,
             float* __restrict__ dst)
{
    extern __shared__ char sm[];
    unsigned* As = (unsigned*)(sm + PHI_A_OFF);
    unsigned* Bs = (unsigned*)(sm + PHI_B_OFF);
    float* stage = (float*)sm;
    float* sqv   = (float*)(sm + PHI_SQ_OFF);

    int tid = threadIdx.x, wid = tid >> 5, lane = tid & 31;
    int rbase = blockIdx.x * 128;

    {
        int row = tid >> 2, qtr = tid & 3;
        int r = rbase + row, n = r >> 4, h = r & 15;
        const float* srow = src + (size_t)n * D_MOD + h * 64 + qtr * 16;
        float ps = 0.f;
        #pragma unroll
        for (int j = 0; j < 4; j++) {
            float4 v = ((const float4*)srow)[j];
            float ux = rn_tf32(v.x * PHI_SCALE);
            float uy = rn_tf32(v.y * PHI_SCALE);
            float uz = rn_tf32(v.z * PHI_SCALE);
            float uw = rn_tf32(v.w * PHI_SCALE);
            ps += ux * ux + uy * uy + uz * uz + uw * uw;
            *(uint4*)(As + row * PASTR + qtr * 16 + j * 4) = make_uint4(
                __float_as_uint(ux), __float_as_uint(uy),
                __float_as_uint(uz), __float_as_uint(uw));
        }
        ps += __shfl_xor_sync(0xFFFFFFFFu, ps, 1);
        ps += __shfl_xor_sync(0xFFFFFFFFu, ps, 2);
        if (qtr == 0) sqv[row] = 0.5f * ps;
    }
    {
        int m = tid >> 1, half = tid & 1;
        const float* orow = omega + m * 64 + half * 32;
        #pragma unroll
        for (int j = 0; j < 8; j++) {
            float4 v = ((const float4*)orow)[j];
            *(uint4*)(Bs + m * PASTR + half * 32 + j * 4) = make_uint4(
                __float_as_uint(rn_tf32(v.x)), __float_as_uint(rn_tf32(v.y)),
                __float_as_uint(rn_tf32(v.z)), __float_as_uint(rn_tf32(v.w)));
        }
    }
    __syncthreads();

    float acc[2][8][4];
    #pragma unroll
    for (int mi = 0; mi < 2; mi++)
        #pragma unroll
        for (int ni = 0; ni < 8; ni++)
            #pragma unroll
            for (int j = 0; j < 4; j++) acc[mi][ni][j] = 0.f;

    int kfrag = lane & 3;
    int mrow = (wid & 3) * 32 + (lane >> 2);
    int nrow = (wid >> 2) * 64 + (lane >> 2);

    #pragma unroll
    for (int ks = 0; ks < 8; ks++) {
        int kk = ks * 8 + kfrag;
        unsigned afr[2][4], bfr[8][2];
        #pragma unroll
        for (int mi = 0; mi < 2; mi++) {
            const unsigned* ap = As + (mrow + mi * 16) * PASTR + kk;
            afr[mi][0] = ap[0];
            afr[mi][1] = ap[8 * PASTR];
            afr[mi][2] = ap[4];
            afr[mi][3] = ap[8 * PASTR + 4];
        }
        #pragma unroll
        for (int ni = 0; ni < 8; ni++) {
            const unsigned* bp = Bs + (nrow + ni * 8) * PASTR + kk;
            bfr[ni][0] = bp[0];
            bfr[ni][1] = bp[4];
        }
        #pragma unroll
        for (int mi = 0; mi < 2; mi++)
            #pragma unroll
            for (int ni = 0; ni < 8; ni++)
                mma_tf32(acc[mi][ni], afr[mi], bfr[ni]);
    }
    __syncthreads();

    #pragma unroll
    for (int mi = 0; mi < 2; mi++)
        #pragma unroll
        for (int ni = 0; ni < 8; ni++) {
            int row = (wid & 3) * 32 + mi * 16 + (lane >> 2);
            int col = (wid >> 2) * 64 + ni * 8 + (lane & 3) * 2;
            *(float2*)(stage + row * PHI_STAGE_W + col) =
                make_float2(acc[mi][ni][0], acc[mi][ni][1]);
            *(float2*)(stage + (row + 8) * PHI_STAGE_W + col) =
                make_float2(acc[mi][ni][2], acc[mi][ni][3]);
        }
    __syncthreads();

    {
        int row = tid >> 2, seg = (tid & 3) * 64;
        const float* srow = stage + row * PHI_STAGE_W + seg;
        float mx = -1e30f;
        #pragma unroll
        for (int j = 0; j < 16; j++) {
            float4 v = ((const float4*)srow)[j];
            mx = fmaxf(mx, fmaxf(fmaxf(v.x, v.y), fmaxf(v.z, v.w)));
        }
        mx = fmaxf(mx, __shfl_xor_sync(0xFFFFFFFFu, mx, 1));
        mx = fmaxf(mx, __shfl_xor_sync(0xFFFFFFFFu, mx, 2));
        float sb = sqv[row] + mx;

        int r = rbase + row, n = r >> 4, h = r & 15;
        int b = n >> 12, s = n & 4095;
        float* drow = dst + (((size_t)(b * H_N + h)) * S_LEN + s) * M_F + seg;
        #pragma unroll
        for (int j = 0; j < 16; j++) {
            float4 v = ((const float4*)srow)[j];
            ((float4*)drow)[j] = make_float4(
                rn_tf32(__expf(v.x - sb) * RSQRT_M + 1e-6f),
                rn_tf32(__expf(v.y - sb) * RSQRT_M + 1e-6f),
                rn_tf32(__expf(v.z - sb) * RSQRT_M + 1e-6f),
                rn_tf32(__expf(v.w - sb) * RSQRT_M + 1e-6f));
        }
    }
}

// ---------------- tensorized kv: partial[blk][m][72] = pk^T @ [v | 1] -------
// grid = 64 bh x 8 s-chunks (s-chunk 512). CTA: M=256, N=80 (col64 = ones -> z).
#define KV_PSTR  264
#define KV_VSTR  104
#define KV_PKB   (32 * KV_PSTR * 4)      // 33792
#define KV_VB    (32 * KV_VSTR * 4)      // 13312
#define KV_STAGE (KV_PKB + KV_VB)        // 47104
#define KV_SM    (2 * KV_STAGE)          // 94208

__global__ __launch_bounds__(256, 2)
void kv_mma(const float* __restrict__ pk, const float* __restrict__ v,
            float* __restrict__ partial)
{
    extern __shared__ char sm[];
    unsigned smu = smem_u32(sm);
    int tid = threadIdx.x, wid = tid >> 5, lane = tid & 31;
    int bh = blockIdx.x >> 3, chunk = blockIdx.x & 7;
    int b = bh >> 4, h = bh & 15;
    int s0 = chunk * 512;

    const float* pkb = pk + ((size_t)bh * S_LEN + s0) * M_F;
    const float* vb  = v + ((size_t)(b * S_LEN + s0)) * D_MOD + h * 64;

    // init ones/zero cols 64..79 of both v-tile stages
    for (int i = tid; i < 32 * 16 * 2; i += 256) {
        int st = i >> 9, r = (i & 511) >> 4, cc = (i & 15) + 64;
        ((float*)(sm + st * KV_STAGE + KV_PKB))[r * KV_VSTR + cc] = (cc == 64) ? 1.f : 0.f;
    }
    __syncthreads();

    auto issue_copy = [&](int cc, int st) {
        unsigned base = smu + st * KV_STAGE;
        #pragma unroll
        for (int i2 = 0; i2 < 8; i2++) {
            int j = tid + 256 * i2;
            int row = j >> 6, seg = j & 63;
            CP16(base + (unsigned)(row * KV_PSTR + seg * 4) * 4,
                 pkb + (size_t)(cc * 32 + row) * M_F + seg * 4);
        }
        // v tile: 32 rows x 64 cols = 512 CP16 over 2 iterations of 256 threads
        #pragma unroll
        for (int i2 = 0; i2 < 2; i2++) {
            int j = tid + 256 * i2;
            int row = j >> 4, seg = j & 15;
            CP16(base + KV_PKB + (unsigned)(row * KV_VSTR + seg * 4) * 4,
                 vb + (size_t)(cc * 32 + row) * D_MOD + seg * 4);
        }
    };

    float acc[4][5][4];
    #pragma unroll
    for (int mi = 0; mi < 4; mi++)
        #pragma unroll
        for (int ni = 0; ni < 5; ni++)
            #pragma unroll
            for (int j = 0; j < 4; j++) acc[mi][ni][j] = 0.f;

    issue_copy(0, 0); CP_COMMIT();
    issue_copy(1, 1); CP_COMMIT();

    int mbase = (wid & 3) * 64 + (lane >> 2);
    int nbase = (wid >> 2) * 40 + (lane >> 2);

    for (int c = 0; c < 16; c++) {
        int p = c & 1;
        CP_WAIT1();
        __syncthreads();

        const unsigned* As = (const unsigned*)(sm + p * KV_STAGE);
        const unsigned* Vs = (const unsigned*)(sm + p * KV_STAGE + KV_PKB);

        #pragma unroll
        for (int ks = 0; ks < 4; ks++) {
            int kk = ks * 8 + (lane & 3);
            unsigned afr[4][4], bfr[5][2];
            #pragma unroll
            for (int mi = 0; mi < 4; mi++) {
                int mr = mbase + mi * 16;
                afr[mi][0] = As[kk * KV_PSTR + mr];
                afr[mi][1] = As[kk * KV_PSTR + mr + 8];
                afr[mi][2] = As[(kk + 4) * KV_PSTR + mr];
                afr[mi][3] = As[(kk + 4) * KV_PSTR + mr + 8];
            }
            #pragma unroll
            for (int ni = 0; ni < 5; ni++) {
                int nr = nbase + ni * 8;
                bfr[ni][0] = Vs[kk * KV_VSTR + nr];
                bfr[ni][1] = Vs[(kk + 4) * KV_VSTR + nr];
            }
            #pragma unroll
            for (int mi = 0; mi < 4; mi++)
                #pragma unroll
                for (int ni = 0; ni < 5; ni++)
                    mma_tf32(acc[mi][ni], afr[mi], bfr[ni]);
        }
        __syncthreads();

        if (c + 2 < 16) issue_copy(c + 2, p);
        CP_COMMIT();
    }

    float* pb = partial + (size_t)blockIdx.x * (256 * 72);
    #pragma unroll
    for (int mi = 0; mi < 4; mi++)
        #pragma unroll
        for (int ni = 0; ni < 5; ni++) {
            int row = (wid & 3) * 64 + mi * 16 + (lane >> 2);
            int col = (wid >> 2) * 40 + ni * 8 + (lane & 3) * 2;
            if (col < 64) {
                *(float2*)(pb + row * 72 + col) =
                    make_float2(acc[mi][ni][0], acc[mi][ni][1]);
                *(float2*)(pb + (row + 8) * 72 + col) =
                    make_float2(acc[mi][ni][2], acc[mi][ni][3]);
            } else if (col == 64) {
                pb[row * 72 + 64] = acc[mi][ni][0];
                pb[(row + 8) * 72 + 64] = acc[mi][ni][2];
            }
        }
}

__global__ void kv_reduce(const float* __restrict__ partial,
                          float* __restrict__ kv, float* __restrict__ z)
{
    int bh = blockIdx.x;
    for (int j = threadIdx.x; j < 256 * 72; j += 256) {
        float s = 0.f;
        #pragma unroll
        for (int c = 0; c < 8; c++)
            s += partial[((size_t)(bh * 8 + c)) * (256 * 72) + j];
        int m = j / 72, k2 = j - m * 72;
        if (k2 < 64) kv[(size_t)bh * (M_F * HK) + m * 64 + k2] = s;
        else if (k2 == 64) z[bh * M_F + m] = s;
    }
}

// ---------------- tensorized num/den: attn = (pq @ kv) / (pq @ z) ------------
#define ND_BSTR  260
#define ND_B_OFF 0
#define ND_Z_OFF (64 * ND_BSTR * 4)
#define ND_A_OFF (ND_Z_OFF + 1024)
#define ND_SM    (ND_A_OFF + 2 * TILEB)

__global__ __launch_bounds__(256, 2)
void numden_mma(const float* __restrict__ pq, const float* __restrict__ kvg,
                const float* __restrict__ zg, float* __restrict__ attn)
{
    extern __shared__ char sm[];
    unsigned smu = smem_u32(sm);
    float* Bsf   = (float*)(sm + ND_B_OFF);
    float* z_s   = (float*)(sm + ND_Z_OFF);
    float* den_s = (float*)(sm + ND_B_OFF);
    float* stage = (float*)(sm + ND_A_OFF);

    int bh = blockIdx.x >> 5;
    int chunk = blockIdx.x & 31;
    int b = bh >> 4, h = bh & 15;
    int tid = threadIdx.x, wid = tid >> 5, lane = tid & 31;
    int s0 = chunk * 128;

    const float* pqb = pq + ((size_t)bh * S_LEN + s0) * M_F;

    int arow[4], aseg[4];
    unsigned adst[4];
    #pragma unroll
    for (int i = 0; i < 4; i++) {
        int u = tid + 256 * i;
        arow[i] = u >> 3; aseg[i] = u & 7;
        adst[i] = smu + ND_A_OFF + (unsigned)(arow[i] * TSTR + aseg[i] * 4) * 4;
    }

    #pragma unroll
    for (int s = 0; s < 2; s++) {
        const float* Ac = pqb + s * 32;
        unsigned so = s * TILEB;
        #pragma unroll
        for (int i = 0; i < 4; i++)
            CP16(adst[i] + so, Ac + (size_t)arow[i] * M_F + aseg[i] * 4);
        CP_COMMIT();
    }

    {
        const float* kvb = kvg + (size_t)bh * (M_F * HK);
        for (int i = tid; i < M_F * HK; i += 256) {
            int m = i >> 6, k = i & 63;
            Bsf[k * ND_BSTR + m] = rn_tf32(kvb[i]);
        }
        z_s[tid] = zg[bh * M_F + tid];
    }

    float acc[2][4][4];
    #pragma unroll
    for (int mi = 0; mi < 2; mi++)
        #pragma unroll
        for (int ni = 0; ni < 4; ni++)
            #pragma unroll
            for (int j = 0; j < 4; j++) acc[mi][ni][j] = 0.f;

    int kfrag = lane & 3;
    int mrow = (wid & 3) * 32 + (lane >> 2);
    int nrow = (wid >> 2) * 32 + (lane >> 2);
    const unsigned* Bsu = (const unsigned*)Bsf;

    for (int c = 0; c < 8; c++) {
        int p = c & 1;
        CP_WAIT1();
        __syncthreads();

        const unsigned* As = (const unsigned*)(sm + ND_A_OFF + p * TILEB);
        #pragma unroll
        for (int ks = 0; ks < 4; ks++) {
            int kk = ks * 8 + kfrag;
            unsigned afr[2][4], bfr[4][2];
            #pragma unroll
            for (int mi = 0; mi < 2; mi++) {
                const unsigned* ap = As + (mrow + mi * 16) * TSTR + kk;
                afr[mi][0] = ap[0];
                afr[mi][1] = ap[8 * TSTR];
                afr[mi][2] = ap[4];
                afr[mi][3] = ap[8 * TSTR + 4];
            }
            #pragma unroll
            for (int ni = 0; ni < 4; ni++) {
                const unsigned* bp = Bsu + (nrow + ni * 8) * ND_BSTR + c * 32 + kk;
                bfr[ni][0] = bp[0];
                bfr[ni][1] = bp[4];
            }
            #pragma unroll
            for (int mi = 0; mi < 2; mi++)
                #pragma unroll
                for (int ni = 0; ni < 4; ni++)
                    mma_tf32(acc[mi][ni], afr[mi], bfr[ni]);
        }
        __syncthreads();

        if (c + 2 < 8) {
            const float* Ac = pqb + (c + 2) * 32;
            unsigned so = p * TILEB;
            #pragma unroll
            for (int i = 0; i < 4; i++)
                CP16(adst[i] + so, Ac + (size_t)arow[i] * M_F + aseg[i] * 4);
        }
        CP_COMMIT();
    }
    CP_WAIT0();
    __syncthreads();

    #pragma unroll
    for (int mi = 0; mi < 2; mi++)
        #pragma unroll
        for (int ni = 0; ni < 4; ni++) {
            int row = (wid & 3) * 32 + mi * 16 + (lane >> 2);
            int col = (wid >> 2) * 32 + ni * 8 + (lane & 3) * 2;
            *(float2*)(stage + row * 68 + col) =
                make_float2(acc[mi][ni][0], acc[mi][ni][1]);
            *(float2*)(stage + (row + 8) * 68 + col) =
                make_float2(acc[mi][ni][2], acc[mi][ni][3]);
        }

    {
        int row = tid >> 1, half = tid & 1;
        const float* prow = pqb + (size_t)row * M_F + half * 128;
        const float* zr = z_s + half * 128;
        float dp = 0.f;
        #pragma unroll 8
        for (int j = 0; j < 32; j++) {
            float4 pv = ((const float4*)prow)[j];
            float4 zv = ((const float4*)zr)[j];
            dp += pv.x * zv.x + pv.y * zv.y + pv.z * zv.z + pv.w * zv.w;
        }
        dp += __shfl_xor_sync(0xFFFFFFFFu, dp, 1);
        if (half == 0) den_s[row] = dp;
    }
    __syncthreads();

    #pragma unroll
    for (int i = 0; i < 8; i++) {
        int u = tid + 256 * i;
        int row = u >> 4, c4 = u & 15;
        float4 v = *(const float4*)(stage + row * 68 + c4 * 4);
        float rd = 1.0f / den_s[row];
        float* dst = attn + ((size_t)(b * S_LEN + s0 + row)) * D_MOD + h * 64 + c4 * 4;
        *(float4*)dst = make_float4(rn_tf32(v.x * rd), rn_tf32(v.y * rd),
                                    rn_tf32(v.z * rd), rn_tf32(v.w * rd));
    }
}

// ---------------- LayerNorm ----------------
template<int RND>
__global__ void ln_kernel(const float* __restrict__ X, const float* __restrict__ g,
                          const float* __restrict__ bv, float* __restrict__ out)
{
    int row = blockIdx.x, tid = threadIdx.x;
    float4 v = ((const float4*)(X + (size_t)row * D_MOD))[tid];
    float s = v.x + v.y + v.z + v.w;
    __shared__ float ws[8];
    #pragma unroll
    for (int o = 16; o; o >>= 1) s += __shfl_xor_sync(0xFFFFFFFFu, s, o);
    if ((tid & 31) == 0) ws[tid >> 5] = s;
    __syncthreads();
    float tot = 0.f;
    #pragma unroll
    for (int w = 0; w < 8; w++) tot += ws[w];
    float mu = tot * (1.f / 1024.f);
    float dx = v.x - mu, dy = v.y - mu, dz = v.z - mu, dw = v.w - mu;
    float sqvv = dx*dx + dy*dy + dz*dz + dw*dw;
    __syncthreads();
    #pragma unroll
    for (int o = 16; o; o >>= 1) sqvv += __shfl_xor_sync(0xFFFFFFFFu, sqvv, o);
    if ((tid & 31) == 0) ws[tid >> 5] = sqvv;
    __syncthreads();
    float tot2 = 0.f;
    #pragma unroll
    for (int w = 0; w < 8; w++) tot2 += ws[w];
    float rs = rsqrtf(tot2 * (1.f / 1024.f) + 1e-6f);
    float4 gg = ((const float4*)g)[tid];
    float4 bb = ((const float4*)bv)[tid];
    float4 o4 = make_float4(dx*rs*gg.x + bb.x, dy*rs*gg.y + bb.y,
                            dz*rs*gg.z + bb.z, dw*rs*gg.w + bb.w);
    if (RND) o4 = make_float4(rn_tf32(o4.x), rn_tf32(o4.y), rn_tf32(o4.z), rn_tf32(o4.w));
    ((float4*)(out + (size_t)row * D_MOD))[tid] = o4;
}

// ---------------- orchestration ----------------
extern "C" void kernel_launch(void* const* d_in, const int* in_sizes, int n_in,
                              void* d_out, int out_size)
{
    const float* x     = (const float*)d_in[0];
    const float* wq    = (const float*)d_in[1];
    const float* wk    = (const float*)d_in[2];
    const float* wv    = (const float*)d_in[3];
    const float* wo    = (const float*)d_in[4];
    const float* omega = (const float*)d_in[5];
    const float* ln1g  = (const float*)d_in[6];
    const float* ln1b  = (const float*)d_in[7];
    const float* w1    = (const float*)d_in[8];
    const float* b1    = (const float*)d_in[9];
    const float* w2    = (const float*)d_in[10];
    const float* b2    = (const float*)d_in[11];
    const float* ln2g  = (const float*)d_in[12];
    const float* ln2b  = (const float*)d_in[13];
    float* out = (float*)d_out;

    float *q, *k, *v, *xr, *pq, *pk, *kv, *z, *kvp, *attn, *y, *x1, *act;
    float *wqT, *wkT, *wvT, *woT, *w1T, *w2T;
    cudaGetSymbolAddress((void**)&q,    g_q);
    cudaGetSymbolAddress((void**)&k,    g_k);
    cudaGetSymbolAddress((void**)&v,    g_v);
    cudaGetSymbolAddress((void**)&xr,   g_xr);
    cudaGetSymbolAddress((void**)&pq,   g_pq);
    cudaGetSymbolAddress((void**)&pk,   g_pk);
    cudaGetSymbolAddress((void**)&kv,   g_kv);
    cudaGetSymbolAddress((void**)&z,    g_z);
    cudaGetSymbolAddress((void**)&kvp,  g_kvp);
    cudaGetSymbolAddress((void**)&attn, g_attn);
    cudaGetSymbolAddress((void**)&y,    g_y);
    cudaGetSymbolAddress((void**)&x1,   g_x1);
    cudaGetSymbolAddress((void**)&act,  g_act);
    cudaGetSymbolAddress((void**)&wqT,  g_wqT);
    cudaGetSymbolAddress((void**)&wkT,  g_wkT);
    cudaGetSymbolAddress((void**)&wvT,  g_wvT);
    cudaGetSymbolAddress((void**)&woT,  g_woT);
    cudaGetSymbolAddress((void**)&w1T,  g_w1T);
    cudaGetSymbolAddress((void**)&w2T,  g_w2T);

    cudaFuncSetAttribute(numden_mma, cudaFuncAttributeMaxDynamicSharedMemorySize, ND_SM);
    cudaFuncSetAttribute(phi_mma, cudaFuncAttributeMaxDynamicSharedMemorySize, PHI_SM);
    cudaFuncSetAttribute(kv_mma, cudaFuncAttributeMaxDynamicSharedMemorySize, KV_SM);
    cudaFuncSetAttribute(tc_gemm<0>, cudaFuncAttributeMaxDynamicSharedMemorySize, SM_DYN);
    cudaFuncSetAttribute(tc_gemm<1>, cudaFuncAttributeMaxDynamicSharedMemorySize, SM_DYN);
    cudaFuncSetAttribute(tc_gemm<2>, cudaFuncAttributeMaxDynamicSharedMemorySize, SM_DYN);
    cudaFuncSetAttribute(tc_gemm<3>, cudaFuncAttributeMaxDynamicSharedMemorySize, SM_DYN);
    cudaFuncSetAttribute(tc_gemm<4>, cudaFuncAttributeMaxDynamicSharedMemorySize, SM_DYN);

    dim3 tb(32, 8);
    transpose_k<<<dim3(32, 32),   tb>>>(wq, wqT, 1024, 1024);
    transpose_k<<<dim3(32, 32),   tb>>>(wk, wkT, 1024, 1024);
    transpose_k<<<dim3(32, 32),   tb>>>(wv, wvT, 1024, 1024);
    transpose_k<<<dim3(32, 32),   tb>>>(wo, woT, 1024, 1024);
    transpose_k<<<dim3(128, 32),  tb>>>(w1, w1T, 1024, 4096);
    transpose_k<<<dim3(32, 128),  tb>>>(w2, w2T, 4096, 1024);
    round_kernel<<<(N_TOK * D_MOD / 4 + 255) / 256, 256>>>(x, xr, N_TOK * D_MOD / 4);

    dim3 gD(D_MOD / 128, N_TOK / 128);   // (8, 128)
    dim3 gF(FF_D / 128, N_TOK / 128);    // (32, 128)

    tc_gemm<0><<<gD, 256, SM_DYN>>>(xr, wqT, nullptr, nullptr, q, D_MOD, D_MOD);
    tc_gemm<0><<<gD, 256, SM_DYN>>>(xr, wkT, nullptr, nullptr, k, D_MOD, D_MOD);
    tc_gemm<4><<<gD, 256, SM_DYN>>>(xr, wvT, nullptr, nullptr, v, D_MOD, D_MOD);

    phi_mma<<<2048, 512, PHI_SM>>>(q, omega, pq);
    phi_mma<<<2048, 512, PHI_SM>>>(k, omega, pk);

    kv_mma<<<512, 256, KV_SM>>>(pk, v, kvp);
    kv_reduce<<<64, 256>>>(kvp, kv, z);

    numden_mma<<<2048, 256, ND_SM>>>(pq, kv, z, attn);

    tc_gemm<1><<<gD, 256, SM_DYN>>>(attn, woT, nullptr, x, y, D_MOD, D_MOD);
    ln_kernel<1><<<N_TOK, 256>>>(y, ln1g, ln1b, x1);

    tc_gemm<2><<<gF, 256, SM_DYN>>>(x1, w1T, b1, nullptr, act, D_MOD, FF_D);
    tc_gemm<3><<<gD, 256, SM_DYN>>>(act, w2T, b2, x1, y, FF_D, D_MOD);
    ln_kernel<0><<<N_TOK, 256>>>(y, ln2g, ln2b, out);
}

// round 12
// speedup vs baseline: 2.2494x; 1.6194x over previous
#include <cuda_runtime.h>
#include <cuda_fp16.h>
#include <math.h>

#define N_TOK 16384
#define D_MOD 1024
#define H_N   16
#define HK    64
#define M_F   256
#define FF_D  4096
#define S_LEN 4096
#define PHI_SCALE 0.35355339059327373f   // 64^-0.25
#define RSQRT_M  0.0625f                 // 1/sqrt(256)

// ---------------- scratch (device globals; allocation-free) ----------------
__device__ __half g_q   [N_TOK * D_MOD];
__device__ __half g_k   [N_TOK * D_MOD];
__device__ float  g_v   [N_TOK * D_MOD];
__device__ __half g_xr  [N_TOK * D_MOD];
__device__ __half g_pq  [64 * S_LEN * M_F];
__device__ float  g_pk  [64 * S_LEN * M_F];
__device__ float  g_kv  [64 * M_F * HK];
__device__ float  g_z   [64 * M_F];
__device__ float  g_kvp [512 * 256 * 72];
__device__ __half g_attn[N_TOK * D_MOD];
__device__ float  g_y   [N_TOK * D_MOD];
__device__ __half g_x1  [N_TOK * D_MOD];
__device__ __half g_act [N_TOK * FF_D];
__device__ __half g_wqT [D_MOD * D_MOD];
__device__ __half g_wkT [D_MOD * D_MOD];
__device__ __half g_wvT [D_MOD * D_MOD];
__device__ __half g_woT [D_MOD * D_MOD];
__device__ __half g_w1T [D_MOD * FF_D];
__device__ __half g_w2T [D_MOD * FF_D];

__device__ __forceinline__ unsigned smem_u32(const void* p) {
    unsigned a;
    asm("{ .reg .u64 t; cvta.to.shared.u64 t, %1; cvt.u32.u64 %0, t; }" : "=r"(a) : "l"(p));
    return a;
}
__device__ __forceinline__ float rn_tf32(float f) {
    unsigned u;
    asm("cvt.rn.tf32.f32 %0, %1;" : "=r"(u) : "f"(f));
    return __uint_as_float(u);
}

__device__ __forceinline__ void mma_f16(float* d, const unsigned* a, const unsigned* b) {
    asm volatile(
        "mma.sync.aligned.m16n8k16.row.col.f32.f16.f16.f32 "
        "{%0,%1,%2,%3}, {%4,%5,%6,%7}, {%8,%9}, {%0,%1,%2,%3};"
        : "+f"(d[0]), "+f"(d[1]), "+f"(d[2]), "+f"(d[3])
        : "r"(a[0]), "r"(a[1]), "r"(a[2]), "r"(a[3]), "r"(b[0]), "r"(b[1]));
}
__device__ __forceinline__ void mma_tf32(float* d, const unsigned* a, const unsigned* b) {
    asm volatile(
        "mma.sync.aligned.m16n8k8.row.col.f32.tf32.tf32.f32 "
        "{%0,%1,%2,%3}, {%4,%5,%6,%7}, {%8,%9}, {%0,%1,%2,%3};"
        : "+f"(d[0]), "+f"(d[1]), "+f"(d[2]), "+f"(d[3])
        : "r"(a[0]), "r"(a[1]), "r"(a[2]), "r"(a[3]), "r"(b[0]), "r"(b[1]));
}

#define CP16(dst, src) \
    asm volatile("cp.async.ca.shared.global [%0], [%1], 16;" :: "r"(dst), "l"(src))
#define CP_COMMIT() asm volatile("cp.async.commit_group;" ::: "memory")
#define CP_WAIT1()  asm volatile("cp.async.wait_group 1;" ::: "memory")
#define CP_WAIT0()  asm volatile("cp.async.wait_group 0;" ::: "memory")

// ---------------- fp16 warp-MMA GEMM: C[M,N] = A[M,Kd] @ BT[N,Kd]^T ----------
// 128x128 CTA tile, 8 warps (64x32), K-chunk 64 halves, 3 slots, 1 sync/chunk.
// EPI: 0 half-out, 1 +Rf(float) float-out, 2 gelu(x+bias) half-out,
//      3 +bias+Rh(half) float-out, 4 float-out rn_tf32
#define HSTR   72
#define TILEB  (128 * HSTR * 2)          // 18432 bytes
#define STAGEB (2 * TILEB)               // 36864
#define SM_DYN (3 * STAGEB)              // 110592

template<int EPI>
__global__ __launch_bounds__(256, 2)
void tc_gemm(const __half* __restrict__ A, const __half* __restrict__ BT,
             const float* __restrict__ bias, const float* __restrict__ Rf,
             const __half* __restrict__ Rh, void* __restrict__ Cv,
             int Kd, int NC)
{
    extern __shared__ char sm[];
    unsigned smu = smem_u32(sm);
    int tid = threadIdx.x, wid = tid >> 5, lane = tid & 31;
    int r0 = blockIdx.y * 128, c0 = blockIdx.x * 128;
    int wm = wid & 1, wn = wid >> 1;

    const __half* Ab = A + (size_t)r0 * Kd;
    const __half* Bb = BT + (size_t)c0 * Kd;

    // copy mapping: per tile 128 rows x 8 segs(16B=8 halves), 4 iters
    int crow[4], cseg[4];
    unsigned cdst[4];
    #pragma unroll
    for (int i = 0; i < 4; i++) {
        int u = tid + 256 * i;
        crow[i] = u >> 3; cseg[i] = u & 7;
        cdst[i] = smu + (unsigned)(crow[i] * (HSTR * 2) + cseg[i] * 16);
    }

    float acc[4][4][4];
    #pragma unroll
    for (int mi = 0; mi < 4; mi++)
        #pragma unroll
        for (int ni = 0; ni < 4; ni++)
            #pragma unroll
            for (int j = 0; j < 4; j++) acc[mi][ni][j] = 0.f;

    int nk = Kd >> 6;

    #pragma unroll
    for (int s = 0; s < 2; s++) {
        const __half* Ac = Ab + s * 64;
        const __half* Bc = Bb + s * 64;
        unsigned so = s * STAGEB;
        #pragma unroll
        for (int i = 0; i < 4; i++) {
            CP16(cdst[i] + so,         Ac + (size_t)crow[i] * Kd + cseg[i] * 8);
            CP16(cdst[i] + so + TILEB, Bc + (size_t)crow[i] * Kd + cseg[i] * 8);
        }
        CP_COMMIT();
    }

    int c2 = (lane & 3) * 2;
    int mrow = wm * 64 + (lane >> 2);
    int nrow = wn * 32 + (lane >> 2);

    int p = 0, pn = 2;
    for (int c = 0; c < nk; c++) {
        CP_WAIT1();
        __syncthreads();

        if (c + 2 < nk) {
            const __half* Ac = Ab + (c + 2) * 64;
            const __half* Bc = Bb + (c + 2) * 64;
            unsigned so = pn * STAGEB;
            #pragma unroll
            for (int i = 0; i < 4; i++) {
                CP16(cdst[i] + so,         Ac + (size_t)crow[i] * Kd + cseg[i] * 8);
                CP16(cdst[i] + so + TILEB, Bc + (size_t)crow[i] * Kd + cseg[i] * 8);
            }
        }
        CP_COMMIT();

        const __half* As = (const __half*)(sm + p * STAGEB);
        const __half* Bs = (const __half*)(sm + p * STAGEB + TILEB);

        #pragma unroll
        for (int ks = 0; ks < 4; ks++) {
            int kk = ks * 16 + c2;
            unsigned afr[4][4], bfr[4][2];
            #pragma unroll
            for (int mi = 0; mi < 4; mi++) {
                const __half* ap = As + (mrow + mi * 16) * HSTR + kk;
                afr[mi][0] = *(const unsigned*)(ap);
                afr[mi][1] = *(const unsigned*)(ap + 8 * HSTR);
                afr[mi][2] = *(const unsigned*)(ap + 8);
                afr[mi][3] = *(const unsigned*)(ap + 8 * HSTR + 8);
            }
            #pragma unroll
            for (int ni = 0; ni < 4; ni++) {
                const __half* bp = Bs + (nrow + ni * 8) * HSTR + kk;
                bfr[ni][0] = *(const unsigned*)(bp);
                bfr[ni][1] = *(const unsigned*)(bp + 8);
            }
            #pragma unroll
            for (int mi = 0; mi < 4; mi++)
                #pragma unroll
                for (int ni = 0; ni < 4; ni++)
                    mma_f16(acc[mi][ni], afr[mi], bfr[ni]);
        }
        p = (p == 2) ? 0 : p + 1;
        pn = (pn == 2) ? 0 : pn + 1;
    }
    CP_WAIT0();
    __syncthreads();

    float* stage = (float*)sm;
    #pragma unroll
    for (int mi = 0; mi < 4; mi++)
        #pragma unroll
        for (int ni = 0; ni < 4; ni++) {
            int row = wm * 64 + mi * 16 + (lane >> 2);
            int col = wn * 32 + ni * 8 + (lane & 3) * 2;
            *(float2*)(stage + row * 132 + col) =
                make_float2(acc[mi][ni][0], acc[mi][ni][1]);
            *(float2*)(stage + (row + 8) * 132 + col) =
                make_float2(acc[mi][ni][2], acc[mi][ni][3]);
        }
    __syncthreads();

    #pragma unroll
    for (int i = 0; i < 16; i++) {
        int u = tid + 256 * i;
        int row = u >> 5, c4 = u & 31;
        float4 v = *(const float4*)(stage + row * 132 + c4 * 4);
        size_t base = (size_t)(r0 + row) * NC + c0 + c4 * 4;
        float vv[4] = {v.x, v.y, v.z, v.w};
        #pragma unroll
        for (int j = 0; j < 4; j++) {
            int col = c0 + c4 * 4 + j;
            if (EPI == 1) vv[j] += Rf[base + j];
            else if (EPI == 2) {
                float t = vv[j] + bias[col];
                vv[j] = 0.5f * t * (1.0f + erff(t * 0.70710678118654752f));
            } else if (EPI == 3) vv[j] += bias[col] + __half2float(Rh[base + j]);
            else if (EPI == 4) vv[j] = rn_tf32(vv[j]);
        }
        if (EPI == 0 || EPI == 2) {
            __half2 p0 = __floats2half2_rn(vv[0], vv[1]);
            __half2 p1 = __floats2half2_rn(vv[2], vv[3]);
            uint2 w;
            w.x = *(unsigned*)&p0; w.y = *(unsigned*)&p1;
            *(uint2*)((__half*)Cv + base) = w;
        } else {
            *(float4*)((float*)Cv + base) = make_float4(vv[0], vv[1], vv[2], vv[3]);
        }
    }
}

// ---------------- transpose + round to half ----------------
__global__ void transpose_k(const float* __restrict__ in, __half* __restrict__ out,
                            int R, int Cc)
{
    __shared__ float t[32][33];
    int x = blockIdx.x * 32 + threadIdx.x;
    int y = blockIdx.y * 32 + threadIdx.y;
    #pragma unroll
    for (int j = 0; j < 4; j++)
        t[threadIdx.y + j * 8][threadIdx.x] = in[(size_t)(y + j * 8) * Cc + x];
    __syncthreads();
    int ox = blockIdx.y * 32 + threadIdx.x;
    int oy = blockIdx.x * 32 + threadIdx.y;
    #pragma unroll
    for (int j = 0; j < 4; j++)
        out[(size_t)(oy + j * 8) * R + ox] = __float2half_rn(t[threadIdx.x][threadIdx.y + j * 8]);
}

__global__ void cvt_half_kernel(const float* __restrict__ in, __half* __restrict__ out, int n8)
{
    int i = blockIdx.x * blockDim.x + threadIdx.x;
    if (i < n8) {
        float4 a = ((const float4*)in)[2 * i];
        float4 b = ((const float4*)in)[2 * i + 1];
        __half2 h0 = __floats2half2_rn(a.x, a.y);
        __half2 h1 = __floats2half2_rn(a.z, a.w);
        __half2 h2 = __floats2half2_rn(b.x, b.y);
        __half2 h3 = __floats2half2_rn(b.z, b.w);
        uint4 w;
        w.x = *(unsigned*)&h0; w.y = *(unsigned*)&h1;
        w.z = *(unsigned*)&h2; w.w = *(unsigned*)&h3;
        ((uint4*)out)[i] = w;
    }
}

// ---------------- tensorized FAVOR+ (fp16 MMA) -------------------------------
// OUTHALF=1 -> dst half (pq); OUTHALF=0 -> dst float tf32-rounded (pk)
#define PHSTR 72
#define PHI_A_OFF 0
#define PHI_B_OFF (128 * PHSTR * 2)                 // 18432
#define PHI_STAGE_W 260
#define PHI_SQ_OFF  (128 * PHI_STAGE_W * 4)         // 133120
#define PHI_SM      (PHI_SQ_OFF + 128 * 4)          // 133632

template<int OUTHALF>
__global__ __launch_bounds__(512, 1)
void phi_mma(const __half* __restrict__ src, const float* __restrict__ omega,
             void* __restrict__ dstv)
{
    extern __shared__ char sm[];
    __half* As = (__half*)(sm + PHI_A_OFF);
    __half* Bs = (__half*)(sm + PHI_B_OFF);
    float* stage = (float*)sm;
    float* sqv   = (float*)(sm + PHI_SQ_OFF);

    int tid = threadIdx.x, wid = tid >> 5, lane = tid & 31;
    int rbase = blockIdx.x * 128;

    // fill A: u = rn_half(q*scale); sq[row] = 0.5*sum(u^2)
    {
        int row = tid >> 2, qtr = tid & 3;
        int r = rbase + row, n = r >> 4, h = r & 15;
        const __half2* s2 = (const __half2*)(src + (size_t)n * D_MOD + h * 64 + qtr * 16);
        unsigned outh[8];
        float ps = 0.f;
        #pragma unroll
        for (int j = 0; j < 8; j++) {
            float2 f = __half22float2(s2[j]);
            __half2 hh = __floats2half2_rn(f.x * PHI_SCALE, f.y * PHI_SCALE);
            float2 fr = __half22float2(hh);
            ps += fr.x * fr.x + fr.y * fr.y;
            outh[j] = *(unsigned*)&hh;
        }
        __half* dstA = As + row * PHSTR + qtr * 16;
        *(uint4*)(dstA)     = make_uint4(outh[0], outh[1], outh[2], outh[3]);
        *(uint4*)(dstA + 8) = make_uint4(outh[4], outh[5], outh[6], outh[7]);
        ps += __shfl_xor_sync(0xFFFFFFFFu, ps, 1);
        ps += __shfl_xor_sync(0xFFFFFFFFu, ps, 2);
        if (qtr == 0) sqv[row] = 0.5f * ps;
    }
    // fill B: rn_half(omega[m][k]) [256][72]
    {
        int m = tid >> 1, hf = tid & 1;
        const float* orow = omega + m * 64 + hf * 32;
        #pragma unroll
        for (int j = 0; j < 4; j++) {
            float4 a = ((const float4*)orow)[2 * j];
            float4 b = ((const float4*)orow)[2 * j + 1];
            __half2 h0 = __floats2half2_rn(a.x, a.y);
            __half2 h1 = __floats2half2_rn(a.z, a.w);
            __half2 h2 = __floats2half2_rn(b.x, b.y);
            __half2 h3 = __floats2half2_rn(b.z, b.w);
            uint4 w;
            w.x = *(unsigned*)&h0; w.y = *(unsigned*)&h1;
            w.z = *(unsigned*)&h2; w.w = *(unsigned*)&h3;
            *(uint4*)(Bs + m * PHSTR + hf * 32 + j * 8) = w;
        }
    }
    __syncthreads();

    float acc[2][8][4];
    #pragma unroll
    for (int mi = 0; mi < 2; mi++)
        #pragma unroll
        for (int ni = 0; ni < 8; ni++)
            #pragma unroll
            for (int j = 0; j < 4; j++) acc[mi][ni][j] = 0.f;

    int c2 = (lane & 3) * 2;
    int mrow = (wid & 3) * 32 + (lane >> 2);
    int nrow = (wid >> 2) * 64 + (lane >> 2);

    #pragma unroll
    for (int ks = 0; ks < 4; ks++) {
        int kk = ks * 16 + c2;
        unsigned afr[2][4], bfr[8][2];
        #pragma unroll
        for (int mi = 0; mi < 2; mi++) {
            const __half* ap = As + (mrow + mi * 16) * PHSTR + kk;
            afr[mi][0] = *(const unsigned*)(ap);
            afr[mi][1] = *(const unsigned*)(ap + 8 * PHSTR);
            afr[mi][2] = *(const unsigned*)(ap + 8);
            afr[mi][3] = *(const unsigned*)(ap + 8 * PHSTR + 8);
        }
        #pragma unroll
        for (int ni = 0; ni < 8; ni++) {
            const __half* bp = Bs + (nrow + ni * 8) * PHSTR + kk;
            bfr[ni][0] = *(const unsigned*)(bp);
            bfr[ni][1] = *(const unsigned*)(bp + 8);
        }
        #pragma unroll
        for (int mi = 0; mi < 2; mi++)
            #pragma unroll
            for (int ni = 0; ni < 8; ni++)
                mma_f16(acc[mi][ni], afr[mi], bfr[ni]);
    }
    __syncthreads();   // A/B dead; stage aliases

    #pragma unroll
    for (int mi = 0; mi < 2; mi++)
        #pragma unroll
        for (int ni = 0; ni < 8; ni++) {
            int row = (wid & 3) * 32 + mi * 16 + (lane >> 2);
            int col = (wid >> 2) * 64 + ni * 8 + (lane & 3) * 2;
            *(float2*)(stage + row * PHI_STAGE_W + col) =
                make_float2(acc[mi][ni][0], acc[mi][ni][1]);
            *(float2*)(stage + (row + 8) * PHI_STAGE_W + col) =
                make_float2(acc[mi][ni][2], acc[mi][ni][3]);
        }
    __syncthreads();

    {
        int row = tid >> 2, seg = (tid & 3) * 64;
        const float* srow = stage + row * PHI_STAGE_W + seg;
        float mx = -1e30f;
        #pragma unroll
        for (int j = 0; j < 16; j++) {
            float4 v = ((const float4*)srow)[j];
            mx = fmaxf(mx, fmaxf(fmaxf(v.x, v.y), fmaxf(v.z, v.w)));
        }
        mx = fmaxf(mx, __shfl_xor_sync(0xFFFFFFFFu, mx, 1));
        mx = fmaxf(mx, __shfl_xor_sync(0xFFFFFFFFu, mx, 2));
        float sb = sqv[row] + mx;

        int r = rbase + row, n = r >> 4, h = r & 15;
        int b = n >> 12, s = n & 4095;
        size_t rowoff = (((size_t)(b * H_N + h)) * S_LEN + s) * M_F + seg;
        #pragma unroll
        for (int j = 0; j < 16; j++) {
            float4 v = ((const float4*)srow)[j];
            float e0 = __expf(v.x - sb) * RSQRT_M + 1e-6f;
            float e1 = __expf(v.y - sb) * RSQRT_M + 1e-6f;
            float e2 = __expf(v.z - sb) * RSQRT_M + 1e-6f;
            float e3 = __expf(v.w - sb) * RSQRT_M + 1e-6f;
            if (OUTHALF) {
                __half2 p0 = __floats2half2_rn(e0, e1);
                __half2 p1 = __floats2half2_rn(e2, e3);
                uint2 w;
                w.x = *(unsigned*)&p0; w.y = *(unsigned*)&p1;
                *(uint2*)((__half*)dstv + rowoff + j * 4) = w;
            } else {
                *(float4*)((float*)dstv + rowoff + j * 4) = make_float4(
                    rn_tf32(e0), rn_tf32(e1), rn_tf32(e2), rn_tf32(e3));
            }
        }
    }
}

// ---------------- tensorized kv (tf32, unchanged from R10) ------------------
#define KV_PSTR  264
#define KV_VSTR  104
#define KV_PKB   (32 * KV_PSTR * 4)
#define KV_VB    (32 * KV_VSTR * 4)
#define KV_STAGE (KV_PKB + KV_VB)
#define KV_SM    (2 * KV_STAGE)

__global__ __launch_bounds__(256, 2)
void kv_mma(const float* __restrict__ pk, const float* __restrict__ v,
            float* __restrict__ partial)
{
    extern __shared__ char sm[];
    unsigned smu = smem_u32(sm);
    int tid = threadIdx.x, wid = tid >> 5, lane = tid & 31;
    int bh = blockIdx.x >> 3, chunk = blockIdx.x & 7;
    int b = bh >> 4, h = bh & 15;
    int s0 = chunk * 512;

    const float* pkb = pk + ((size_t)bh * S_LEN + s0) * M_F;
    const float* vb  = v + ((size_t)(b * S_LEN + s0)) * D_MOD + h * 64;

    for (int i = tid; i < 32 * 16 * 2; i += 256) {
        int st = i >> 9, r = (i & 511) >> 4, cc = (i & 15) + 64;
        ((float*)(sm + st * KV_STAGE + KV_PKB))[r * KV_VSTR + cc] = (cc == 64) ? 1.f : 0.f;
    }
    __syncthreads();

    auto issue_copy = [&](int cc, int st) {
        unsigned base = smu + st * KV_STAGE;
        #pragma unroll
        for (int i2 = 0; i2 < 8; i2++) {
            int j = tid + 256 * i2;
            int row = j >> 6, seg = j & 63;
            CP16(base + (unsigned)(row * KV_PSTR + seg * 4) * 4,
                 pkb + (size_t)(cc * 32 + row) * M_F + seg * 4);
        }
        #pragma unroll
        for (int i2 = 0; i2 < 2; i2++) {
            int j = tid + 256 * i2;
            int row = j >> 4, seg = j & 15;
            CP16(base + KV_PKB + (unsigned)(row * KV_VSTR + seg * 4) * 4,
                 vb + (size_t)(cc * 32 + row) * D_MOD + seg * 4);
        }
    };

    float acc[4][5][4];
    #pragma unroll
    for (int mi = 0; mi < 4; mi++)
        #pragma unroll
        for (int ni = 0; ni < 5; ni++)
            #pragma unroll
            for (int j = 0; j < 4; j++) acc[mi][ni][j] = 0.f;

    issue_copy(0, 0); CP_COMMIT();
    issue_copy(1, 1); CP_COMMIT();

    int mbase = (wid & 3) * 64 + (lane >> 2);
    int nbase = (wid >> 2) * 40 + (lane >> 2);

    for (int c = 0; c < 16; c++) {
        int p = c & 1;
        CP_WAIT1();
        __syncthreads();

        const unsigned* As = (const unsigned*)(sm + p * KV_STAGE);
        const unsigned* Vs = (const unsigned*)(sm + p * KV_STAGE + KV_PKB);

        #pragma unroll
        for (int ks = 0; ks < 4; ks++) {
            int kk = ks * 8 + (lane & 3);
            unsigned afr[4][4], bfr[5][2];
            #pragma unroll
            for (int mi = 0; mi < 4; mi++) {
                int mr = mbase + mi * 16;
                afr[mi][0] = As[kk * KV_PSTR + mr];
                afr[mi][1] = As[kk * KV_PSTR + mr + 8];
                afr[mi][2] = As[(kk + 4) * KV_PSTR + mr];
                afr[mi][3] = As[(kk + 4) * KV_PSTR + mr + 8];
            }
            #pragma unroll
            for (int ni = 0; ni < 5; ni++) {
                int nr = nbase + ni * 8;
                bfr[ni][0] = Vs[kk * KV_VSTR + nr];
                bfr[ni][1] = Vs[(kk + 4) * KV_VSTR + nr];
            }
            #pragma unroll
            for (int mi = 0; mi < 4; mi++)
                #pragma unroll
                for (int ni = 0; ni < 5; ni++)
                    mma_tf32(acc[mi][ni], afr[mi], bfr[ni]);
        }
        __syncthreads();

        if (c + 2 < 16) issue_copy(c + 2, p);
        CP_COMMIT();
    }

    float* pb = partial + (size_t)blockIdx.x * (256 * 72);
    #pragma unroll
    for (int mi = 0; mi < 4; mi++)
        #pragma unroll
        for (int ni = 0; ni < 5; ni++) {
            int row = (wid & 3) * 64 + mi * 16 + (lane >> 2);
            int col = (wid >> 2) * 40 + ni * 8 + (lane & 3) * 2;
            if (col < 64) {
                *(float2*)(pb + row * 72 + col) =
                    make_float2(acc[mi][ni][0], acc[mi][ni][1]);
                *(float2*)(pb + (row + 8) * 72 + col) =
                    make_float2(acc[mi][ni][2], acc[mi][ni][3]);
            } else if (col == 64) {
                pb[row * 72 + 64] = acc[mi][ni][0];
                pb[(row + 8) * 72 + 64] = acc[mi][ni][2];
            }
        }
}

__global__ void kv_reduce(const float* __restrict__ partial,
                          float* __restrict__ kv, float* __restrict__ z)
{
    int bh = blockIdx.x;
    for (int j = threadIdx.x; j < 256 * 72; j += 256) {
        float s = 0.f;
        #pragma unroll
        for (int c = 0; c < 8; c++)
            s += partial[((size_t)(bh * 8 + c)) * (256 * 72) + j];
        int m = j / 72, k2 = j - m * 72;
        if (k2 < 64) kv[(size_t)bh * (M_F * HK) + m * 64 + k2] = s;
        else if (k2 == 64) z[bh * M_F + m] = s;
    }
}

// ---------------- fp16 num/den: attn = (pq @ kv) / (pq @ z) ------------------
#define ND_BSTR  264
#define ND_B_OFF 0
#define ND_Z_OFF (64 * ND_BSTR * 2)              // 33792
#define ND_A_OFF (ND_Z_OFF + 1024)               // 34816
#define ND_SM    (ND_A_OFF + 2 * TILEB)          // 71680

__global__ __launch_bounds__(256, 2)
void numden_mma(const __half* __restrict__ pq, const float* __restrict__ kvg,
                const float* __restrict__ zg, __half* __restrict__ attn)
{
    extern __shared__ char sm[];
    unsigned smu = smem_u32(sm);
    __half* Bsf  = (__half*)(sm + ND_B_OFF);
    float* z_s   = (float*)(sm + ND_Z_OFF);
    float* den_s = (float*)(sm + ND_B_OFF);      // aliases Bs after MMA
    float* stage = (float*)(sm + ND_A_OFF);      // aliases As after MMA

    int bh = blockIdx.x >> 5;
    int chunk = blockIdx.x & 31;
    int b = bh >> 4, h = bh & 15;
    int tid = threadIdx.x, wid = tid >> 5, lane = tid & 31;
    int s0 = chunk * 128;

    const __half* pqb = pq + ((size_t)bh * S_LEN + s0) * M_F;

    // A copy: chunk = [128 rows][64 halves] -> 8 segs/row, 4 iters
    int arow[4], aseg[4];
    unsigned adst[4];
    #pragma unroll
    for (int i = 0; i < 4; i++) {
        int u = tid + 256 * i;
        arow[i] = u >> 3; aseg[i] = u & 7;
        adst[i] = smu + ND_A_OFF + (unsigned)(arow[i] * (HSTR * 2) + aseg[i] * 16);
    }

    #pragma unroll
    for (int s = 0; s < 2; s++) {
        const __half* Ac = pqb + s * 64;
        unsigned so = s * TILEB;
        #pragma unroll
        for (int i = 0; i < 4; i++)
            CP16(adst[i] + so, Ac + (size_t)arow[i] * M_F + aseg[i] * 8);
        CP_COMMIT();
    }

    {
        const float* kvb = kvg + (size_t)bh * (M_F * HK);
        for (int i = tid; i < M_F * HK; i += 256) {
            int m = i >> 6, k = i & 63;
            Bsf[k * ND_BSTR + m] = __float2half_rn(kvb[i]);
        }
        z_s[tid] = zg[bh * M_F + tid];
    }

    float acc[2][4][4];
    #pragma unroll
    for (int mi = 0; mi < 2; mi++)
        #pragma unroll
        for (int ni = 0; ni < 4; ni++)
            #pragma unroll
            for (int j = 0; j < 4; j++) acc[mi][ni][j] = 0.f;

    int c2 = (lane & 3) * 2;
    int mrow = (wid & 3) * 32 + (lane >> 2);
    int nrow = (wid >> 2) * 32 + (lane >> 2);

    for (int c = 0; c < 4; c++) {
        int p = c & 1;
        CP_WAIT1();
        __syncthreads();

        const __half* As = (const __half*)(sm + ND_A_OFF + p * TILEB);
        #pragma unroll
        for (int ks = 0; ks < 4; ks++) {
            int kk = ks * 16 + c2;
            unsigned afr[2][4], bfr[4][2];
            #pragma unroll
            for (int mi = 0; mi < 2; mi++) {
                const __half* ap = As + (mrow + mi * 16) * HSTR + kk;
                afr[mi][0] = *(const unsigned*)(ap);
                afr[mi][1] = *(const unsigned*)(ap + 8 * HSTR);
                afr[mi][2] = *(const unsigned*)(ap + 8);
                afr[mi][3] = *(const unsigned*)(ap + 8 * HSTR + 8);
            }
            #pragma unroll
            for (int ni = 0; ni < 4; ni++) {
                const __half* bp = Bsf + (nrow + ni * 8) * ND_BSTR + c * 64 + kk;
                bfr[ni][0] = *(const unsigned*)(bp);
                bfr[ni][1] = *(const unsigned*)(bp + 8);
            }
            #pragma unroll
            for (int mi = 0; mi < 2; mi++)
                #pragma unroll
                for (int ni = 0; ni < 4; ni++)
                    mma_f16(acc[mi][ni], afr[mi], bfr[ni]);
        }
        __syncthreads();

        if (c + 2 < 4) {
            const __half* Ac = pqb + (c + 2) * 64;
            unsigned so = p * TILEB;
            #pragma unroll
            for (int i = 0; i < 4; i++)
                CP16(adst[i] + so, Ac + (size_t)arow[i] * M_F + aseg[i] * 8);
        }
        CP_COMMIT();
    }
    CP_WAIT0();
    __syncthreads();

    #pragma unroll
    for (int mi = 0; mi < 2; mi++)
        #pragma unroll
        for (int ni = 0; ni < 4; ni++) {
            int row = (wid & 3) * 32 + mi * 16 + (lane >> 2);
            int col = (wid >> 2) * 32 + ni * 8 + (lane & 3) * 2;
            *(float2*)(stage + row * 68 + col) =
                make_float2(acc[mi][ni][0], acc[mi][ni][1]);
            *(float2*)(stage + (row + 8) * 68 + col) =
                make_float2(acc[mi][ni][2], acc[mi][ni][3]);
        }

    // den: 2 threads/row, 128 m each, from global pq(half) + z_s
    {
        int row = tid >> 1, half = tid & 1;
        const __half2* pr = (const __half2*)(pqb + (size_t)row * M_F + half * 128);
        const float* zr = z_s + half * 128;
        float dp = 0.f;
        #pragma unroll 8
        for (int j = 0; j < 64; j++) {
            float2 f = __half22float2(pr[j]);
            dp += f.x * zr[2 * j] + f.y * zr[2 * j + 1];
        }
        dp += __shfl_xor_sync(0xFFFFFFFFu, dp, 1);
        if (half == 0) den_s[row] = dp;
    }
    __syncthreads();

    #pragma unroll
    for (int i = 0; i < 8; i++) {
        int u = tid + 256 * i;
        int row = u >> 4, c4 = u & 15;
        float4 v = *(const float4*)(stage + row * 68 + c4 * 4);
        float rd = 1.0f / den_s[row];
        __half2 p0 = __floats2half2_rn(v.x * rd, v.y * rd);
        __half2 p1 = __floats2half2_rn(v.z * rd, v.w * rd);
        uint2 w;
        w.x = *(unsigned*)&p0; w.y = *(unsigned*)&p1;
        *(uint2*)(attn + ((size_t)(b * S_LEN + s0 + row)) * D_MOD + h * 64 + c4 * 4) = w;
    }
}

// ---------------- LayerNorm (OUTHALF: write half) ----------------
template<int OUTHALF>
__global__ void ln_kernel(const float* __restrict__ X, const float* __restrict__ g,
                          const float* __restrict__ bv, void* __restrict__ outv)
{
    int row = blockIdx.x, tid = threadIdx.x;
    float4 v = ((const float4*)(X + (size_t)row * D_MOD))[tid];
    float s = v.x + v.y + v.z + v.w;
    __shared__ float ws[8];
    #pragma unroll
    for (int o = 16; o; o >>= 1) s += __shfl_xor_sync(0xFFFFFFFFu, s, o);
    if ((tid & 31) == 0) ws[tid >> 5] = s;
    __syncthreads();
    float tot = 0.f;
    #pragma unroll
    for (int w = 0; w < 8; w++) tot += ws[w];
    float mu = tot * (1.f / 1024.f);
    float dx = v.x - mu, dy = v.y - mu, dz = v.z - mu, dw = v.w - mu;
    float sqvv = dx*dx + dy*dy + dz*dz + dw*dw;
    __syncthreads();
    #pragma unroll
    for (int o = 16; o; o >>= 1) sqvv += __shfl_xor_sync(0xFFFFFFFFu, sqvv, o);
    if ((tid & 31) == 0) ws[tid >> 5] = sqvv;
    __syncthreads();
    float tot2 = 0.f;
    #pragma unroll
    for (int w = 0; w < 8; w++) tot2 += ws[w];
    float rs = rsqrtf(tot2 * (1.f / 1024.f) + 1e-6f);
    float4 gg = ((const float4*)g)[tid];
    float4 bb = ((const float4*)bv)[tid];
    float o0 = dx*rs*gg.x + bb.x, o1 = dy*rs*gg.y + bb.y;
    float o2 = dz*rs*gg.z + bb.z, o3 = dw*rs*gg.w + bb.w;
    if (OUTHALF) {
        __half2 p0 = __floats2half2_rn(o0, o1);
        __half2 p1 = __floats2half2_rn(o2, o3);
        uint2 w;
        w.x = *(unsigned*)&p0; w.y = *(unsigned*)&p1;
        *(uint2*)((__half*)outv + (size_t)row * D_MOD + tid * 4) = w;
    } else {
        ((float4*)((float*)outv + (size_t)row * D_MOD))[tid] =
            make_float4(o0, o1, o2, o3);
    }
}

// ---------------- orchestration ----------------
extern "C" void kernel_launch(void* const* d_in, const int* in_sizes, int n_in,
                              void* d_out, int out_size)
{
    const float* x     = (const float*)d_in[0];
    const float* wq    = (const float*)d_in[1];
    const float* wk    = (const float*)d_in[2];
    const float* wv    = (const float*)d_in[3];
    const float* wo    = (const float*)d_in[4];
    const float* omega = (const float*)d_in[5];
    const float* ln1g  = (const float*)d_in[6];
    const float* ln1b  = (const float*)d_in[7];
    const float* w1    = (const float*)d_in[8];
    const float* b1    = (const float*)d_in[9];
    const float* w2    = (const float*)d_in[10];
    const float* b2    = (const float*)d_in[11];
    const float* ln2g  = (const float*)d_in[12];
    const float* ln2b  = (const float*)d_in[13];
    float* out = (float*)d_out;

    __half *q, *k, *xr, *pq, *attn, *x1, *act;
    float *v, *pk, *kv, *z, *kvp, *y;
    __half *wqT, *wkT, *wvT, *woT, *w1T, *w2T;
    cudaGetSymbolAddress((void**)&q,    g_q);
    cudaGetSymbolAddress((void**)&k,    g_k);
    cudaGetSymbolAddress((void**)&v,    g_v);
    cudaGetSymbolAddress((void**)&xr,   g_xr);
    cudaGetSymbolAddress((void**)&pq,   g_pq);
    cudaGetSymbolAddress((void**)&pk,   g_pk);
    cudaGetSymbolAddress((void**)&kv,   g_kv);
    cudaGetSymbolAddress((void**)&z,    g_z);
    cudaGetSymbolAddress((void**)&kvp,  g_kvp);
    cudaGetSymbolAddress((void**)&attn, g_attn);
    cudaGetSymbolAddress((void**)&y,    g_y);
    cudaGetSymbolAddress((void**)&x1,   g_x1);
    cudaGetSymbolAddress((void**)&act,  g_act);
    cudaGetSymbolAddress((void**)&wqT,  g_wqT);
    cudaGetSymbolAddress((void**)&wkT,  g_wkT);
    cudaGetSymbolAddress((void**)&wvT,  g_wvT);
    cudaGetSymbolAddress((void**)&woT,  g_woT);
    cudaGetSymbolAddress((void**)&w1T,  g_w1T);
    cudaGetSymbolAddress((void**)&w2T,  g_w2T);

    cudaFuncSetAttribute(numden_mma, cudaFuncAttributeMaxDynamicSharedMemorySize, ND_SM);
    cudaFuncSetAttribute(phi_mma<0>, cudaFuncAttributeMaxDynamicSharedMemorySize, PHI_SM);
    cudaFuncSetAttribute(phi_mma<1>, cudaFuncAttributeMaxDynamicSharedMemorySize, PHI_SM);
    cudaFuncSetAttribute(kv_mma, cudaFuncAttributeMaxDynamicSharedMemorySize, KV_SM);
    cudaFuncSetAttribute(tc_gemm<0>, cudaFuncAttributeMaxDynamicSharedMemorySize, SM_DYN);
    cudaFuncSetAttribute(tc_gemm<1>, cudaFuncAttributeMaxDynamicSharedMemorySize, SM_DYN);
    cudaFuncSetAttribute(tc_gemm<2>, cudaFuncAttributeMaxDynamicSharedMemorySize, SM_DYN);
    cudaFuncSetAttribute(tc_gemm<3>, cudaFuncAttributeMaxDynamicSharedMemorySize, SM_DYN);
    cudaFuncSetAttribute(tc_gemm<4>, cudaFuncAttributeMaxDynamicSharedMemorySize, SM_DYN);

    dim3 tb(32, 8);
    transpose_k<<<dim3(32, 32),   tb>>>(wq, wqT, 1024, 1024);
    transpose_k<<<dim3(32, 32),   tb>>>(wk, wkT, 1024, 1024);
    transpose_k<<<dim3(32, 32),   tb>>>(wv, wvT, 1024, 1024);
    transpose_k<<<dim3(32, 32),   tb>>>(wo, woT, 1024, 1024);
    transpose_k<<<dim3(128, 32),  tb>>>(w1, w1T, 1024, 4096);
    transpose_k<<<dim3(32, 128),  tb>>>(w2, w2T, 4096, 1024);
    cvt_half_kernel<<<(N_TOK * D_MOD / 8 + 255) / 256, 256>>>(x, xr, N_TOK * D_MOD / 8);

    dim3 gD(D_MOD / 128, N_TOK / 128);   // (8, 128)
    dim3 gF(FF_D / 128, N_TOK / 128);    // (32, 128)

    tc_gemm<0><<<gD, 256, SM_DYN>>>(xr, wqT, nullptr, nullptr, nullptr, q, D_MOD, D_MOD);
    tc_gemm<0><<<gD, 256, SM_DYN>>>(xr, wkT, nullptr, nullptr, nullptr, k, D_MOD, D_MOD);
    tc_gemm<4><<<gD, 256, SM_DYN>>>(xr, wvT, nullptr, nullptr, nullptr, v, D_MOD, D_MOD);

    phi_mma<1><<<2048, 512, PHI_SM>>>(q, omega, pq);
    phi_mma<0><<<2048, 512, PHI_SM>>>(k, omega, pk);

    kv_mma<<<512, 256, KV_SM>>>(pk, v, kvp);
    kv_reduce<<<64, 256>>>(kvp, kv, z);

    numden_mma<<<2048, 256, ND_SM>>>(pq, kv, z, attn);

    tc_gemm<1><<<gD, 256, SM_DYN>>>(attn, woT, nullptr, x, nullptr, y, D_MOD, D_MOD);
    ln_kernel<1><<<N_TOK, 256>>>(y, ln1g, ln1b, x1);

    tc_gemm<2><<<gF, 256, SM_DYN>>>(x1, w1T, b1, nullptr, nullptr, act, D_MOD, FF_D);
    tc_gemm<3><<<gD, 256, SM_DYN>>>(act, w2T, b2, nullptr, x1, y, FF_D, D_MOD);
    ln_kernel<0><<<N_TOK, 256>>>(y, ln2g, ln2b, out);
}

// round 13
// speedup vs baseline: 2.2780x; 1.0127x over previous
#include <cuda_runtime.h>
#include <cuda_fp16.h>
#include <math.h>

#define N_TOK 16384
#define D_MOD 1024
#define H_N   16
#define HK    64
#define M_F   256
#define FF_D  4096
#define S_LEN 4096
#define PHI_SCALE 0.35355339059327373f   // 64^-0.25
#define RSQRT_M  0.0625f                 // 1/sqrt(256)

// ---------------- scratch (device globals; allocation-free) ----------------
__device__ __half g_qk  [N_TOK * 2048];          // q cols 0-1023, k cols 1024-2047
__device__ float  g_v   [N_TOK * D_MOD];
__device__ __half g_xr  [N_TOK * D_MOD];
__device__ __half g_pq  [64 * S_LEN * M_F];
__device__ float  g_pk  [64 * S_LEN * M_F];
__device__ float  g_kv  [64 * M_F * HK];
__device__ float  g_z   [64 * M_F];
__device__ float  g_kvp [512 * 256 * 72];
__device__ __half g_attn[N_TOK * D_MOD];
__device__ float  g_y   [N_TOK * D_MOD];
__device__ __half g_x1  [N_TOK * D_MOD];
__device__ __half g_act [N_TOK * FF_D];
__device__ __half g_wqkvT[3 * D_MOD * D_MOD];    // concat wqT|wkT|wvT
__device__ __half g_woT [D_MOD * D_MOD];
__device__ __half g_w1T [D_MOD * FF_D];
__device__ __half g_w2T [D_MOD * FF_D];

__device__ __forceinline__ unsigned smem_u32(const void* p) {
    unsigned a;
    asm("{ .reg .u64 t; cvta.to.shared.u64 t, %1; cvt.u32.u64 %0, t; }" : "=r"(a) : "l"(p));
    return a;
}
__device__ __forceinline__ float rn_tf32(float f) {
    unsigned u;
    asm("cvt.rn.tf32.f32 %0, %1;" : "=r"(u) : "f"(f));
    return __uint_as_float(u);
}

__device__ __forceinline__ void mma_f16(float* d, const unsigned* a, const unsigned* b) {
    asm volatile(
        "mma.sync.aligned.m16n8k16.row.col.f32.f16.f16.f32 "
        "{%0,%1,%2,%3}, {%4,%5,%6,%7}, {%8,%9}, {%0,%1,%2,%3};"
        : "+f"(d[0]), "+f"(d[1]), "+f"(d[2]), "+f"(d[3])
        : "r"(a[0]), "r"(a[1]), "r"(a[2]), "r"(a[3]), "r"(b[0]), "r"(b[1]));
}
__device__ __forceinline__ void mma_tf32(float* d, const unsigned* a, const unsigned* b) {
    asm volatile(
        "mma.sync.aligned.m16n8k8.row.col.f32.tf32.tf32.f32 "
        "{%0,%1,%2,%3}, {%4,%5,%6,%7}, {%8,%9}, {%0,%1,%2,%3};"
        : "+f"(d[0]), "+f"(d[1]), "+f"(d[2]), "+f"(d[3])
        : "r"(a[0]), "r"(a[1]), "r"(a[2]), "r"(a[3]), "r"(b[0]), "r"(b[1]));
}

#define CP16(dst, src) \
    asm volatile("cp.async.ca.shared.global [%0], [%1], 16;" :: "r"(dst), "l"(src))
#define CP_COMMIT() asm volatile("cp.async.commit_group;" ::: "memory")
#define CP_WAIT1()  asm volatile("cp.async.wait_group 1;" ::: "memory")
#define CP_WAIT0()  asm volatile("cp.async.wait_group 0;" ::: "memory")

// ---------------- fp16 warp-MMA GEMM: C[M,N] = A[M,Kd] @ BT[N,Kd]^T ----------
// 128x128 CTA tile, 8 warps (64x32), K-chunk 64 halves, 3 slots, 1 sync/chunk.
// EPI: 0 half-out, 1 +Rf(float) float-out, 2 gelu(x+bias) half-out,
//      3 +bias+Rh(half) float-out, 5 QKV route (qk half / v float rn_tf32)
#define HSTR   72
#define TILEB  (128 * HSTR * 2)          // 18432 bytes
#define STAGEB (2 * TILEB)               // 36864
#define SM_DYN (3 * STAGEB)              // 110592

template<int EPI>
__global__ __launch_bounds__(256, 2)
void tc_gemm(const __half* __restrict__ A, const __half* __restrict__ BT,
             const float* __restrict__ bias, const float* __restrict__ Rf,
             const __half* __restrict__ Rh, void* __restrict__ Cv,
             void* __restrict__ Cv2, int Kd, int NC)
{
    extern __shared__ char sm[];
    unsigned smu = smem_u32(sm);
    int tid = threadIdx.x, wid = tid >> 5, lane = tid & 31;
    int r0 = blockIdx.y * 128, c0 = blockIdx.x * 128;
    int wm = wid & 1, wn = wid >> 1;

    const __half* Ab = A + (size_t)r0 * Kd;
    const __half* Bb = BT + (size_t)c0 * Kd;

    int crow[4], cseg[4];
    unsigned cdst[4];
    #pragma unroll
    for (int i = 0; i < 4; i++) {
        int u = tid + 256 * i;
        crow[i] = u >> 3; cseg[i] = u & 7;
        cdst[i] = smu + (unsigned)(crow[i] * (HSTR * 2) + cseg[i] * 16);
    }

    float acc[4][4][4];
    #pragma unroll
    for (int mi = 0; mi < 4; mi++)
        #pragma unroll
        for (int ni = 0; ni < 4; ni++)
            #pragma unroll
            for (int j = 0; j < 4; j++) acc[mi][ni][j] = 0.f;

    int nk = Kd >> 6;

    #pragma unroll
    for (int s = 0; s < 2; s++) {
        const __half* Ac = Ab + s * 64;
        const __half* Bc = Bb + s * 64;
        unsigned so = s * STAGEB;
        #pragma unroll
        for (int i = 0; i < 4; i++) {
            CP16(cdst[i] + so,         Ac + (size_t)crow[i] * Kd + cseg[i] * 8);
            CP16(cdst[i] + so + TILEB, Bc + (size_t)crow[i] * Kd + cseg[i] * 8);
        }
        CP_COMMIT();
    }

    int c2 = (lane & 3) * 2;
    int mrow = wm * 64 + (lane >> 2);
    int nrow = wn * 32 + (lane >> 2);

    int p = 0, pn = 2;
    for (int c = 0; c < nk; c++) {
        CP_WAIT1();
        __syncthreads();

        if (c + 2 < nk) {
            const __half* Ac = Ab + (c + 2) * 64;
            const __half* Bc = Bb + (c + 2) * 64;
            unsigned so = pn * STAGEB;
            #pragma unroll
            for (int i = 0; i < 4; i++) {
                CP16(cdst[i] + so,         Ac + (size_t)crow[i] * Kd + cseg[i] * 8);
                CP16(cdst[i] + so + TILEB, Bc + (size_t)crow[i] * Kd + cseg[i] * 8);
            }
        }
        CP_COMMIT();

        const __half* As = (const __half*)(sm + p * STAGEB);
        const __half* Bs = (const __half*)(sm + p * STAGEB + TILEB);

        #pragma unroll
        for (int ks = 0; ks < 4; ks++) {
            int kk = ks * 16 + c2;
            unsigned afr[4][4], bfr[4][2];
            #pragma unroll
            for (int mi = 0; mi < 4; mi++) {
                const __half* ap = As + (mrow + mi * 16) * HSTR + kk;
                afr[mi][0] = *(const unsigned*)(ap);
                afr[mi][1] = *(const unsigned*)(ap + 8 * HSTR);
                afr[mi][2] = *(const unsigned*)(ap + 8);
                afr[mi][3] = *(const unsigned*)(ap + 8 * HSTR + 8);
            }
            #pragma unroll
            for (int ni = 0; ni < 4; ni++) {
                const __half* bp = Bs + (nrow + ni * 8) * HSTR + kk;
                bfr[ni][0] = *(const unsigned*)(bp);
                bfr[ni][1] = *(const unsigned*)(bp + 8);
            }
            #pragma unroll
            for (int mi = 0; mi < 4; mi++)
                #pragma unroll
                for (int ni = 0; ni < 4; ni++)
                    mma_f16(acc[mi][ni], afr[mi], bfr[ni]);
        }
        p = (p == 2) ? 0 : p + 1;
        pn = (pn == 2) ? 0 : pn + 1;
    }
    CP_WAIT0();
    __syncthreads();

    float* stage = (float*)sm;
    #pragma unroll
    for (int mi = 0; mi < 4; mi++)
        #pragma unroll
        for (int ni = 0; ni < 4; ni++) {
            int row = wm * 64 + mi * 16 + (lane >> 2);
            int col = wn * 32 + ni * 8 + (lane & 3) * 2;
            *(float2*)(stage + row * 132 + col) =
                make_float2(acc[mi][ni][0], acc[mi][ni][1]);
            *(float2*)(stage + (row + 8) * 132 + col) =
                make_float2(acc[mi][ni][2], acc[mi][ni][3]);
        }
    __syncthreads();

    #pragma unroll
    for (int i = 0; i < 16; i++) {
        int u = tid + 256 * i;
        int row = u >> 5, c4 = u & 31;
        float4 v = *(const float4*)(stage + row * 132 + c4 * 4);
        float vv[4] = {v.x, v.y, v.z, v.w};

        if (EPI == 5) {
            // QKV routing: c0 in [0,2048) -> qk half (stride 2048); else v float
            if (c0 < 2048) {
                size_t base = (size_t)(r0 + row) * 2048 + c0 + c4 * 4;
                __half2 p0 = __floats2half2_rn(vv[0], vv[1]);
                __half2 p1 = __floats2half2_rn(vv[2], vv[3]);
                uint2 w;
                w.x = *(unsigned*)&p0; w.y = *(unsigned*)&p1;
                *(uint2*)((__half*)Cv2 + base) = w;
            } else {
                size_t base = (size_t)(r0 + row) * 1024 + (c0 - 2048) + c4 * 4;
                *(float4*)((float*)Cv + base) = make_float4(
                    rn_tf32(vv[0]), rn_tf32(vv[1]), rn_tf32(vv[2]), rn_tf32(vv[3]));
            }
            continue;
        }

        size_t base = (size_t)(r0 + row) * NC + c0 + c4 * 4;
        #pragma unroll
        for (int j = 0; j < 4; j++) {
            int col = c0 + c4 * 4 + j;
            if (EPI == 1) vv[j] += Rf[base + j];
            else if (EPI == 2) {
                float t = vv[j] + bias[col];
                vv[j] = 0.5f * t * (1.0f + erff(t * 0.70710678118654752f));
            } else if (EPI == 3) vv[j] += bias[col] + __half2float(Rh[base + j]);
        }
        if (EPI == 0 || EPI == 2) {
            __half2 p0 = __floats2half2_rn(vv[0], vv[1]);
            __half2 p1 = __floats2half2_rn(vv[2], vv[3]);
            uint2 w;
            w.x = *(unsigned*)&p0; w.y = *(unsigned*)&p1;
            *(uint2*)((__half*)Cv + base) = w;
        } else {
            *(float4*)((float*)Cv + base) = make_float4(vv[0], vv[1], vv[2], vv[3]);
        }
    }
}

// ---------------- batched transpose + round to half (4x 1024x1024) ----------
__global__ void transpose4_k(const float* __restrict__ i0, const float* __restrict__ i1,
                             const float* __restrict__ i2, const float* __restrict__ i3,
                             __half* __restrict__ o0, __half* __restrict__ o1,
                             __half* __restrict__ o2, __half* __restrict__ o3)
{
    const float* in = (blockIdx.z == 0) ? i0 : (blockIdx.z == 1) ? i1 :
                      (blockIdx.z == 2) ? i2 : i3;
    __half* out = (blockIdx.z == 0) ? o0 : (blockIdx.z == 1) ? o1 :
                  (blockIdx.z == 2) ? o2 : o3;
    __shared__ float t[32][33];
    int x = blockIdx.x * 32 + threadIdx.x;
    int y = blockIdx.y * 32 + threadIdx.y;
    #pragma unroll
    for (int j = 0; j < 4; j++)
        t[threadIdx.y + j * 8][threadIdx.x] = in[(size_t)(y + j * 8) * 1024 + x];
    __syncthreads();
    int ox = blockIdx.y * 32 + threadIdx.x;
    int oy = blockIdx.x * 32 + threadIdx.y;
    #pragma unroll
    for (int j = 0; j < 4; j++)
        out[(size_t)(oy + j * 8) * 1024 + ox] = __float2half_rn(t[threadIdx.x][threadIdx.y + j * 8]);
}

__global__ void transpose_k(const float* __restrict__ in, __half* __restrict__ out,
                            int R, int Cc)
{
    __shared__ float t[32][33];
    int x = blockIdx.x * 32 + threadIdx.x;
    int y = blockIdx.y * 32 + threadIdx.y;
    #pragma unroll
    for (int j = 0; j < 4; j++)
        t[threadIdx.y + j * 8][threadIdx.x] = in[(size_t)(y + j * 8) * Cc + x];
    __syncthreads();
    int ox = blockIdx.y * 32 + threadIdx.x;
    int oy = blockIdx.x * 32 + threadIdx.y;
    #pragma unroll
    for (int j = 0; j < 4; j++)
        out[(size_t)(oy + j * 8) * R + ox] = __float2half_rn(t[threadIdx.x][threadIdx.y + j * 8]);
}

__global__ void cvt_half_kernel(const float* __restrict__ in, __half* __restrict__ out, int n8)
{
    int i = blockIdx.x * blockDim.x + threadIdx.x;
    if (i < n8) {
        float4 a = ((const float4*)in)[2 * i];
        float4 b = ((const float4*)in)[2 * i + 1];
        __half2 h0 = __floats2half2_rn(a.x, a.y);
        __half2 h1 = __floats2half2_rn(a.z, a.w);
        __half2 h2 = __floats2half2_rn(b.x, b.y);
        __half2 h3 = __floats2half2_rn(b.z, b.w);
        uint4 w;
        w.x = *(unsigned*)&h0; w.y = *(unsigned*)&h1;
        w.z = *(unsigned*)&h2; w.w = *(unsigned*)&h3;
        ((uint4*)out)[i] = w;
    }
}

// ---------------- tensorized FAVOR+ (fp16 MMA), fused q+k launch -------------
// blockIdx.x < 2048: pq from q-half of qk (half out); else pk from k-half (float out)
#define PHSTR 72
#define PHI_A_OFF 0
#define PHI_B_OFF (128 * PHSTR * 2)                 // 18432
#define PHI_STAGE_W 260
#define PHI_SQ_OFF  (128 * PHI_STAGE_W * 4)         // 133120
#define PHI_SM      (PHI_SQ_OFF + 128 * 4)          // 133632

__global__ __launch_bounds__(512, 1)
void phi_mma(const __half* __restrict__ qk, const float* __restrict__ omega,
             __half* __restrict__ pqd, float* __restrict__ pkd)
{
    extern __shared__ char sm[];
    __half* As = (__half*)(sm + PHI_A_OFF);
    __half* Bs = (__half*)(sm + PHI_B_OFF);
    float* stage = (float*)sm;
    float* sqv   = (float*)(sm + PHI_SQ_OFF);

    int tid = threadIdx.x, wid = tid >> 5, lane = tid & 31;
    int outh = (blockIdx.x < 2048) ? 1 : 0;
    int rbase = (blockIdx.x & 2047) * 128;
    const __half* src = qk + (outh ? 0 : 1024);

    {
        int row = tid >> 2, qtr = tid & 3;
        int r = rbase + row, n = r >> 4, h = r & 15;
        const __half2* s2 = (const __half2*)(src + (size_t)n * 2048 + h * 64 + qtr * 16);
        unsigned outw[8];
        float ps = 0.f;
        #pragma unroll
        for (int j = 0; j < 8; j++) {
            float2 f = __half22float2(s2[j]);
            __half2 hh = __floats2half2_rn(f.x * PHI_SCALE, f.y * PHI_SCALE);
            float2 fr = __half22float2(hh);
            ps += fr.x * fr.x + fr.y * fr.y;
            outw[j] = *(unsigned*)&hh;
        }
        __half* dstA = As + row * PHSTR + qtr * 16;
        *(uint4*)(dstA)     = make_uint4(outw[0], outw[1], outw[2], outw[3]);
        *(uint4*)(dstA + 8) = make_uint4(outw[4], outw[5], outw[6], outw[7]);
        ps += __shfl_xor_sync(0xFFFFFFFFu, ps, 1);
        ps += __shfl_xor_sync(0xFFFFFFFFu, ps, 2);
        if (qtr == 0) sqv[row] = 0.5f * ps;
    }
    {
        int m = tid >> 1, hf = tid & 1;
        const float* orow = omega + m * 64 + hf * 32;
        #pragma unroll
        for (int j = 0; j < 4; j++) {
            float4 a = ((const float4*)orow)[2 * j];
            float4 b = ((const float4*)orow)[2 * j + 1];
            __half2 h0 = __floats2half2_rn(a.x, a.y);
            __half2 h1 = __floats2half2_rn(a.z, a.w);
            __half2 h2 = __floats2half2_rn(b.x, b.y);
            __half2 h3 = __floats2half2_rn(b.z, b.w);
            uint4 w;
            w.x = *(unsigned*)&h0; w.y = *(unsigned*)&h1;
            w.z = *(unsigned*)&h2; w.w = *(unsigned*)&h3;
            *(uint4*)(Bs + m * PHSTR + hf * 32 + j * 8) = w;
        }
    }
    __syncthreads();

    float acc[2][8][4];
    #pragma unroll
    for (int mi = 0; mi < 2; mi++)
        #pragma unroll
        for (int ni = 0; ni < 8; ni++)
            #pragma unroll
            for (int j = 0; j < 4; j++) acc[mi][ni][j] = 0.f;

    int c2 = (lane & 3) * 2;
    int mrow = (wid & 3) * 32 + (lane >> 2);
    int nrow = (wid >> 2) * 64 + (lane >> 2);

    #pragma unroll
    for (int ks = 0; ks < 4; ks++) {
        int kk = ks * 16 + c2;
        unsigned afr[2][4], bfr[8][2];
        #pragma unroll
        for (int mi = 0; mi < 2; mi++) {
            const __half* ap = As + (mrow + mi * 16) * PHSTR + kk;
            afr[mi][0] = *(const unsigned*)(ap);
            afr[mi][1] = *(const unsigned*)(ap + 8 * PHSTR);
            afr[mi][2] = *(const unsigned*)(ap + 8);
            afr[mi][3] = *(const unsigned*)(ap + 8 * PHSTR + 8);
        }
        #pragma unroll
        for (int ni = 0; ni < 8; ni++) {
            const __half* bp = Bs + (nrow + ni * 8) * PHSTR + kk;
            bfr[ni][0] = *(const unsigned*)(bp);
            bfr[ni][1] = *(const unsigned*)(bp + 8);
        }
        #pragma unroll
        for (int mi = 0; mi < 2; mi++)
            #pragma unroll
            for (int ni = 0; ni < 8; ni++)
                mma_f16(acc[mi][ni], afr[mi], bfr[ni]);
    }
    __syncthreads();

    #pragma unroll
    for (int mi = 0; mi < 2; mi++)
        #pragma unroll
        for (int ni = 0; ni < 8; ni++) {
            int row = (wid & 3) * 32 + mi * 16 + (lane >> 2);
            int col = (wid >> 2) * 64 + ni * 8 + (lane & 3) * 2;
            *(float2*)(stage + row * PHI_STAGE_W + col) =
                make_float2(acc[mi][ni][0], acc[mi][ni][1]);
            *(float2*)(stage + (row + 8) * PHI_STAGE_W + col) =
                make_float2(acc[mi][ni][2], acc[mi][ni][3]);
        }
    __syncthreads();

    {
        int row = tid >> 2, seg = (tid & 3) * 64;
        const float* srow = stage + row * PHI_STAGE_W + seg;
        float mx = -1e30f;
        #pragma unroll
        for (int j = 0; j < 16; j++) {
            float4 v = ((const float4*)srow)[j];
            mx = fmaxf(mx, fmaxf(fmaxf(v.x, v.y), fmaxf(v.z, v.w)));
        }
        mx = fmaxf(mx, __shfl_xor_sync(0xFFFFFFFFu, mx, 1));
        mx = fmaxf(mx, __shfl_xor_sync(0xFFFFFFFFu, mx, 2));
        float sb = sqv[row] + mx;

        int r = rbase + row, n = r >> 4, h = r & 15;
        int b = n >> 12, s = n & 4095;
        size_t rowoff = (((size_t)(b * H_N + h)) * S_LEN + s) * M_F + seg;
        #pragma unroll
        for (int j = 0; j < 16; j++) {
            float4 v = ((const float4*)srow)[j];
            float e0 = __expf(v.x - sb) * RSQRT_M + 1e-6f;
            float e1 = __expf(v.y - sb) * RSQRT_M + 1e-6f;
            float e2 = __expf(v.z - sb) * RSQRT_M + 1e-6f;
            float e3 = __expf(v.w - sb) * RSQRT_M + 1e-6f;
            if (outh) {
                __half2 p0 = __floats2half2_rn(e0, e1);
                __half2 p1 = __floats2half2_rn(e2, e3);
                uint2 w;
                w.x = *(unsigned*)&p0; w.y = *(unsigned*)&p1;
                *(uint2*)(pqd + rowoff + j * 4) = w;
            } else {
                *(float4*)(pkd + rowoff + j * 4) = make_float4(
                    rn_tf32(e0), rn_tf32(e1), rn_tf32(e2), rn_tf32(e3));
            }
        }
    }
}

// ---------------- tensorized kv (tf32) ------------------
#define KV_PSTR  264
#define KV_VSTR  104
#define KV_PKB   (32 * KV_PSTR * 4)
#define KV_VB    (32 * KV_VSTR * 4)
#define KV_STAGE (KV_PKB + KV_VB)
#define KV_SM    (2 * KV_STAGE)

__global__ __launch_bounds__(256, 2)
void kv_mma(const float* __restrict__ pk, const float* __restrict__ v,
            float* __restrict__ partial)
{
    extern __shared__ char sm[];
    unsigned smu = smem_u32(sm);
    int tid = threadIdx.x, wid = tid >> 5, lane = tid & 31;
    int bh = blockIdx.x >> 3, chunk = blockIdx.x & 7;
    int b = bh >> 4, h = bh & 15;
    int s0 = chunk * 512;

    const float* pkb = pk + ((size_t)bh * S_LEN + s0) * M_F;
    const float* vb  = v + ((size_t)(b * S_LEN + s0)) * D_MOD + h * 64;

    for (int i = tid; i < 32 * 16 * 2; i += 256) {
        int st = i >> 9, r = (i & 511) >> 4, cc = (i & 15) + 64;
        ((float*)(sm + st * KV_STAGE + KV_PKB))[r * KV_VSTR + cc] = (cc == 64) ? 1.f : 0.f;
    }
    __syncthreads();

    auto issue_copy = [&](int cc, int st) {
        unsigned base = smu + st * KV_STAGE;
        #pragma unroll
        for (int i2 = 0; i2 < 8; i2++) {
            int j = tid + 256 * i2;
            int row = j >> 6, seg = j & 63;
            CP16(base + (unsigned)(row * KV_PSTR + seg * 4) * 4,
                 pkb + (size_t)(cc * 32 + row) * M_F + seg * 4);
        }
        #pragma unroll
        for (int i2 = 0; i2 < 2; i2++) {
            int j = tid + 256 * i2;
            int row = j >> 4, seg = j & 15;
            CP16(base + KV_PKB + (unsigned)(row * KV_VSTR + seg * 4) * 4,
                 vb + (size_t)(cc * 32 + row) * D_MOD + seg * 4);
        }
    };

    float acc[4][5][4];
    #pragma unroll
    for (int mi = 0; mi < 4; mi++)
        #pragma unroll
        for (int ni = 0; ni < 5; ni++)
            #pragma unroll
            for (int j = 0; j < 4; j++) acc[mi][ni][j] = 0.f;

    issue_copy(0, 0); CP_COMMIT();
    issue_copy(1, 1); CP_COMMIT();

    int mbase = (wid & 3) * 64 + (lane >> 2);
    int nbase = (wid >> 2) * 40 + (lane >> 2);

    for (int c = 0; c < 16; c++) {
        int p = c & 1;
        CP_WAIT1();
        __syncthreads();

        const unsigned* As = (const unsigned*)(sm + p * KV_STAGE);
        const unsigned* Vs = (const unsigned*)(sm + p * KV_STAGE + KV_PKB);

        #pragma unroll
        for (int ks = 0; ks < 4; ks++) {
            int kk = ks * 8 + (lane & 3);
            unsigned afr[4][4], bfr[5][2];
            #pragma unroll
            for (int mi = 0; mi < 4; mi++) {
                int mr = mbase + mi * 16;
                afr[mi][0] = As[kk * KV_PSTR + mr];
                afr[mi][1] = As[kk * KV_PSTR + mr + 8];
                afr[mi][2] = As[(kk + 4) * KV_PSTR + mr];
                afr[mi][3] = As[(kk + 4) * KV_PSTR + mr + 8];
            }
            #pragma unroll
            for (int ni = 0; ni < 5; ni++) {
                int nr = nbase + ni * 8;
                bfr[ni][0] = Vs[kk * KV_VSTR + nr];
                bfr[ni][1] = Vs[(kk + 4) * KV_VSTR + nr];
            }
            #pragma unroll
            for (int mi = 0; mi < 4; mi++)
                #pragma unroll
                for (int ni = 0; ni < 5; ni++)
                    mma_tf32(acc[mi][ni], afr[mi], bfr[ni]);
        }
        __syncthreads();

        if (c + 2 < 16) issue_copy(c + 2, p);
        CP_COMMIT();
    }

    float* pb = partial + (size_t)blockIdx.x * (256 * 72);
    #pragma unroll
    for (int mi = 0; mi < 4; mi++)
        #pragma unroll
        for (int ni = 0; ni < 5; ni++) {
            int row = (wid & 3) * 64 + mi * 16 + (lane >> 2);
            int col = (wid >> 2) * 40 + ni * 8 + (lane & 3) * 2;
            if (col < 64) {
                *(float2*)(pb + row * 72 + col) =
                    make_float2(acc[mi][ni][0], acc[mi][ni][1]);
                *(float2*)(pb + (row + 8) * 72 + col) =
                    make_float2(acc[mi][ni][2], acc[mi][ni][3]);
            } else if (col == 64) {
                pb[row * 72 + 64] = acc[mi][ni][0];
                pb[(row + 8) * 72 + 64] = acc[mi][ni][2];
            }
        }
}

__global__ void kv_reduce(const float* __restrict__ partial,
                          float* __restrict__ kv, float* __restrict__ z)
{
    int bh = blockIdx.x;
    for (int j = threadIdx.x; j < 256 * 72; j += 256) {
        float s = 0.f;
        #pragma unroll
        for (int c = 0; c < 8; c++)
            s += partial[((size_t)(bh * 8 + c)) * (256 * 72) + j];
        int m = j / 72, k2 = j - m * 72;
        if (k2 < 64) kv[(size_t)bh * (M_F * HK) + m * 64 + k2] = s;
        else if (k2 == 64) z[bh * M_F + m] = s;
    }
}

// ---------------- fp16 num/den: attn = (pq @ kv) / (pq @ z) ------------------
#define ND_BSTR  264
#define ND_B_OFF 0
#define ND_Z_OFF (64 * ND_BSTR * 2)              // 33792
#define ND_A_OFF (ND_Z_OFF + 1024)               // 34816
#define ND_SM    (ND_A_OFF + 2 * TILEB)          // 71680

__global__ __launch_bounds__(256, 2)
void numden_mma(const __half* __restrict__ pq, const float* __restrict__ kvg,
                const float* __restrict__ zg, __half* __restrict__ attn)
{
    extern __shared__ char sm[];
    unsigned smu = smem_u32(sm);
    __half* Bsf  = (__half*)(sm + ND_B_OFF);
    float* z_s   = (float*)(sm + ND_Z_OFF);
    float* den_s = (float*)(sm + ND_B_OFF);
    float* stage = (float*)(sm + ND_A_OFF);

    int bh = blockIdx.x >> 5;
    int chunk = blockIdx.x & 31;
    int b = bh >> 4, h = bh & 15;
    int tid = threadIdx.x, wid = tid >> 5, lane = tid & 31;
    int s0 = chunk * 128;

    const __half* pqb = pq + ((size_t)bh * S_LEN + s0) * M_F;

    int arow[4], aseg[4];
    unsigned adst[4];
    #pragma unroll
    for (int i = 0; i < 4; i++) {
        int u = tid + 256 * i;
        arow[i] = u >> 3; aseg[i] = u & 7;
        adst[i] = smu + ND_A_OFF + (unsigned)(arow[i] * (HSTR * 2) + aseg[i] * 16);
    }

    #pragma unroll
    for (int s = 0; s < 2; s++) {
        const __half* Ac = pqb + s * 64;
        unsigned so = s * TILEB;
        #pragma unroll
        for (int i = 0; i < 4; i++)
            CP16(adst[i] + so, Ac + (size_t)arow[i] * M_F + aseg[i] * 8);
        CP_COMMIT();
    }

    {
        const float* kvb = kvg + (size_t)bh * (M_F * HK);
        for (int i = tid; i < M_F * HK; i += 256) {
            int m = i >> 6, k = i & 63;
            Bsf[k * ND_BSTR + m] = __float2half_rn(kvb[i]);
        }
        z_s[tid] = zg[bh * M_F + tid];
    }

    float acc[2][4][4];
    #pragma unroll
    for (int mi = 0; mi < 2; mi++)
        #pragma unroll
        for (int ni = 0; ni < 4; ni++)
            #pragma unroll
            for (int j = 0; j < 4; j++) acc[mi][ni][j] = 0.f;

    int c2 = (lane & 3) * 2;
    int mrow = (wid & 3) * 32 + (lane >> 2);
    int nrow = (wid >> 2) * 32 + (lane >> 2);

    for (int c = 0; c < 4; c++) {
        int p = c & 1;
        CP_WAIT1();
        __syncthreads();

        const __half* As = (const __half*)(sm + ND_A_OFF + p * TILEB);
        #pragma unroll
        for (int ks = 0; ks < 4; ks++) {
            int kk = ks * 16 + c2;
            unsigned afr[2][4], bfr[4][2];
            #pragma unroll
            for (int mi = 0; mi < 2; mi++) {
                const __half* ap = As + (mrow + mi * 16) * HSTR + kk;
                afr[mi][0] = *(const unsigned*)(ap);
                afr[mi][1] = *(const unsigned*)(ap + 8 * HSTR);
                afr[mi][2] = *(const unsigned*)(ap + 8);
                afr[mi][3] = *(const unsigned*)(ap + 8 * HSTR + 8);
            }
            #pragma unroll
            for (int ni = 0; ni < 4; ni++) {
                const __half* bp = Bsf + (nrow + ni * 8) * ND_BSTR + c * 64 + kk;
                bfr[ni][0] = *(const unsigned*)(bp);
                bfr[ni][1] = *(const unsigned*)(bp + 8);
            }
            #pragma unroll
            for (int mi = 0; mi < 2; mi++)
                #pragma unroll
                for (int ni = 0; ni < 4; ni++)
                    mma_f16(acc[mi][ni], afr[mi], bfr[ni]);
        }
        __syncthreads();

        if (c + 2 < 4) {
            const __half* Ac = pqb + (c + 2) * 64;
            unsigned so = p * TILEB;
            #pragma unroll
            for (int i = 0; i < 4; i++)
                CP16(adst[i] + so, Ac + (size_t)arow[i] * M_F + aseg[i] * 8);
        }
        CP_COMMIT();
    }
    CP_WAIT0();
    __syncthreads();

    #pragma unroll
    for (int mi = 0; mi < 2; mi++)
        #pragma unroll
        for (int ni = 0; ni < 4; ni++) {
            int row = (wid & 3) * 32 + mi * 16 + (lane >> 2);
            int col = (wid >> 2) * 32 + ni * 8 + (lane & 3) * 2;
            *(float2*)(stage + row * 68 + col) =
                make_float2(acc[mi][ni][0], acc[mi][ni][1]);
            *(float2*)(stage + (row + 8) * 68 + col) =
                make_float2(acc[mi][ni][2], acc[mi][ni][3]);
        }

    {
        int row = tid >> 1, half = tid & 1;
        const __half2* pr = (const __half2*)(pqb + (size_t)row * M_F + half * 128);
        const float* zr = z_s + half * 128;
        float dp = 0.f;
        #pragma unroll 8
        for (int j = 0; j < 64; j++) {
            float2 f = __half22float2(pr[j]);
            dp += f.x * zr[2 * j] + f.y * zr[2 * j + 1];
        }
        dp += __shfl_xor_sync(0xFFFFFFFFu, dp, 1);
        if (half == 0) den_s[row] = dp;
    }
    __syncthreads();

    #pragma unroll
    for (int i = 0; i < 8; i++) {
        int u = tid + 256 * i;
        int row = u >> 4, c4 = u & 15;
        float4 v = *(const float4*)(stage + row * 68 + c4 * 4);
        float rd = 1.0f / den_s[row];
        __half2 p0 = __floats2half2_rn(v.x * rd, v.y * rd);
        __half2 p1 = __floats2half2_rn(v.z * rd, v.w * rd);
        uint2 w;
        w.x = *(unsigned*)&p0; w.y = *(unsigned*)&p1;
        *(uint2*)(attn + ((size_t)(b * S_LEN + s0 + row)) * D_MOD + h * 64 + c4 * 4) = w;
    }
}

// ---------------- LayerNorm (OUTHALF: write half) ----------------
template<int OUTHALF>
__global__ void ln_kernel(const float* __restrict__ X, const float* __restrict__ g,
                          const float* __restrict__ bv, void* __restrict__ outv)
{
    int row = blockIdx.x, tid = threadIdx.x;
    float4 v = ((const float4*)(X + (size_t)row * D_MOD))[tid];
    float s = v.x + v.y + v.z + v.w;
    __shared__ float ws[8];
    #pragma unroll
    for (int o = 16; o; o >>= 1) s += __shfl_xor_sync(0xFFFFFFFFu, s, o);
    if ((tid & 31) == 0) ws[tid >> 5] = s;
    __syncthreads();
    float tot = 0.f;
    #pragma unroll
    for (int w = 0; w < 8; w++) tot += ws[w];
    float mu = tot * (1.f / 1024.f);
    float dx = v.x - mu, dy = v.y - mu, dz = v.z - mu, dw = v.w - mu;
    float sqvv = dx*dx + dy*dy + dz*dz + dw*dw;
    __syncthreads();
    #pragma unroll
    for (int o = 16; o; o >>= 1) sqvv += __shfl_xor_sync(0xFFFFFFFFu, sqvv, o);
    if ((tid & 31) == 0) ws[tid >> 5] = sqvv;
    __syncthreads();
    float tot2 = 0.f;
    #pragma unroll
    for (int w = 0; w < 8; w++) tot2 += ws[w];
    float rs = rsqrtf(tot2 * (1.f / 1024.f) + 1e-6f);
    float4 gg = ((const float4*)g)[tid];
    float4 bb = ((const float4*)bv)[tid];
    float o0 = dx*rs*gg.x + bb.x, o1 = dy*rs*gg.y + bb.y;
    float o2 = dz*rs*gg.z + bb.z, o3 = dw*rs*gg.w + bb.w;
    if (OUTHALF) {
        __half2 p0 = __floats2half2_rn(o0, o1);
        __half2 p1 = __floats2half2_rn(o2, o3);
        uint2 w;
        w.x = *(unsigned*)&p0; w.y = *(unsigned*)&p1;
        *(uint2*)((__half*)outv + (size_t)row * D_MOD + tid * 4) = w;
    } else {
        ((float4*)((float*)outv + (size_t)row * D_MOD))[tid] =
            make_float4(o0, o1, o2, o3);
    }
}

// ---------------- orchestration ----------------
extern "C" void kernel_launch(void* const* d_in, const int* in_sizes, int n_in,
                              void* d_out, int out_size)
{
    const float* x     = (const float*)d_in[0];
    const float* wq    = (const float*)d_in[1];
    const float* wk    = (const float*)d_in[2];
    const float* wv    = (const float*)d_in[3];
    const float* wo    = (const float*)d_in[4];
    const float* omega = (const float*)d_in[5];
    const float* ln1g  = (const float*)d_in[6];
    const float* ln1b  = (const float*)d_in[7];
    const float* w1    = (const float*)d_in[8];
    const float* b1    = (const float*)d_in[9];
    const float* w2    = (const float*)d_in[10];
    const float* b2    = (const float*)d_in[11];
    const float* ln2g  = (const float*)d_in[12];
    const float* ln2b  = (const float*)d_in[13];
    float* out = (float*)d_out;

    __half *qk, *xr, *pq, *attn, *x1, *act;
    float *v, *pk, *kv, *z, *kvp, *y;
    __half *wqkvT, *woT, *w1T, *w2T;
    cudaGetSymbolAddress((void**)&qk,   g_qk);
    cudaGetSymbolAddress((void**)&v,    g_v);
    cudaGetSymbolAddress((void**)&xr,   g_xr);
    cudaGetSymbolAddress((void**)&pq,   g_pq);
    cudaGetSymbolAddress((void**)&pk,   g_pk);
    cudaGetSymbolAddress((void**)&kv,   g_kv);
    cudaGetSymbolAddress((void**)&z,    g_z);
    cudaGetSymbolAddress((void**)&kvp,  g_kvp);
    cudaGetSymbolAddress((void**)&attn, g_attn);
    cudaGetSymbolAddress((void**)&y,    g_y);
    cudaGetSymbolAddress((void**)&x1,   g_x1);
    cudaGetSymbolAddress((void**)&act,  g_act);
    cudaGetSymbolAddress((void**)&wqkvT, g_wqkvT);
    cudaGetSymbolAddress((void**)&woT,  g_woT);
    cudaGetSymbolAddress((void**)&w1T,  g_w1T);
    cudaGetSymbolAddress((void**)&w2T,  g_w2T);

    cudaFuncSetAttribute(numden_mma, cudaFuncAttributeMaxDynamicSharedMemorySize, ND_SM);
    cudaFuncSetAttribute(phi_mma, cudaFuncAttributeMaxDynamicSharedMemorySize, PHI_SM);
    cudaFuncSetAttribute(kv_mma, cudaFuncAttributeMaxDynamicSharedMemorySize, KV_SM);
    cudaFuncSetAttribute(tc_gemm<0>, cudaFuncAttributeMaxDynamicSharedMemorySize, SM_DYN);
    cudaFuncSetAttribute(tc_gemm<1>, cudaFuncAttributeMaxDynamicSharedMemorySize, SM_DYN);
    cudaFuncSetAttribute(tc_gemm<2>, cudaFuncAttributeMaxDynamicSharedMemorySize, SM_DYN);
    cudaFuncSetAttribute(tc_gemm<3>, cudaFuncAttributeMaxDynamicSharedMemorySize, SM_DYN);
    cudaFuncSetAttribute(tc_gemm<5>, cudaFuncAttributeMaxDynamicSharedMemorySize, SM_DYN);

    dim3 tb(32, 8);
    transpose4_k<<<dim3(32, 32, 4), tb>>>(wq, wk, wv, wo,
        wqkvT, wqkvT + 1024 * 1024, wqkvT + 2 * 1024 * 1024, woT);
    transpose_k<<<dim3(128, 32),  tb>>>(w1, w1T, 1024, 4096);
    transpose_k<<<dim3(32, 128),  tb>>>(w2, w2T, 4096, 1024);
    cvt_half_kernel<<<(N_TOK * D_MOD / 8 + 255) / 256, 256>>>(x, xr, N_TOK * D_MOD / 8);

    dim3 gQKV(3072 / 128, N_TOK / 128);  // (24, 128)
    dim3 gD(D_MOD / 128, N_TOK / 128);   // (8, 128)
    dim3 gF(FF_D / 128, N_TOK / 128);    // (32, 128)

    tc_gemm<5><<<gQKV, 256, SM_DYN>>>(xr, wqkvT, nullptr, nullptr, nullptr,
                                      v, qk, D_MOD, 3072);

    phi_mma<<<4096, 512, PHI_SM>>>(qk, omega, pq, pk);

    kv_mma<<<512, 256, KV_SM>>>(pk, v, kvp);
    kv_reduce<<<64, 256>>>(kvp, kv, z);

    numden_mma<<<2048, 256, ND_SM>>>(pq, kv, z, attn);

    tc_gemm<1><<<gD, 256, SM_DYN>>>(attn, woT, nullptr, x, nullptr, y, nullptr,
                                    D_MOD, D_MOD);
    ln_kernel<1><<<N_TOK, 256>>>(y, ln1g, ln1b, x1);

    tc_gemm<2><<<gF, 256, SM_DYN>>>(x1, w1T, b1, nullptr, nullptr, act, nullptr,
                                    D_MOD, FF_D);
    tc_gemm<3><<<gD, 256, SM_DYN>>>(act, w2T, b2, nullptr, x1, y, nullptr,
                                    FF_D, D_MOD);
    ln_kernel<0><<<N_TOK, 256>>>(y, ln2g, ln2b, out);
}

// round 14
// speedup vs baseline: 2.4302x; 1.0668x over previous
#include <cuda_runtime.h>
#include <cuda_fp16.h>
#include <math.h>

#define N_TOK 16384
#define D_MOD 1024
#define H_N   16
#define HK    64
#define M_F   256
#define FF_D  4096
#define S_LEN 4096
#define PHI_SCALE 0.35355339059327373f   // 64^-0.25
#define RSQRT_M  0.0625f                 // 1/sqrt(256)

// ---------------- scratch (device globals; allocation-free) ----------------
__device__ __half g_qk  [N_TOK * 2048];          // q cols 0-1023, k cols 1024-2047
__device__ __half g_v   [N_TOK * D_MOD];
__device__ __half g_xr  [N_TOK * D_MOD];
__device__ __half g_pq  [64 * S_LEN * M_F];
__device__ __half g_pk  [64 * S_LEN * M_F];
__device__ float  g_kv  [64 * M_F * HK];
__device__ float  g_z   [64 * M_F];
__device__ float  g_kvp [512 * 256 * 72];
__device__ __half g_attn[N_TOK * D_MOD];
__device__ float  g_y   [N_TOK * D_MOD];
__device__ __half g_x1  [N_TOK * D_MOD];
__device__ __half g_act [N_TOK * FF_D];
__device__ __half g_wqkvT[3 * D_MOD * D_MOD];    // concat wqT|wkT|wvT
__device__ __half g_woT [D_MOD * D_MOD];
__device__ __half g_w1T [D_MOD * FF_D];
__device__ __half g_w2T [D_MOD * FF_D];

__device__ __forceinline__ unsigned smem_u32(const void* p) {
    unsigned a;
    asm("{ .reg .u64 t; cvta.to.shared.u64 t, %1; cvt.u32.u64 %0, t; }" : "=r"(a) : "l"(p));
    return a;
}
__device__ __forceinline__ float rn_tf32(float f) {
    unsigned u;
    asm("cvt.rn.tf32.f32 %0, %1;" : "=r"(u) : "f"(f));
    return __uint_as_float(u);
}
// pack two halves (rows k, k+1 of a k-major tile, same column) into one mma reg
__device__ __forceinline__ unsigned pk2(const __half* p, int str) {
    unsigned lo = *(const unsigned short*)p;
    unsigned hi = *(const unsigned short*)(p + str);
    return lo | (hi << 16);
}

__device__ __forceinline__ void mma_f16(float* d, const unsigned* a, const unsigned* b) {
    asm volatile(
        "mma.sync.aligned.m16n8k16.row.col.f32.f16.f16.f32 "
        "{%0,%1,%2,%3}, {%4,%5,%6,%7}, {%8,%9}, {%0,%1,%2,%3};"
        : "+f"(d[0]), "+f"(d[1]), "+f"(d[2]), "+f"(d[3])
        : "r"(a[0]), "r"(a[1]), "r"(a[2]), "r"(a[3]), "r"(b[0]), "r"(b[1]));
}

#define CP16(dst, src) \
    asm volatile("cp.async.ca.shared.global [%0], [%1], 16;" :: "r"(dst), "l"(src))
#define CP_COMMIT() asm volatile("cp.async.commit_group;" ::: "memory")
#define CP_WAIT1()  asm volatile("cp.async.wait_group 1;" ::: "memory")
#define CP_WAIT0()  asm volatile("cp.async.wait_group 0;" ::: "memory")

// ---------------- fp16 warp-MMA GEMM ----------------
// EPI: 0 half-out, 1 +Rf(float) float-out, 2 gelu(x+bias) half-out,
//      3 +bias+Rh(half) float-out, 5 QKV route (qk half / v half)
#define HSTR   72
#define TILEB  (128 * HSTR * 2)          // 18432 bytes
#define STAGEB (2 * TILEB)               // 36864
#define SM_DYN (3 * STAGEB)              // 110592

template<int EPI>
__global__ __launch_bounds__(256, 2)
void tc_gemm(const __half* __restrict__ A, const __half* __restrict__ BT,
             const float* __restrict__ bias, const float* __restrict__ Rf,
             const __half* __restrict__ Rh, void* __restrict__ Cv,
             void* __restrict__ Cv2, int Kd, int NC)
{
    extern __shared__ char sm[];
    unsigned smu = smem_u32(sm);
    int tid = threadIdx.x, wid = tid >> 5, lane = tid & 31;
    int r0 = blockIdx.y * 128, c0 = blockIdx.x * 128;
    int wm = wid & 1, wn = wid >> 1;

    const __half* Ab = A + (size_t)r0 * Kd;
    const __half* Bb = BT + (size_t)c0 * Kd;

    int crow[4], cseg[4];
    unsigned cdst[4];
    #pragma unroll
    for (int i = 0; i < 4; i++) {
        int u = tid + 256 * i;
        crow[i] = u >> 3; cseg[i] = u & 7;
        cdst[i] = smu + (unsigned)(crow[i] * (HSTR * 2) + cseg[i] * 16);
    }

    float acc[4][4][4];
    #pragma unroll
    for (int mi = 0; mi < 4; mi++)
        #pragma unroll
        for (int ni = 0; ni < 4; ni++)
            #pragma unroll
            for (int j = 0; j < 4; j++) acc[mi][ni][j] = 0.f;

    int nk = Kd >> 6;

    #pragma unroll
    for (int s = 0; s < 2; s++) {
        const __half* Ac = Ab + s * 64;
        const __half* Bc = Bb + s * 64;
        unsigned so = s * STAGEB;
        #pragma unroll
        for (int i = 0; i < 4; i++) {
            CP16(cdst[i] + so,         Ac + (size_t)crow[i] * Kd + cseg[i] * 8);
            CP16(cdst[i] + so + TILEB, Bc + (size_t)crow[i] * Kd + cseg[i] * 8);
        }
        CP_COMMIT();
    }

    int c2 = (lane & 3) * 2;
    int mrow = wm * 64 + (lane >> 2);
    int nrow = wn * 32 + (lane >> 2);

    int p = 0, pn = 2;
    for (int c = 0; c < nk; c++) {
        CP_WAIT1();
        __syncthreads();

        if (c + 2 < nk) {
            const __half* Ac = Ab + (c + 2) * 64;
            const __half* Bc = Bb + (c + 2) * 64;
            unsigned so = pn * STAGEB;
            #pragma unroll
            for (int i = 0; i < 4; i++) {
                CP16(cdst[i] + so,         Ac + (size_t)crow[i] * Kd + cseg[i] * 8);
                CP16(cdst[i] + so + TILEB, Bc + (size_t)crow[i] * Kd + cseg[i] * 8);
            }
        }
        CP_COMMIT();

        const __half* As = (const __half*)(sm + p * STAGEB);
        const __half* Bs = (const __half*)(sm + p * STAGEB + TILEB);

        #pragma unroll
        for (int ks = 0; ks < 4; ks++) {
            int kk = ks * 16 + c2;
            unsigned afr[4][4], bfr[4][2];
            #pragma unroll
            for (int mi = 0; mi < 4; mi++) {
                const __half* ap = As + (mrow + mi * 16) * HSTR + kk;
                afr[mi][0] = *(const unsigned*)(ap);
                afr[mi][1] = *(const unsigned*)(ap + 8 * HSTR);
                afr[mi][2] = *(const unsigned*)(ap + 8);
                afr[mi][3] = *(const unsigned*)(ap + 8 * HSTR + 8);
            }
            #pragma unroll
            for (int ni = 0; ni < 4; ni++) {
                const __half* bp = Bs + (nrow + ni * 8) * HSTR + kk;
                bfr[ni][0] = *(const unsigned*)(bp);
                bfr[ni][1] = *(const unsigned*)(bp + 8);
            }
            #pragma unroll
            for (int mi = 0; mi < 4; mi++)
                #pragma unroll
                for (int ni = 0; ni < 4; ni++)
                    mma_f16(acc[mi][ni], afr[mi], bfr[ni]);
        }
        p = (p == 2) ? 0 : p + 1;
        pn = (pn == 2) ? 0 : pn + 1;
    }
    CP_WAIT0();
    __syncthreads();

    float* stage = (float*)sm;
    #pragma unroll
    for (int mi = 0; mi < 4; mi++)
        #pragma unroll
        for (int ni = 0; ni < 4; ni++) {
            int row = wm * 64 + mi * 16 + (lane >> 2);
            int col = wn * 32 + ni * 8 + (lane & 3) * 2;
            *(float2*)(stage + row * 132 + col) =
                make_float2(acc[mi][ni][0], acc[mi][ni][1]);
            *(float2*)(stage + (row + 8) * 132 + col) =
                make_float2(acc[mi][ni][2], acc[mi][ni][3]);
        }
    __syncthreads();

    #pragma unroll
    for (int i = 0; i < 16; i++) {
        int u = tid + 256 * i;
        int row = u >> 5, c4 = u & 31;
        float4 v = *(const float4*)(stage + row * 132 + c4 * 4);
        float vv[4] = {v.x, v.y, v.z, v.w};

        if (EPI == 5) {
            // QKV routing: c0 in [0,2048) -> qk half; else v half
            if (c0 < 2048) {
                size_t base = (size_t)(r0 + row) * 2048 + c0 + c4 * 4;
                __half2 p0 = __floats2half2_rn(vv[0], vv[1]);
                __half2 p1 = __floats2half2_rn(vv[2], vv[3]);
                uint2 w;
                w.x = *(unsigned*)&p0; w.y = *(unsigned*)&p1;
                *(uint2*)((__half*)Cv2 + base) = w;
            } else {
                size_t base = (size_t)(r0 + row) * 1024 + (c0 - 2048) + c4 * 4;
                __half2 p0 = __floats2half2_rn(vv[0], vv[1]);
                __half2 p1 = __floats2half2_rn(vv[2], vv[3]);
                uint2 w;
                w.x = *(unsigned*)&p0; w.y = *(unsigned*)&p1;
                *(uint2*)((__half*)Cv + base) = w;
            }
            continue;
        }

        size_t base = (size_t)(r0 + row) * NC + c0 + c4 * 4;
        #pragma unroll
        for (int j = 0; j < 4; j++) {
            int col = c0 + c4 * 4 + j;
            if (EPI == 1) vv[j] += Rf[base + j];
            else if (EPI == 2) {
                float t = vv[j] + bias[col];
                vv[j] = 0.5f * t * (1.0f + erff(t * 0.70710678118654752f));
            } else if (EPI == 3) vv[j] += bias[col] + __half2float(Rh[base + j]);
        }
        if (EPI == 0 || EPI == 2) {
            __half2 p0 = __floats2half2_rn(vv[0], vv[1]);
            __half2 p1 = __floats2half2_rn(vv[2], vv[3]);
            uint2 w;
            w.x = *(unsigned*)&p0; w.y = *(unsigned*)&p1;
            *(uint2*)((__half*)Cv + base) = w;
        } else {
            *(float4*)((float*)Cv + base) = make_float4(vv[0], vv[1], vv[2], vv[3]);
        }
    }
}

// ---------------- batched transpose + round to half (4x 1024x1024) ----------
__global__ void transpose4_k(const float* __restrict__ i0, const float* __restrict__ i1,
                             const float* __restrict__ i2, const float* __restrict__ i3,
                             __half* __restrict__ o0, __half* __restrict__ o1,
                             __half* __restrict__ o2, __half* __restrict__ o3)
{
    const float* in = (blockIdx.z == 0) ? i0 : (blockIdx.z == 1) ? i1 :
                      (blockIdx.z == 2) ? i2 : i3;
    __half* out = (blockIdx.z == 0) ? o0 : (blockIdx.z == 1) ? o1 :
                  (blockIdx.z == 2) ? o2 : o3;
    __shared__ float t[32][33];
    int x = blockIdx.x * 32 + threadIdx.x;
    int y = blockIdx.y * 32 + threadIdx.y;
    #pragma unroll
    for (int j = 0; j < 4; j++)
        t[threadIdx.y + j * 8][threadIdx.x] = in[(size_t)(y + j * 8) * 1024 + x];
    __syncthreads();
    int ox = blockIdx.y * 32 + threadIdx.x;
    int oy = blockIdx.x * 32 + threadIdx.y;
    #pragma unroll
    for (int j = 0; j < 4; j++)
        out[(size_t)(oy + j * 8) * 1024 + ox] = __float2half_rn(t[threadIdx.x][threadIdx.y + j * 8]);
}

__global__ void transpose_k(const float* __restrict__ in, __half* __restrict__ out,
                            int R, int Cc)
{
    __shared__ float t[32][33];
    int x = blockIdx.x * 32 + threadIdx.x;
    int y = blockIdx.y * 32 + threadIdx.y;
    #pragma unroll
    for (int j = 0; j < 4; j++)
        t[threadIdx.y + j * 8][threadIdx.x] = in[(size_t)(y + j * 8) * Cc + x];
    __syncthreads();
    int ox = blockIdx.y * 32 + threadIdx.x;
    int oy = blockIdx.x * 32 + threadIdx.y;
    #pragma unroll
    for (int j = 0; j < 4; j++)
        out[(size_t)(oy + j * 8) * R + ox] = __float2half_rn(t[threadIdx.x][threadIdx.y + j * 8]);
}

__global__ void cvt_half_kernel(const float* __restrict__ in, __half* __restrict__ out, int n8)
{
    int i = blockIdx.x * blockDim.x + threadIdx.x;
    if (i < n8) {
        float4 a = ((const float4*)in)[2 * i];
        float4 b = ((const float4*)in)[2 * i + 1];
        __half2 h0 = __floats2half2_rn(a.x, a.y);
        __half2 h1 = __floats2half2_rn(a.z, a.w);
        __half2 h2 = __floats2half2_rn(b.x, b.y);
        __half2 h3 = __floats2half2_rn(b.z, b.w);
        uint4 w;
        w.x = *(unsigned*)&h0; w.y = *(unsigned*)&h1;
        w.z = *(unsigned*)&h2; w.w = *(unsigned*)&h3;
        ((uint4*)out)[i] = w;
    }
}

// ---------------- tensorized FAVOR+ (fp16 MMA), fused q+k launch -------------
#define PHSTR 72
#define PHI_A_OFF 0
#define PHI_B_OFF (128 * PHSTR * 2)                 // 18432
#define PHI_STAGE_W 260
#define PHI_SQ_OFF  (128 * PHI_STAGE_W * 4)         // 133120
#define PHI_SM      (PHI_SQ_OFF + 128 * 4)          // 133632

__global__ __launch_bounds__(512, 1)
void phi_mma(const __half* __restrict__ qk, const float* __restrict__ omega,
             __half* __restrict__ pqd, __half* __restrict__ pkd)
{
    extern __shared__ char sm[];
    __half* As = (__half*)(sm + PHI_A_OFF);
    __half* Bs = (__half*)(sm + PHI_B_OFF);
    float* stage = (float*)sm;
    float* sqv   = (float*)(sm + PHI_SQ_OFF);

    int tid = threadIdx.x, wid = tid >> 5, lane = tid & 31;
    int outh = (blockIdx.x < 2048) ? 1 : 0;
    int rbase = (blockIdx.x & 2047) * 128;
    const __half* src = qk + (outh ? 0 : 1024);
    __half* dst = outh ? pqd : pkd;

    {
        int row = tid >> 2, qtr = tid & 3;
        int r = rbase + row, n = r >> 4, h = r & 15;
        const __half2* s2 = (const __half2*)(src + (size_t)n * 2048 + h * 64 + qtr * 16);
        unsigned outw[8];
        float ps = 0.f;
        #pragma unroll
        for (int j = 0; j < 8; j++) {
            float2 f = __half22float2(s2[j]);
            __half2 hh = __floats2half2_rn(f.x * PHI_SCALE, f.y * PHI_SCALE);
            float2 fr = __half22float2(hh);
            ps += fr.x * fr.x + fr.y * fr.y;
            outw[j] = *(unsigned*)&hh;
        }
        __half* dstA = As + row * PHSTR + qtr * 16;
        *(uint4*)(dstA)     = make_uint4(outw[0], outw[1], outw[2], outw[3]);
        *(uint4*)(dstA + 8) = make_uint4(outw[4], outw[5], outw[6], outw[7]);
        ps += __shfl_xor_sync(0xFFFFFFFFu, ps, 1);
        ps += __shfl_xor_sync(0xFFFFFFFFu, ps, 2);
        if (qtr == 0) sqv[row] = 0.5f * ps;
    }
    {
        int m = tid >> 1, hf = tid & 1;
        const float* orow = omega + m * 64 + hf * 32;
        #pragma unroll
        for (int j = 0; j < 4; j++) {
            float4 a = ((const float4*)orow)[2 * j];
            float4 b = ((const float4*)orow)[2 * j + 1];
            __half2 h0 = __floats2half2_rn(a.x, a.y);
            __half2 h1 = __floats2half2_rn(a.z, a.w);
            __half2 h2 = __floats2half2_rn(b.x, b.y);
            __half2 h3 = __floats2half2_rn(b.z, b.w);
            uint4 w;
            w.x = *(unsigned*)&h0; w.y = *(unsigned*)&h1;
            w.z = *(unsigned*)&h2; w.w = *(unsigned*)&h3;
            *(uint4*)(Bs + m * PHSTR + hf * 32 + j * 8) = w;
        }
    }
    __syncthreads();

    float acc[2][8][4];
    #pragma unroll
    for (int mi = 0; mi < 2; mi++)
        #pragma unroll
        for (int ni = 0; ni < 8; ni++)
            #pragma unroll
            for (int j = 0; j < 4; j++) acc[mi][ni][j] = 0.f;

    int c2 = (lane & 3) * 2;
    int mrow = (wid & 3) * 32 + (lane >> 2);
    int nrow = (wid >> 2) * 64 + (lane >> 2);

    #pragma unroll
    for (int ks = 0; ks < 4; ks++) {
        int kk = ks * 16 + c2;
        unsigned afr[2][4], bfr[8][2];
        #pragma unroll
        for (int mi = 0; mi < 2; mi++) {
            const __half* ap = As + (mrow + mi * 16) * PHSTR + kk;
            afr[mi][0] = *(const unsigned*)(ap);
            afr[mi][1] = *(const unsigned*)(ap + 8 * PHSTR);
            afr[mi][2] = *(const unsigned*)(ap + 8);
            afr[mi][3] = *(const unsigned*)(ap + 8 * PHSTR + 8);
        }
        #pragma unroll
        for (int ni = 0; ni < 8; ni++) {
            const __half* bp = Bs + (nrow + ni * 8) * PHSTR + kk;
            bfr[ni][0] = *(const unsigned*)(bp);
            bfr[ni][1] = *(const unsigned*)(bp + 8);
        }
        #pragma unroll
        for (int mi = 0; mi < 2; mi++)
            #pragma unroll
            for (int ni = 0; ni < 8; ni++)
                mma_f16(acc[mi][ni], afr[mi], bfr[ni]);
    }
    __syncthreads();

    #pragma unroll
    for (int mi = 0; mi < 2; mi++)
        #pragma unroll
        for (int ni = 0; ni < 8; ni++) {
            int row = (wid & 3) * 32 + mi * 16 + (lane >> 2);
            int col = (wid >> 2) * 64 + ni * 8 + (lane & 3) * 2;
            *(float2*)(stage + row * PHI_STAGE_W + col) =
                make_float2(acc[mi][ni][0], acc[mi][ni][1]);
            *(float2*)(stage + (row + 8) * PHI_STAGE_W + col) =
                make_float2(acc[mi][ni][2], acc[mi][ni][3]);
        }
    __syncthreads();

    {
        int row = tid >> 2, seg = (tid & 3) * 64;
        const float* srow = stage + row * PHI_STAGE_W + seg;
        float mx = -1e30f;
        #pragma unroll
        for (int j = 0; j < 16; j++) {
            float4 v = ((const float4*)srow)[j];
            mx = fmaxf(mx, fmaxf(fmaxf(v.x, v.y), fmaxf(v.z, v.w)));
        }
        mx = fmaxf(mx, __shfl_xor_sync(0xFFFFFFFFu, mx, 1));
        mx = fmaxf(mx, __shfl_xor_sync(0xFFFFFFFFu, mx, 2));
        float sb = sqv[row] + mx;

        int r = rbase + row, n = r >> 4, h = r & 15;
        int b = n >> 12, s = n & 4095;
        size_t rowoff = (((size_t)(b * H_N + h)) * S_LEN + s) * M_F + seg;
        #pragma unroll
        for (int j = 0; j < 16; j++) {
            float4 v = ((const float4*)srow)[j];
            __half2 p0 = __floats2half2_rn(__expf(v.x - sb) * RSQRT_M + 1e-6f,
                                           __expf(v.y - sb) * RSQRT_M + 1e-6f);
            __half2 p1 = __floats2half2_rn(__expf(v.z - sb) * RSQRT_M + 1e-6f,
                                           __expf(v.w - sb) * RSQRT_M + 1e-6f);
            uint2 w;
            w.x = *(unsigned*)&p0; w.y = *(unsigned*)&p1;
            *(uint2*)(dst + rowoff + j * 4) = w;
        }
    }
}

// ---------------- fp16 kv: partial[blk][m][72] = pk^T @ [v | 1] --------------
// grid = 64 bh x 8 s-chunks. CTA M=256, N=80 (col64 = ones -> z), K=s chunk 512.
// s-major half tiles; transposed fragments via 2x u16 pack.
#define KV_PSTR  264
#define KV_VSTR  88
#define KV_PKB   (32 * KV_PSTR * 2)      // 16896
#define KV_VB    (32 * KV_VSTR * 2)      // 5632
#define KV_STAGE (KV_PKB + KV_VB)        // 22528
#define KV_SM    (2 * KV_STAGE)          // 45056

__global__ __launch_bounds__(256, 2)
void kv_mma(const __half* __restrict__ pk, const __half* __restrict__ v,
            float* __restrict__ partial)
{
    extern __shared__ char sm[];
    unsigned smu = smem_u32(sm);
    int tid = threadIdx.x, wid = tid >> 5, lane = tid & 31;
    int bh = blockIdx.x >> 3, chunk = blockIdx.x & 7;
    int b = bh >> 4, h = bh & 15;
    int s0 = chunk * 512;

    const __half* pkb = pk + ((size_t)bh * S_LEN + s0) * M_F;
    const __half* vb  = v + ((size_t)(b * S_LEN + s0)) * D_MOD + h * 64;

    // init cols 64..79 of both v-tile stages (col 64 = ones -> z)
    for (int i = tid; i < 32 * 16 * 2; i += 256) {
        int st = i >> 9, r = (i & 511) >> 4, cc = (i & 15) + 64;
        ((__half*)(sm + st * KV_STAGE + KV_PKB))[r * KV_VSTR + cc] =
            (cc == 64) ? __float2half(1.f) : __float2half(0.f);
    }
    __syncthreads();

    auto issue_copy = [&](int cc, int st) {
        unsigned base = smu + st * KV_STAGE;
        // pk tile: 32 rows x 256 halves = 32 segs/row
        #pragma unroll
        for (int i2 = 0; i2 < 4; i2++) {
            int j = tid + 256 * i2;
            int row = j >> 5, seg = j & 31;
            CP16(base + (unsigned)(row * (KV_PSTR * 2) + seg * 16),
                 pkb + (size_t)(cc * 32 + row) * M_F + seg * 8);
        }
        // v tile: 32 rows x 64 halves = 8 segs/row, 1 iter
        {
            int row = tid >> 3, seg = tid & 7;
            CP16(base + KV_PKB + (unsigned)(row * (KV_VSTR * 2) + seg * 16),
                 vb + (size_t)(cc * 32 + row) * D_MOD + seg * 8);
        }
    };

    float acc[4][5][4];
    #pragma unroll
    for (int mi = 0; mi < 4; mi++)
        #pragma unroll
        for (int ni = 0; ni < 5; ni++)
            #pragma unroll
            for (int j = 0; j < 4; j++) acc[mi][ni][j] = 0.f;

    issue_copy(0, 0); CP_COMMIT();
    issue_copy(1, 1); CP_COMMIT();

    int mbase = (wid & 3) * 64 + (lane >> 2);
    int nbase = (wid >> 2) * 40 + (lane >> 2);

    for (int c = 0; c < 16; c++) {
        int p = c & 1;
        CP_WAIT1();
        __syncthreads();

        const __half* As = (const __half*)(sm + p * KV_STAGE);
        const __half* Vs = (const __half*)(sm + p * KV_STAGE + KV_PKB);

        #pragma unroll
        for (int ks = 0; ks < 2; ks++) {
            int k0 = ks * 16 + (lane & 3) * 2;
            unsigned afr[4][4], bfr[5][2];
            #pragma unroll
            for (int mi = 0; mi < 4; mi++) {
                int m = mbase + mi * 16;
                afr[mi][0] = pk2(As + k0 * KV_PSTR + m, KV_PSTR);
                afr[mi][1] = pk2(As + k0 * KV_PSTR + m + 8, KV_PSTR);
                afr[mi][2] = pk2(As + (k0 + 8) * KV_PSTR + m, KV_PSTR);
                afr[mi][3] = pk2(As + (k0 + 8) * KV_PSTR + m + 8, KV_PSTR);
            }
            #pragma unroll
            for (int ni = 0; ni < 5; ni++) {
                int n = nbase + ni * 8;
                bfr[ni][0] = pk2(Vs + k0 * KV_VSTR + n, KV_VSTR);
                bfr[ni][1] = pk2(Vs + (k0 + 8) * KV_VSTR + n, KV_VSTR);
            }
            #pragma unroll
            for (int mi = 0; mi < 4; mi++)
                #pragma unroll
                for (int ni = 0; ni < 5; ni++)
                    mma_f16(acc[mi][ni], afr[mi], bfr[ni]);
        }
        __syncthreads();

        if (c + 2 < 16) issue_copy(c + 2, p);
        CP_COMMIT();
    }

    float* pb = partial + (size_t)blockIdx.x * (256 * 72);
    #pragma unroll
    for (int mi = 0; mi < 4; mi++)
        #pragma unroll
        for (int ni = 0; ni < 5; ni++) {
            int row = (wid & 3) * 64 + mi * 16 + (lane >> 2);
            int col = (wid >> 2) * 40 + ni * 8 + (lane & 3) * 2;
            if (col < 64) {
                *(float2*)(pb + row * 72 + col) =
                    make_float2(acc[mi][ni][0], acc[mi][ni][1]);
                *(float2*)(pb + (row + 8) * 72 + col) =
                    make_float2(acc[mi][ni][2], acc[mi][ni][3]);
            } else if (col == 64) {
                pb[row * 72 + 64] = acc[mi][ni][0];
                pb[(row + 8) * 72 + 64] = acc[mi][ni][2];
            }
        }
}

__global__ void kv_reduce(const float* __restrict__ partial,
                          float* __restrict__ kv, float* __restrict__ z)
{
    int bh = blockIdx.x;
    for (int j = threadIdx.x; j < 256 * 72; j += 256) {
        float s = 0.f;
        #pragma unroll
        for (int c = 0; c < 8; c++)
            s += partial[((size_t)(bh * 8 + c)) * (256 * 72) + j];
        int m = j / 72, k2 = j - m * 72;
        if (k2 < 64) kv[(size_t)bh * (M_F * HK) + m * 64 + k2] = s;
        else if (k2 == 64) z[bh * M_F + m] = s;
    }
}

// ---------------- fp16 num/den: attn = (pq @ kv) / (pq @ z) ------------------
#define ND_BSTR  264
#define ND_B_OFF 0
#define ND_Z_OFF (64 * ND_BSTR * 2)              // 33792
#define ND_A_OFF (ND_Z_OFF + 1024)               // 34816
#define ND_SM    (ND_A_OFF + 2 * TILEB)          // 71680

__global__ __launch_bounds__(256, 2)
void numden_mma(const __half* __restrict__ pq, const float* __restrict__ kvg,
                const float* __restrict__ zg, __half* __restrict__ attn)
{
    extern __shared__ char sm[];
    unsigned smu = smem_u32(sm);
    __half* Bsf  = (__half*)(sm + ND_B_OFF);
    float* z_s   = (float*)(sm + ND_Z_OFF);
    float* den_s = (float*)(sm + ND_B_OFF);      // aliases Bs after MMA
    float* stage = (float*)(sm + ND_A_OFF);      // aliases As after MMA

    int bh = blockIdx.x >> 5;
    int chunk = blockIdx.x & 31;
    int b = bh >> 4, h = bh & 15;
    int tid = threadIdx.x, wid = tid >> 5, lane = tid & 31;
    int s0 = chunk * 128;

    const __half* pqb = pq + ((size_t)bh * S_LEN + s0) * M_F;

    int arow[4], aseg[4];
    unsigned adst[4];
    #pragma unroll
    for (int i = 0; i < 4; i++) {
        int u = tid + 256 * i;
        arow[i] = u >> 3; aseg[i] = u & 7;
        adst[i] = smu + ND_A_OFF + (unsigned)(arow[i] * (HSTR * 2) + aseg[i] * 16);
    }

    #pragma unroll
    for (int s = 0; s < 2; s++) {
        const __half* Ac = pqb + s * 64;
        unsigned so = s * TILEB;
        #pragma unroll
        for (int i = 0; i < 4; i++)
            CP16(adst[i] + so, Ac + (size_t)arow[i] * M_F + aseg[i] * 8);
        CP_COMMIT();
    }

    {
        const float* kvb = kvg + (size_t)bh * (M_F * HK);
        for (int i = tid; i < M_F * HK; i += 256) {
            int m = i >> 6, k = i & 63;
            Bsf[k * ND_BSTR + m] = __float2half_rn(kvb[i]);
        }
        z_s[tid] = zg[bh * M_F + tid];
    }

    float acc[2][4][4];
    #pragma unroll
    for (int mi = 0; mi < 2; mi++)
        #pragma unroll
        for (int ni = 0; ni < 4; ni++)
            #pragma unroll
            for (int j = 0; j < 4; j++) acc[mi][ni][j] = 0.f;

    int c2 = (lane & 3) * 2;
    int mrow = (wid & 3) * 32 + (lane >> 2);
    int nrow = (wid >> 2) * 32 + (lane >> 2);
    int drow = tid >> 1, dhf = tid & 1;
    float dp = 0.f;

    for (int c = 0; c < 4; c++) {
        int p = c & 1;
        CP_WAIT1();
        __syncthreads();

        const __half* As = (const __half*)(sm + ND_A_OFF + p * TILEB);
        #pragma unroll
        for (int ks = 0; ks < 4; ks++) {
            int kk = ks * 16 + c2;
            unsigned afr[2][4], bfr[4][2];
            #pragma unroll
            for (int mi = 0; mi < 2; mi++) {
                const __half* ap = As + (mrow + mi * 16) * HSTR + kk;
                afr[mi][0] = *(const unsigned*)(ap);
                afr[mi][1] = *(const unsigned*)(ap + 8 * HSTR);
                afr[mi][2] = *(const unsigned*)(ap + 8);
                afr[mi][3] = *(const unsigned*)(ap + 8 * HSTR + 8);
            }
            #pragma unroll
            for (int ni = 0; ni < 4; ni++) {
                const __half* bp = Bsf + (nrow + ni * 8) * ND_BSTR + c * 64 + kk;
                bfr[ni][0] = *(const unsigned*)(bp);
                bfr[ni][1] = *(const unsigned*)(bp + 8);
            }
            #pragma unroll
            for (int mi = 0; mi < 2; mi++)
                #pragma unroll
                for (int ni = 0; ni < 4; ni++)
                    mma_f16(acc[mi][ni], afr[mi], bfr[ni]);
        }

        // den partial from SMEM pq tile (32 halves/thread) before tile is reused
        {
            const __half* ar = As + drow * HSTR + dhf * 32;
            const float* zr = z_s + c * 64 + dhf * 32;
            #pragma unroll
            for (int j = 0; j < 16; j++) {
                float2 f = __half22float2(*(const __half2*)(ar + 2 * j));
                dp += f.x * zr[2 * j] + f.y * zr[2 * j + 1];
            }
        }
        __syncthreads();

        if (c + 2 < 4) {
            const __half* Ac = pqb + (c + 2) * 64;
            unsigned so = p * TILEB;
            #pragma unroll
            for (int i = 0; i < 4; i++)
                CP16(adst[i] + so, Ac + (size_t)arow[i] * M_F + aseg[i] * 8);
        }
        CP_COMMIT();
    }
    CP_WAIT0();
    __syncthreads();

    #pragma unroll
    for (int mi = 0; mi < 2; mi++)
        #pragma unroll
        for (int ni = 0; ni < 4; ni++) {
            int row = (wid & 3) * 32 + mi * 16 + (lane >> 2);
            int col = (wid >> 2) * 32 + ni * 8 + (lane & 3) * 2;
            *(float2*)(stage + row * 68 + col) =
                make_float2(acc[mi][ni][0], acc[mi][ni][1]);
            *(float2*)(stage + (row + 8) * 68 + col) =
                make_float2(acc[mi][ni][2], acc[mi][ni][3]);
        }

    dp += __shfl_xor_sync(0xFFFFFFFFu, dp, 1);
    if (dhf == 0) den_s[drow] = dp;
    __syncthreads();

    #pragma unroll
    for (int i = 0; i < 8; i++) {
        int u = tid + 256 * i;
        int row = u >> 4, c4 = u & 15;
        float4 v = *(const float4*)(stage + row * 68 + c4 * 4);
        float rd = 1.0f / den_s[row];
        __half2 p0 = __floats2half2_rn(v.x * rd, v.y * rd);
        __half2 p1 = __floats2half2_rn(v.z * rd, v.w * rd);
        uint2 w;
        w.x = *(unsigned*)&p0; w.y = *(unsigned*)&p1;
        *(uint2*)(attn + ((size_t)(b * S_LEN + s0 + row)) * D_MOD + h * 64 + c4 * 4) = w;
    }
}

// ---------------- LayerNorm (OUTHALF: write half) ----------------
template<int OUTHALF>
__global__ void ln_kernel(const float* __restrict__ X, const float* __restrict__ g,
                          const float* __restrict__ bv, void* __restrict__ outv)
{
    int row = blockIdx.x, tid = threadIdx.x;
    float4 v = ((const float4*)(X + (size_t)row * D_MOD))[tid];
    float s = v.x + v.y + v.z + v.w;
    __shared__ float ws[8];
    #pragma unroll
    for (int o = 16; o; o >>= 1) s += __shfl_xor_sync(0xFFFFFFFFu, s, o);
    if ((tid & 31) == 0) ws[tid >> 5] = s;
    __syncthreads();
    float tot = 0.f;
    #pragma unroll
    for (int w = 0; w < 8; w++) tot += ws[w];
    float mu = tot * (1.f / 1024.f);
    float dx = v.x - mu, dy = v.y - mu, dz = v.z - mu, dw = v.w - mu;
    float sqvv = dx*dx + dy*dy + dz*dz + dw*dw;
    __syncthreads();
    #pragma unroll
    for (int o = 16; o; o >>= 1) sqvv += __shfl_xor_sync(0xFFFFFFFFu, sqvv, o);
    if ((tid & 31) == 0) ws[tid >> 5] = sqvv;
    __syncthreads();
    float tot2 = 0.f;
    #pragma unroll
    for (int w = 0; w < 8; w++) tot2 += ws[w];
    float rs = rsqrtf(tot2 * (1.f / 1024.f) + 1e-6f);
    float4 gg = ((const float4*)g)[tid];
    float4 bb = ((const float4*)bv)[tid];
    float o0 = dx*rs*gg.x + bb.x, o1 = dy*rs*gg.y + bb.y;
    float o2 = dz*rs*gg.z + bb.z, o3 = dw*rs*gg.w + bb.w;
    if (OUTHALF) {
        __half2 p0 = __floats2half2_rn(o0, o1);
        __half2 p1 = __floats2half2_rn(o2, o3);
        uint2 w;
        w.x = *(unsigned*)&p0; w.y = *(unsigned*)&p1;
        *(uint2*)((__half*)outv + (size_t)row * D_MOD + tid * 4) = w;
    } else {
        ((float4*)((float*)outv + (size_t)row * D_MOD))[tid] =
            make_float4(o0, o1, o2, o3);
    }
}

// ---------------- orchestration ----------------
extern "C" void kernel_launch(void* const* d_in, const int* in_sizes, int n_in,
                              void* d_out, int out_size)
{
    const float* x     = (const float*)d_in[0];
    const float* wq    = (const float*)d_in[1];
    const float* wk    = (const float*)d_in[2];
    const float* wv    = (const float*)d_in[3];
    const float* wo    = (const float*)d_in[4];
    const float* omega = (const float*)d_in[5];
    const float* ln1g  = (const float*)d_in[6];
    const float* ln1b  = (const float*)d_in[7];
    const float* w1    = (const float*)d_in[8];
    const float* b1    = (const float*)d_in[9];
    const float* w2    = (const float*)d_in[10];
    const float* b2    = (const float*)d_in[11];
    const float* ln2g  = (const float*)d_in[12];
    const float* ln2b  = (const float*)d_in[13];
    float* out = (float*)d_out;

    __half *qk, *v, *xr, *pq, *pk, *attn, *x1, *act;
    float *kv, *z, *kvp, *y;
    __half *wqkvT, *woT, *w1T, *w2T;
    cudaGetSymbolAddress((void**)&qk,   g_qk);
    cudaGetSymbolAddress((void**)&v,    g_v);
    cudaGetSymbolAddress((void**)&xr,   g_xr);
    cudaGetSymbolAddress((void**)&pq,   g_pq);
    cudaGetSymbolAddress((void**)&pk,   g_pk);
    cudaGetSymbolAddress((void**)&kv,   g_kv);
    cudaGetSymbolAddress((void**)&z,    g_z);
    cudaGetSymbolAddress((void**)&kvp,  g_kvp);
    cudaGetSymbolAddress((void**)&attn, g_attn);
    cudaGetSymbolAddress((void**)&y,    g_y);
    cudaGetSymbolAddress((void**)&x1,   g_x1);
    cudaGetSymbolAddress((void**)&act,  g_act);
    cudaGetSymbolAddress((void**)&wqkvT, g_wqkvT);
    cudaGetSymbolAddress((void**)&woT,  g_woT);
    cudaGetSymbolAddress((void**)&w1T,  g_w1T);
    cudaGetSymbolAddress((void**)&w2T,  g_w2T);

    cudaFuncSetAttribute(numden_mma, cudaFuncAttributeMaxDynamicSharedMemorySize, ND_SM);
    cudaFuncSetAttribute(phi_mma, cudaFuncAttributeMaxDynamicSharedMemorySize, PHI_SM);
    cudaFuncSetAttribute(kv_mma, cudaFuncAttributeMaxDynamicSharedMemorySize, KV_SM);
    cudaFuncSetAttribute(tc_gemm<0>, cudaFuncAttributeMaxDynamicSharedMemorySize, SM_DYN);
    cudaFuncSetAttribute(tc_gemm<1>, cudaFuncAttributeMaxDynamicSharedMemorySize, SM_DYN);
    cudaFuncSetAttribute(tc_gemm<2>, cudaFuncAttributeMaxDynamicSharedMemorySize, SM_DYN);
    cudaFuncSetAttribute(tc_gemm<3>, cudaFuncAttributeMaxDynamicSharedMemorySize, SM_DYN);
    cudaFuncSetAttribute(tc_gemm<5>, cudaFuncAttributeMaxDynamicSharedMemorySize, SM_DYN);

    dim3 tb(32, 8);
    transpose4_k<<<dim3(32, 32, 4), tb>>>(wq, wk, wv, wo,
        wqkvT, wqkvT + 1024 * 1024, wqkvT + 2 * 1024 * 1024, woT);
    transpose_k<<<dim3(128, 32),  tb>>>(w1, w1T, 1024, 4096);
    transpose_k<<<dim3(32, 128),  tb>>>(w2, w2T, 4096, 1024);
    cvt_half_kernel<<<(N_TOK * D_MOD / 8 + 255) / 256, 256>>>(x, xr, N_TOK * D_MOD / 8);

    dim3 gQKV(3072 / 128, N_TOK / 128);  // (24, 128)
    dim3 gD(D_MOD / 128, N_TOK / 128);   // (8, 128)
    dim3 gF(FF_D / 128, N_TOK / 128);    // (32, 128)

    tc_gemm<5><<<gQKV, 256, SM_DYN>>>(xr, wqkvT, nullptr, nullptr, nullptr,
                                      v, qk, D_MOD, 3072);

    phi_mma<<<4096, 512, PHI_SM>>>(qk, omega, pq, pk);

    kv_mma<<<512, 256, KV_SM>>>(pk, v, kvp);
    kv_reduce<<<64, 256>>>(kvp, kv, z);

    numden_mma<<<2048, 256, ND_SM>>>(pq, kv, z, attn);

    tc_gemm<1><<<gD, 256, SM_DYN>>>(attn, woT, nullptr, x, nullptr, y, nullptr,
                                    D_MOD, D_MOD);
    ln_kernel<1><<<N_TOK, 256>>>(y, ln1g, ln1b, x1);

    tc_gemm<2><<<gF, 256, SM_DYN>>>(x1, w1T, b1, nullptr, nullptr, act, nullptr,
                                    D_MOD, FF_D);
    tc_gemm<3><<<gD, 256, SM_DYN>>>(act, w2T, b2, nullptr, x1, y, nullptr,
                                    FF_D, D_MOD);
    ln_kernel<0><<<N_TOK, 256>>>(y, ln2g, ln2b, out);
}

// round 15
// speedup vs baseline: 2.5199x; 1.0369x over previous
#include <cuda_runtime.h>
#include <cuda_fp16.h>
#include <math.h>

#define N_TOK 16384
#define D_MOD 1024
#define H_N   16
#define HK    64
#define M_F   256
#define FF_D  4096
#define S_LEN 4096
#define PHI_SCALE 0.35355339059327373f   // 64^-0.25
#define RSQRT_M  0.0625f                 // 1/sqrt(256)

// ---------------- scratch (device globals; allocation-free) ----------------
__device__ __half g_qk  [N_TOK * 2048];          // q cols 0-1023, k cols 1024-2047
__device__ __half g_v   [N_TOK * D_MOD];
__device__ __half g_xr  [N_TOK * D_MOD];
__device__ __half g_pq  [64 * S_LEN * M_F];
__device__ __half g_pk  [64 * S_LEN * M_F];
__device__ float  g_kv  [64 * M_F * HK];
__device__ float  g_z   [64 * M_F];
__device__ float  g_kvp [512 * 256 * 72];
__device__ __half g_attn[N_TOK * D_MOD];
__device__ float  g_y   [N_TOK * D_MOD];
__device__ __half g_x1  [N_TOK * D_MOD];
__device__ __half g_act [N_TOK * FF_D];
__device__ __half g_wqkvT[3 * D_MOD * D_MOD];    // concat wqT|wkT|wvT
__device__ __half g_woT [D_MOD * D_MOD];
__device__ __half g_w1T [D_MOD * FF_D];
__device__ __half g_w2T [D_MOD * FF_D];

__device__ __forceinline__ unsigned smem_u32(const void* p) {
    unsigned a;
    asm("{ .reg .u64 t; cvta.to.shared.u64 t, %1; cvt.u32.u64 %0, t; }" : "=r"(a) : "l"(p));
    return a;
}
// pack two halves (rows k, k+1 of a k-major tile, same column) into one mma reg
__device__ __forceinline__ unsigned pk2(const __half* p, int str) {
    unsigned lo = *(const unsigned short*)p;
    unsigned hi = *(const unsigned short*)(p + str);
    return lo | (hi << 16);
}
__device__ __forceinline__ void ldsm_x4(unsigned& r0, unsigned& r1,
                                        unsigned& r2, unsigned& r3, unsigned addr) {
    asm volatile("ldmatrix.sync.aligned.m8n8.x4.shared.b16 {%0,%1,%2,%3}, [%4];"
        : "=r"(r0), "=r"(r1), "=r"(r2), "=r"(r3) : "r"(addr));
}

__device__ __forceinline__ void mma_f16(float* d, const unsigned* a, const unsigned* b) {
    asm volatile(
        "mma.sync.aligned.m16n8k16.row.col.f32.f16.f16.f32 "
        "{%0,%1,%2,%3}, {%4,%5,%6,%7}, {%8,%9}, {%0,%1,%2,%3};"
        : "+f"(d[0]), "+f"(d[1]), "+f"(d[2]), "+f"(d[3])
        : "r"(a[0]), "r"(a[1]), "r"(a[2]), "r"(a[3]), "r"(b[0]), "r"(b[1]));
}

#define CP16(dst, src) \
    asm volatile("cp.async.ca.shared.global [%0], [%1], 16;" :: "r"(dst), "l"(src))
#define CP_COMMIT() asm volatile("cp.async.commit_group;" ::: "memory")
#define CP_WAIT1()  asm volatile("cp.async.wait_group 1;" ::: "memory")
#define CP_WAIT0()  asm volatile("cp.async.wait_group 0;" ::: "memory")

// ---------------- fp16 warp-MMA GEMM (ldmatrix fragments) ----------------
// EPI: 0 half-out, 1 +Rf(float) float-out, 2 gelu(x+bias) half-out,
//      3 +bias+Rh(half) float-out, 5 QKV route (qk half / v half)
#define HSTR   72
#define ROWB   144                       // HSTR*2 bytes per row
#define TILEB  (128 * ROWB)              // 18432 bytes
#define STAGEB (2 * TILEB)               // 36864
#define SM_DYN (3 * STAGEB)              // 110592

template<int EPI>
__global__ __launch_bounds__(256, 2)
void tc_gemm(const __half* __restrict__ A, const __half* __restrict__ BT,
             const float* __restrict__ bias, const float* __restrict__ Rf,
             const __half* __restrict__ Rh, void* __restrict__ Cv,
             void* __restrict__ Cv2, int Kd, int NC)
{
    extern __shared__ char sm[];
    unsigned smu = smem_u32(sm);
    int tid = threadIdx.x, wid = tid >> 5, lane = tid & 31;
    int r0 = blockIdx.y * 128, c0 = blockIdx.x * 128;
    int wm = wid & 1, wn = wid >> 1;

    const __half* Ab = A + (size_t)r0 * Kd;
    const __half* Bb = BT + (size_t)c0 * Kd;

    int crow[4], cseg[4];
    unsigned cdst[4];
    #pragma unroll
    for (int i = 0; i < 4; i++) {
        int u = tid + 256 * i;
        crow[i] = u >> 3; cseg[i] = u & 7;
        cdst[i] = smu + (unsigned)(crow[i] * ROWB + cseg[i] * 16);
    }

    // ldmatrix per-lane address offsets (bytes, within a tile)
    // A (x4, 16x16): lanes 0-15 -> rows 0-15 @k0 ; 16-31 -> rows 0-15 @k8(+16B)
    unsigned aoff = (unsigned)((lane & 15) * ROWB + (lane >> 4) * 16);
    // B (x4, two 8x16 tiles): lanes 0-7 n0-7@k0, 8-15 n0-7@k8, 16-23 n8-15@k0, 24-31 n8-15@k8
    unsigned boff = (unsigned)((((lane >> 4) * 8) + (lane & 7)) * ROWB +
                               ((lane >> 3) & 1) * 16);

    float acc[4][4][4];
    #pragma unroll
    for (int mi = 0; mi < 4; mi++)
        #pragma unroll
        for (int ni = 0; ni < 4; ni++)
            #pragma unroll
            for (int j = 0; j < 4; j++) acc[mi][ni][j] = 0.f;

    int nk = Kd >> 6;

    #pragma unroll
    for (int s = 0; s < 2; s++) {
        const __half* Ac = Ab + s * 64;
        const __half* Bc = Bb + s * 64;
        unsigned so = s * STAGEB;
        #pragma unroll
        for (int i = 0; i < 4; i++) {
            CP16(cdst[i] + so,         Ac + (size_t)crow[i] * Kd + cseg[i] * 8);
            CP16(cdst[i] + so + TILEB, Bc + (size_t)crow[i] * Kd + cseg[i] * 8);
        }
        CP_COMMIT();
    }

    int p = 0, pn = 2;
    for (int c = 0; c < nk; c++) {
        CP_WAIT1();
        __syncthreads();

        if (c + 2 < nk) {
            const __half* Ac = Ab + (c + 2) * 64;
            const __half* Bc = Bb + (c + 2) * 64;
            unsigned so = pn * STAGEB;
            #pragma unroll
            for (int i = 0; i < 4; i++) {
                CP16(cdst[i] + so,         Ac + (size_t)crow[i] * Kd + cseg[i] * 8);
                CP16(cdst[i] + so + TILEB, Bc + (size_t)crow[i] * Kd + cseg[i] * 8);
            }
        }
        CP_COMMIT();

        unsigned Asu = smu + p * STAGEB + (unsigned)(wm * 64) * ROWB + aoff;
        unsigned Bsu = smu + p * STAGEB + TILEB + (unsigned)(wn * 32) * ROWB + boff;

        #pragma unroll
        for (int ks = 0; ks < 4; ks++) {
            unsigned kb = ks * 32;
            unsigned afr[4][4], bfr[4][2];
            #pragma unroll
            for (int mi = 0; mi < 4; mi++)
                ldsm_x4(afr[mi][0], afr[mi][1], afr[mi][2], afr[mi][3],
                        Asu + mi * (16 * ROWB) + kb);
            #pragma unroll
            for (int pr = 0; pr < 2; pr++)
                ldsm_x4(bfr[2*pr][0], bfr[2*pr][1], bfr[2*pr+1][0], bfr[2*pr+1][1],
                        Bsu + pr * (16 * ROWB) + kb);
            #pragma unroll
            for (int mi = 0; mi < 4; mi++)
                #pragma unroll
                for (int ni = 0; ni < 4; ni++)
                    mma_f16(acc[mi][ni], afr[mi], bfr[ni]);
        }
        p = (p == 2) ? 0 : p + 1;
        pn = (pn == 2) ? 0 : pn + 1;
    }
    CP_WAIT0();
    __syncthreads();

    float* stage = (float*)sm;
    #pragma unroll
    for (int mi = 0; mi < 4; mi++)
        #pragma unroll
        for (int ni = 0; ni < 4; ni++) {
            int row = wm * 64 + mi * 16 + (lane >> 2);
            int col = wn * 32 + ni * 8 + (lane & 3) * 2;
            *(float2*)(stage + row * 132 + col) =
                make_float2(acc[mi][ni][0], acc[mi][ni][1]);
            *(float2*)(stage + (row + 8) * 132 + col) =
                make_float2(acc[mi][ni][2], acc[mi][ni][3]);
        }
    __syncthreads();

    #pragma unroll
    for (int i = 0; i < 16; i++) {
        int u = tid + 256 * i;
        int row = u >> 5, c4 = u & 31;
        float4 v = *(const float4*)(stage + row * 132 + c4 * 4);
        float vv[4] = {v.x, v.y, v.z, v.w};

        if (EPI == 5) {
            if (c0 < 2048) {
                size_t base = (size_t)(r0 + row) * 2048 + c0 + c4 * 4;
                __half2 p0 = __floats2half2_rn(vv[0], vv[1]);
                __half2 p1 = __floats2half2_rn(vv[2], vv[3]);
                uint2 w;
                w.x = *(unsigned*)&p0; w.y = *(unsigned*)&p1;
                *(uint2*)((__half*)Cv2 + base) = w;
            } else {
                size_t base = (size_t)(r0 + row) * 1024 + (c0 - 2048) + c4 * 4;
                __half2 p0 = __floats2half2_rn(vv[0], vv[1]);
                __half2 p1 = __floats2half2_rn(vv[2], vv[3]);
                uint2 w;
                w.x = *(unsigned*)&p0; w.y = *(unsigned*)&p1;
                *(uint2*)((__half*)Cv + base) = w;
            }
            continue;
        }

        size_t base = (size_t)(r0 + row) * NC + c0 + c4 * 4;
        #pragma unroll
        for (int j = 0; j < 4; j++) {
            int col = c0 + c4 * 4 + j;
            if (EPI == 1) vv[j] += Rf[base + j];
            else if (EPI == 2) {
                float t = vv[j] + bias[col];
                vv[j] = 0.5f * t * (1.0f + erff(t * 0.70710678118654752f));
            } else if (EPI == 3) vv[j] += bias[col] + __half2float(Rh[base + j]);
        }
        if (EPI == 0 || EPI == 2) {
            __half2 p0 = __floats2half2_rn(vv[0], vv[1]);
            __half2 p1 = __floats2half2_rn(vv[2], vv[3]);
            uint2 w;
            w.x = *(unsigned*)&p0; w.y = *(unsigned*)&p1;
            *(uint2*)((__half*)Cv + base) = w;
        } else {
            *(float4*)((float*)Cv + base) = make_float4(vv[0], vv[1], vv[2], vv[3]);
        }
    }
}

// ---------------- batched transpose + round to half (4x 1024x1024) ----------
__global__ void transpose4_k(const float* __restrict__ i0, const float* __restrict__ i1,
                             const float* __restrict__ i2, const float* __restrict__ i3,
                             __half* __restrict__ o0, __half* __restrict__ o1,
                             __half* __restrict__ o2, __half* __restrict__ o3)
{
    const float* in = (blockIdx.z == 0) ? i0 : (blockIdx.z == 1) ? i1 :
                      (blockIdx.z == 2) ? i2 : i3;
    __half* out = (blockIdx.z == 0) ? o0 : (blockIdx.z == 1) ? o1 :
                  (blockIdx.z == 2) ? o2 : o3;
    __shared__ float t[32][33];
    int x = blockIdx.x * 32 + threadIdx.x;
    int y = blockIdx.y * 32 + threadIdx.y;
    #pragma unroll
    for (int j = 0; j < 4; j++)
        t[threadIdx.y + j * 8][threadIdx.x] = in[(size_t)(y + j * 8) * 1024 + x];
    __syncthreads();
    int ox = blockIdx.y * 32 + threadIdx.x;
    int oy = blockIdx.x * 32 + threadIdx.y;
    #pragma unroll
    for (int j = 0; j < 4; j++)
        out[(size_t)(oy + j * 8) * 1024 + ox] = __float2half_rn(t[threadIdx.x][threadIdx.y + j * 8]);
}

__global__ void transpose_k(const float* __restrict__ in, __half* __restrict__ out,
                            int R, int Cc)
{
    __shared__ float t[32][33];
    int x = blockIdx.x * 32 + threadIdx.x;
    int y = blockIdx.y * 32 + threadIdx.y;
    #pragma unroll
    for (int j = 0; j < 4; j++)
        t[threadIdx.y + j * 8][threadIdx.x] = in[(size_t)(y + j * 8) * Cc + x];
    __syncthreads();
    int ox = blockIdx.y * 32 + threadIdx.x;
    int oy = blockIdx.x * 32 + threadIdx.y;
    #pragma unroll
    for (int j = 0; j < 4; j++)
        out[(size_t)(oy + j * 8) * R + ox] = __float2half_rn(t[threadIdx.x][threadIdx.y + j * 8]);
}

__global__ void cvt_half_kernel(const float* __restrict__ in, __half* __restrict__ out, int n8)
{
    int i = blockIdx.x * blockDim.x + threadIdx.x;
    if (i < n8) {
        float4 a = ((const float4*)in)[2 * i];
        float4 b = ((const float4*)in)[2 * i + 1];
        __half2 h0 = __floats2half2_rn(a.x, a.y);
        __half2 h1 = __floats2half2_rn(a.z, a.w);
        __half2 h2 = __floats2half2_rn(b.x, b.y);
        __half2 h3 = __floats2half2_rn(b.z, b.w);
        uint4 w;
        w.x = *(unsigned*)&h0; w.y = *(unsigned*)&h1;
        w.z = *(unsigned*)&h2; w.w = *(unsigned*)&h3;
        ((uint4*)out)[i] = w;
    }
}

// ---------------- tensorized FAVOR+ (fp16 MMA), fused q+k launch -------------
#define PHSTR 72
#define PHI_A_OFF 0
#define PHI_B_OFF (128 * PHSTR * 2)                 // 18432
#define PHI_STAGE_W 260
#define PHI_SQ_OFF  (128 * PHI_STAGE_W * 4)         // 133120
#define PHI_SM      (PHI_SQ_OFF + 128 * 4)          // 133632

__global__ __launch_bounds__(512, 1)
void phi_mma(const __half* __restrict__ qk, const float* __restrict__ omega,
             __half* __restrict__ pqd, __half* __restrict__ pkd)
{
    extern __shared__ char sm[];
    __half* As = (__half*)(sm + PHI_A_OFF);
    __half* Bs = (__half*)(sm + PHI_B_OFF);
    float* stage = (float*)sm;
    float* sqv   = (float*)(sm + PHI_SQ_OFF);

    int tid = threadIdx.x, wid = tid >> 5, lane = tid & 31;
    int outh = (blockIdx.x < 2048) ? 1 : 0;
    int rbase = (blockIdx.x & 2047) * 128;
    const __half* src = qk + (outh ? 0 : 1024);
    __half* dst = outh ? pqd : pkd;

    {
        int row = tid >> 2, qtr = tid & 3;
        int r = rbase + row, n = r >> 4, h = r & 15;
        const __half2* s2 = (const __half2*)(src + (size_t)n * 2048 + h * 64 + qtr * 16);
        unsigned outw[8];
        float ps = 0.f;
        #pragma unroll
        for (int j = 0; j < 8; j++) {
            float2 f = __half22float2(s2[j]);
            __half2 hh = __floats2half2_rn(f.x * PHI_SCALE, f.y * PHI_SCALE);
            float2 fr = __half22float2(hh);
            ps += fr.x * fr.x + fr.y * fr.y;
            outw[j] = *(unsigned*)&hh;
        }
        __half* dstA = As + row * PHSTR + qtr * 16;
        *(uint4*)(dstA)     = make_uint4(outw[0], outw[1], outw[2], outw[3]);
        *(uint4*)(dstA + 8) = make_uint4(outw[4], outw[5], outw[6], outw[7]);
        ps += __shfl_xor_sync(0xFFFFFFFFu, ps, 1);
        ps += __shfl_xor_sync(0xFFFFFFFFu, ps, 2);
        if (qtr == 0) sqv[row] = 0.5f * ps;
    }
    {
        int m = tid >> 1, hf = tid & 1;
        const float* orow = omega + m * 64 + hf * 32;
        #pragma unroll
        for (int j = 0; j < 4; j++) {
            float4 a = ((const float4*)orow)[2 * j];
            float4 b = ((const float4*)orow)[2 * j + 1];
            __half2 h0 = __floats2half2_rn(a.x, a.y);
            __half2 h1 = __floats2half2_rn(a.z, a.w);
            __half2 h2 = __floats2half2_rn(b.x, b.y);
            __half2 h3 = __floats2half2_rn(b.z, b.w);
            uint4 w;
            w.x = *(unsigned*)&h0; w.y = *(unsigned*)&h1;
            w.z = *(unsigned*)&h2; w.w = *(unsigned*)&h3;
            *(uint4*)(Bs + m * PHSTR + hf * 32 + j * 8) = w;
        }
    }
    __syncthreads();

    float acc[2][8][4];
    #pragma unroll
    for (int mi = 0; mi < 2; mi++)
        #pragma unroll
        for (int ni = 0; ni < 8; ni++)
            #pragma unroll
            for (int j = 0; j < 4; j++) acc[mi][ni][j] = 0.f;

    int c2 = (lane & 3) * 2;
    int mrow = (wid & 3) * 32 + (lane >> 2);
    int nrow = (wid >> 2) * 64 + (lane >> 2);

    #pragma unroll
    for (int ks = 0; ks < 4; ks++) {
        int kk = ks * 16 + c2;
        unsigned afr[2][4], bfr[8][2];
        #pragma unroll
        for (int mi = 0; mi < 2; mi++) {
            const __half* ap = As + (mrow + mi * 16) * PHSTR + kk;
            afr[mi][0] = *(const unsigned*)(ap);
            afr[mi][1] = *(const unsigned*)(ap + 8 * PHSTR);
            afr[mi][2] = *(const unsigned*)(ap + 8);
            afr[mi][3] = *(const unsigned*)(ap + 8 * PHSTR + 8);
        }
        #pragma unroll
        for (int ni = 0; ni < 8; ni++) {
            const __half* bp = Bs + (nrow + ni * 8) * PHSTR + kk;
            bfr[ni][0] = *(const unsigned*)(bp);
            bfr[ni][1] = *(const unsigned*)(bp + 8);
        }
        #pragma unroll
        for (int mi = 0; mi < 2; mi++)
            #pragma unroll
            for (int ni = 0; ni < 8; ni++)
                mma_f16(acc[mi][ni], afr[mi], bfr[ni]);
    }
    __syncthreads();

    #pragma unroll
    for (int mi = 0; mi < 2; mi++)
        #pragma unroll
        for (int ni = 0; ni < 8; ni++) {
            int row = (wid & 3) * 32 + mi * 16 + (lane >> 2);
            int col = (wid >> 2) * 64 + ni * 8 + (lane & 3) * 2;
            *(float2*)(stage + row * PHI_STAGE_W + col) =
                make_float2(acc[mi][ni][0], acc[mi][ni][1]);
            *(float2*)(stage + (row + 8) * PHI_STAGE_W + col) =
                make_float2(acc[mi][ni][2], acc[mi][ni][3]);
        }
    __syncthreads();

    {
        int row = tid >> 2, seg = (tid & 3) * 64;
        const float* srow = stage + row * PHI_STAGE_W + seg;
        float mx = -1e30f;
        #pragma unroll
        for (int j = 0; j < 16; j++) {
            float4 v = ((const float4*)srow)[j];
            mx = fmaxf(mx, fmaxf(fmaxf(v.x, v.y), fmaxf(v.z, v.w)));
        }
        mx = fmaxf(mx, __shfl_xor_sync(0xFFFFFFFFu, mx, 1));
        mx = fmaxf(mx, __shfl_xor_sync(0xFFFFFFFFu, mx, 2));
        float sb = sqv[row] + mx;

        int r = rbase + row, n = r >> 4, h = r & 15;
        int b = n >> 12, s = n & 4095;
        size_t rowoff = (((size_t)(b * H_N + h)) * S_LEN + s) * M_F + seg;
        #pragma unroll
        for (int j = 0; j < 16; j++) {
            float4 v = ((const float4*)srow)[j];
            __half2 p0 = __floats2half2_rn(__expf(v.x - sb) * RSQRT_M + 1e-6f,
                                           __expf(v.y - sb) * RSQRT_M + 1e-6f);
            __half2 p1 = __floats2half2_rn(__expf(v.z - sb) * RSQRT_M + 1e-6f,
                                           __expf(v.w - sb) * RSQRT_M + 1e-6f);
            uint2 w;
            w.x = *(unsigned*)&p0; w.y = *(unsigned*)&p1;
            *(uint2*)(dst + rowoff + j * 4) = w;
        }
    }
}

// ---------------- fp16 kv: partial[blk][m][72] = pk^T @ [v | 1] --------------
#define KV_PSTR  264
#define KV_VSTR  88
#define KV_PKB   (32 * KV_PSTR * 2)      // 16896
#define KV_VB    (32 * KV_VSTR * 2)      // 5632
#define KV_STAGE (KV_PKB + KV_VB)        // 22528
#define KV_SM    (2 * KV_STAGE)          // 45056

__global__ __launch_bounds__(256, 2)
void kv_mma(const __half* __restrict__ pk, const __half* __restrict__ v,
            float* __restrict__ partial)
{
    extern __shared__ char sm[];
    unsigned smu = smem_u32(sm);
    int tid = threadIdx.x, wid = tid >> 5, lane = tid & 31;
    int bh = blockIdx.x >> 3, chunk = blockIdx.x & 7;
    int b = bh >> 4, h = bh & 15;
    int s0 = chunk * 512;

    const __half* pkb = pk + ((size_t)bh * S_LEN + s0) * M_F;
    const __half* vb  = v + ((size_t)(b * S_LEN + s0)) * D_MOD + h * 64;

    for (int i = tid; i < 32 * 16 * 2; i += 256) {
        int st = i >> 9, r = (i & 511) >> 4, cc = (i & 15) + 64;
        ((__half*)(sm + st * KV_STAGE + KV_PKB))[r * KV_VSTR + cc] =
            (cc == 64) ? __float2half(1.f) : __float2half(0.f);
    }
    __syncthreads();

    auto issue_copy = [&](int cc, int st) {
        unsigned base = smu + st * KV_STAGE;
        #pragma unroll
        for (int i2 = 0; i2 < 4; i2++) {
            int j = tid + 256 * i2;
            int row = j >> 5, seg = j & 31;
            CP16(base + (unsigned)(row * (KV_PSTR * 2) + seg * 16),
                 pkb + (size_t)(cc * 32 + row) * M_F + seg * 8);
        }
        {
            int row = tid >> 3, seg = tid & 7;
            CP16(base + KV_PKB + (unsigned)(row * (KV_VSTR * 2) + seg * 16),
                 vb + (size_t)(cc * 32 + row) * D_MOD + seg * 8);
        }
    };

    float acc[4][5][4];
    #pragma unroll
    for (int mi = 0; mi < 4; mi++)
        #pragma unroll
        for (int ni = 0; ni < 5; ni++)
            #pragma unroll
            for (int j = 0; j < 4; j++) acc[mi][ni][j] = 0.f;

    issue_copy(0, 0); CP_COMMIT();
    issue_copy(1, 1); CP_COMMIT();

    int mbase = (wid & 3) * 64 + (lane >> 2);
    int nbase = (wid >> 2) * 40 + (lane >> 2);

    for (int c = 0; c < 16; c++) {
        int p = c & 1;
        CP_WAIT1();
        __syncthreads();

        const __half* As = (const __half*)(sm + p * KV_STAGE);
        const __half* Vs = (const __half*)(sm + p * KV_STAGE + KV_PKB);

        #pragma unroll
        for (int ks = 0; ks < 2; ks++) {
            int k0 = ks * 16 + (lane & 3) * 2;
            unsigned afr[4][4], bfr[5][2];
            #pragma unroll
            for (int mi = 0; mi < 4; mi++) {
                int m = mbase + mi * 16;
                afr[mi][0] = pk2(As + k0 * KV_PSTR + m, KV_PSTR);
                afr[mi][1] = pk2(As + k0 * KV_PSTR + m + 8, KV_PSTR);
                afr[mi][2] = pk2(As + (k0 + 8) * KV_PSTR + m, KV_PSTR);
                afr[mi][3] = pk2(As + (k0 + 8) * KV_PSTR + m + 8, KV_PSTR);
            }
            #pragma unroll
            for (int ni = 0; ni < 5; ni++) {
                int n = nbase + ni * 8;
                bfr[ni][0] = pk2(Vs + k0 * KV_VSTR + n, KV_VSTR);
                bfr[ni][1] = pk2(Vs + (k0 + 8) * KV_VSTR + n, KV_VSTR);
            }
            #pragma unroll
            for (int mi = 0; mi < 4; mi++)
                #pragma unroll
                for (int ni = 0; ni < 5; ni++)
                    mma_f16(acc[mi][ni], afr[mi], bfr[ni]);
        }
        __syncthreads();

        if (c + 2 < 16) issue_copy(c + 2, p);
        CP_COMMIT();
    }

    float* pb = partial + (size_t)blockIdx.x * (256 * 72);
    #pragma unroll
    for (int mi = 0; mi < 4; mi++)
        #pragma unroll
        for (int ni = 0; ni < 5; ni++) {
            int row = (wid & 3) * 64 + mi * 16 + (lane >> 2);
            int col = (wid >> 2) * 40 + ni * 8 + (lane & 3) * 2;
            if (col < 64) {
                *(float2*)(pb + row * 72 + col) =
                    make_float2(acc[mi][ni][0], acc[mi][ni][1]);
                *(float2*)(pb + (row + 8) * 72 + col) =
                    make_float2(acc[mi][ni][2], acc[mi][ni][3]);
            } else if (col == 64) {
                pb[row * 72 + 64] = acc[mi][ni][0];
                pb[(row + 8) * 72 + 64] = acc[mi][ni][2];
            }
        }
}

__global__ void kv_reduce(const float* __restrict__ partial,
                          float* __restrict__ kv, float* __restrict__ z)
{
    int bh = blockIdx.x;
    for (int j = threadIdx.x; j < 256 * 72; j += 256) {
        float s = 0.f;
        #pragma unroll
        for (int c = 0; c < 8; c++)
            s += partial[((size_t)(bh * 8 + c)) * (256 * 72) + j];
        int m = j / 72, k2 = j - m * 72;
        if (k2 < 64) kv[(size_t)bh * (M_F * HK) + m * 64 + k2] = s;
        else if (k2 == 64) z[bh * M_F + m] = s;
    }
}

// ---------------- fp16 num/den: attn = (pq @ kv) / (pq @ z) ------------------
#define ND_BSTR  264
#define ND_B_OFF 0
#define ND_Z_OFF (64 * ND_BSTR * 2)              // 33792
#define ND_A_OFF (ND_Z_OFF + 1024)               // 34816
#define ND_SM    (ND_A_OFF + 2 * TILEB)          // 71680

__global__ __launch_bounds__(256, 2)
void numden_mma(const __half* __restrict__ pq, const float* __restrict__ kvg,
                const float* __restrict__ zg, __half* __restrict__ attn)
{
    extern __shared__ char sm[];
    unsigned smu = smem_u32(sm);
    __half* Bsf  = (__half*)(sm + ND_B_OFF);
    float* z_s   = (float*)(sm + ND_Z_OFF);
    float* den_s = (float*)(sm + ND_B_OFF);      // aliases Bs after MMA
    float* stage = (float*)(sm + ND_A_OFF);      // aliases As after MMA

    int bh = blockIdx.x >> 5;
    int chunk = blockIdx.x & 31;
    int b = bh >> 4, h = bh & 15;
    int tid = threadIdx.x, wid = tid >> 5, lane = tid & 31;
    int s0 = chunk * 128;

    const __half* pqb = pq + ((size_t)bh * S_LEN + s0) * M_F;

    int arow[4], aseg[4];
    unsigned adst[4];
    #pragma unroll
    for (int i = 0; i < 4; i++) {
        int u = tid + 256 * i;
        arow[i] = u >> 3; aseg[i] = u & 7;
        adst[i] = smu + ND_A_OFF + (unsigned)(arow[i] * ROWB + aseg[i] * 16);
    }

    #pragma unroll
    for (int s = 0; s < 2; s++) {
        const __half* Ac = pqb + s * 64;
        unsigned so = s * TILEB;
        #pragma unroll
        for (int i = 0; i < 4; i++)
            CP16(adst[i] + so, Ac + (size_t)arow[i] * M_F + aseg[i] * 8);
        CP_COMMIT();
    }

    {
        const float* kvb = kvg + (size_t)bh * (M_F * HK);
        for (int i = tid; i < M_F * HK; i += 256) {
            int m = i >> 6, k = i & 63;
            Bsf[k * ND_BSTR + m] = __float2half_rn(kvb[i]);
        }
        z_s[tid] = zg[bh * M_F + tid];
    }

    float acc[2][4][4];
    #pragma unroll
    for (int mi = 0; mi < 2; mi++)
        #pragma unroll
        for (int ni = 0; ni < 4; ni++)
            #pragma unroll
            for (int j = 0; j < 4; j++) acc[mi][ni][j] = 0.f;

    int c2 = (lane & 3) * 2;
    int mrow = (wid & 3) * 32 + (lane >> 2);
    int nrow = (wid >> 2) * 32 + (lane >> 2);
    int drow = tid >> 1, dhf = tid & 1;
    float dp = 0.f;

    for (int c = 0; c < 4; c++) {
        int p = c & 1;
        CP_WAIT1();
        __syncthreads();

        const __half* As = (const __half*)(sm + ND_A_OFF + p * TILEB);
        #pragma unroll
        for (int ks = 0; ks < 4; ks++) {
            int kk = ks * 16 + c2;
            unsigned afr[2][4], bfr[4][2];
            #pragma unroll
            for (int mi = 0; mi < 2; mi++) {
                const __half* ap = As + (mrow + mi * 16) * HSTR + kk;
                afr[mi][0] = *(const unsigned*)(ap);
                afr[mi][1] = *(const unsigned*)(ap + 8 * HSTR);
                afr[mi][2] = *(const unsigned*)(ap + 8);
                afr[mi][3] = *(const unsigned*)(ap + 8 * HSTR + 8);
            }
            #pragma unroll
            for (int ni = 0; ni < 4; ni++) {
                const __half* bp = Bsf + (nrow + ni * 8) * ND_BSTR + c * 64 + kk;
                bfr[ni][0] = *(const unsigned*)(bp);
                bfr[ni][1] = *(const unsigned*)(bp + 8);
            }
            #pragma unroll
            for (int mi = 0; mi < 2; mi++)
                #pragma unroll
                for (int ni = 0; ni < 4; ni++)
                    mma_f16(acc[mi][ni], afr[mi], bfr[ni]);
        }

        {
            const __half* ar = As + drow * HSTR + dhf * 32;
            const float* zr = z_s + c * 64 + dhf * 32;
            #pragma unroll
            for (int j = 0; j < 16; j++) {
                float2 f = __half22float2(*(const __half2*)(ar + 2 * j));
                dp += f.x * zr[2 * j] + f.y * zr[2 * j + 1];
            }
        }
        __syncthreads();

        if (c + 2 < 4) {
            const __half* Ac = pqb + (c + 2) * 64;
            unsigned so = p * TILEB;
            #pragma unroll
            for (int i = 0; i < 4; i++)
                CP16(adst[i] + so, Ac + (size_t)arow[i] * M_F + aseg[i] * 8);
        }
        CP_COMMIT();
    }
    CP_WAIT0();
    __syncthreads();

    #pragma unroll
    for (int mi = 0; mi < 2; mi++)
        #pragma unroll
        for (int ni = 0; ni < 4; ni++) {
            int row = (wid & 3) * 32 + mi * 16 + (lane >> 2);
            int col = (wid >> 2) * 32 + ni * 8 + (lane & 3) * 2;
            *(float2*)(stage + row * 68 + col) =
                make_float2(acc[mi][ni][0], acc[mi][ni][1]);
            *(float2*)(stage + (row + 8) * 68 + col) =
                make_float2(acc[mi][ni][2], acc[mi][ni][3]);
        }

    dp += __shfl_xor_sync(0xFFFFFFFFu, dp, 1);
    if (dhf == 0) den_s[drow] = dp;
    __syncthreads();

    #pragma unroll
    for (int i = 0; i < 8; i++) {
        int u = tid + 256 * i;
        int row = u >> 4, c4 = u & 15;
        float4 v = *(const float4*)(stage + row * 68 + c4 * 4);
        float rd = 1.0f / den_s[row];
        __half2 p0 = __floats2half2_rn(v.x * rd, v.y * rd);
        __half2 p1 = __floats2half2_rn(v.z * rd, v.w * rd);
        uint2 w;
        w.x = *(unsigned*)&p0; w.y = *(unsigned*)&p1;
        *(uint2*)(attn + ((size_t)(b * S_LEN + s0 + row)) * D_MOD + h * 64 + c4 * 4) = w;
    }
}

// ---------------- LayerNorm (OUTHALF: write half) ----------------
template<int OUTHALF>
__global__ void ln_kernel(const float* __restrict__ X, const float* __restrict__ g,
                          const float* __restrict__ bv, void* __restrict__ outv)
{
    int row = blockIdx.x, tid = threadIdx.x;
    float4 v = ((const float4*)(X + (size_t)row * D_MOD))[tid];
    float s = v.x + v.y + v.z + v.w;
    __shared__ float ws[8];
    #pragma unroll
    for (int o = 16; o; o >>= 1) s += __shfl_xor_sync(0xFFFFFFFFu, s, o);
    if ((tid & 31) == 0) ws[tid >> 5] = s;
    __syncthreads();
    float tot = 0.f;
    #pragma unroll
    for (int w = 0; w < 8; w++) tot += ws[w];
    float mu = tot * (1.f / 1024.f);
    float dx = v.x - mu, dy = v.y - mu, dz = v.z - mu, dw = v.w - mu;
    float sqvv = dx*dx + dy*dy + dz*dz + dw*dw;
    __syncthreads();
    #pragma unroll
    for (int o = 16; o; o >>= 1) sqvv += __shfl_xor_sync(0xFFFFFFFFu, sqvv, o);
    if ((tid & 31) == 0) ws[tid >> 5] = sqvv;
    __syncthreads();
    float tot2 = 0.f;
    #pragma unroll
    for (int w = 0; w < 8; w++) tot2 += ws[w];
    float rs = rsqrtf(tot2 * (1.f / 1024.f) + 1e-6f);
    float4 gg = ((const float4*)g)[tid];
    float4 bb = ((const float4*)bv)[tid];
    float o0 = dx*rs*gg.x + bb.x, o1 = dy*rs*gg.y + bb.y;
    float o2 = dz*rs*gg.z + bb.z, o3 = dw*rs*gg.w + bb.w;
    if (OUTHALF) {
        __half2 p0 = __floats2half2_rn(o0, o1);
        __half2 p1 = __floats2half2_rn(o2, o3);
        uint2 w;
        w.x = *(unsigned*)&p0; w.y = *(unsigned*)&p1;
        *(uint2*)((__half*)outv + (size_t)row * D_MOD + tid * 4) = w;
    } else {
        ((float4*)((float*)outv + (size_t)row * D_MOD))[tid] =
            make_float4(o0, o1, o2, o3);
    }
}

// ---------------- orchestration ----------------
extern "C" void kernel_launch(void* const* d_in, const int* in_sizes, int n_in,
                              void* d_out, int out_size)
{
    const float* x     = (const float*)d_in[0];
    const float* wq    = (const float*)d_in[1];
    const float* wk    = (const float*)d_in[2];
    const float* wv    = (const float*)d_in[3];
    const float* wo    = (const float*)d_in[4];
    const float* omega = (const float*)d_in[5];
    const float* ln1g  = (const float*)d_in[6];
    const float* ln1b  = (const float*)d_in[7];
    const float* w1    = (const float*)d_in[8];
    const float* b1    = (const float*)d_in[9];
    const float* w2    = (const float*)d_in[10];
    const float* b2    = (const float*)d_in[11];
    const float* ln2g  = (const float*)d_in[12];
    const float* ln2b  = (const float*)d_in[13];
    float* out = (float*)d_out;

    __half *qk, *v, *xr, *pq, *pk, *attn, *x1, *act;
    float *kv, *z, *kvp, *y;
    __half *wqkvT, *woT, *w1T, *w2T;
    cudaGetSymbolAddress((void**)&qk,   g_qk);
    cudaGetSymbolAddress((void**)&v,    g_v);
    cudaGetSymbolAddress((void**)&xr,   g_xr);
    cudaGetSymbolAddress((void**)&pq,   g_pq);
    cudaGetSymbolAddress((void**)&pk,   g_pk);
    cudaGetSymbolAddress((void**)&kv,   g_kv);
    cudaGetSymbolAddress((void**)&z,    g_z);
    cudaGetSymbolAddress((void**)&kvp,  g_kvp);
    cudaGetSymbolAddress((void**)&attn, g_attn);
    cudaGetSymbolAddress((void**)&y,    g_y);
    cudaGetSymbolAddress((void**)&x1,   g_x1);
    cudaGetSymbolAddress((void**)&act,  g_act);
    cudaGetSymbolAddress((void**)&wqkvT, g_wqkvT);
    cudaGetSymbolAddress((void**)&woT,  g_woT);
    cudaGetSymbolAddress((void**)&w1T,  g_w1T);
    cudaGetSymbolAddress((void**)&w2T,  g_w2T);

    cudaFuncSetAttribute(numden_mma, cudaFuncAttributeMaxDynamicSharedMemorySize, ND_SM);
    cudaFuncSetAttribute(phi_mma, cudaFuncAttributeMaxDynamicSharedMemorySize, PHI_SM);
    cudaFuncSetAttribute(kv_mma, cudaFuncAttributeMaxDynamicSharedMemorySize, KV_SM);
    cudaFuncSetAttribute(tc_gemm<1>, cudaFuncAttributeMaxDynamicSharedMemorySize, SM_DYN);
    cudaFuncSetAttribute(tc_gemm<2>, cudaFuncAttributeMaxDynamicSharedMemorySize, SM_DYN);
    cudaFuncSetAttribute(tc_gemm<3>, cudaFuncAttributeMaxDynamicSharedMemorySize, SM_DYN);
    cudaFuncSetAttribute(tc_gemm<5>, cudaFuncAttributeMaxDynamicSharedMemorySize, SM_DYN);

    dim3 tb(32, 8);
    transpose4_k<<<dim3(32, 32, 4), tb>>>(wq, wk, wv, wo,
        wqkvT, wqkvT + 1024 * 1024, wqkvT + 2 * 1024 * 1024, woT);
    transpose_k<<<dim3(128, 32),  tb>>>(w1, w1T, 1024, 4096);
    transpose_k<<<dim3(32, 128),  tb>>>(w2, w2T, 4096, 1024);
    cvt_half_kernel<<<(N_TOK * D_MOD / 8 + 255) / 256, 256>>>(x, xr, N_TOK * D_MOD / 8);

    dim3 gQKV(3072 / 128, N_TOK / 128);  // (24, 128)
    dim3 gD(D_MOD / 128, N_TOK / 128);   // (8, 128)
    dim3 gF(FF_D / 128, N_TOK / 128);    // (32, 128)

    tc_gemm<5><<<gQKV, 256, SM_DYN>>>(xr, wqkvT, nullptr, nullptr, nullptr,
                                      v, qk, D_MOD, 3072);

    phi_mma<<<4096, 512, PHI_SM>>>(qk, omega, pq, pk);

    kv_mma<<<512, 256, KV_SM>>>(pk, v, kvp);
    kv_reduce<<<64, 256>>>(kvp, kv, z);

    numden_mma<<<2048, 256, ND_SM>>>(pq, kv, z, attn);

    tc_gemm<1><<<gD, 256, SM_DYN>>>(attn, woT, nullptr, x, nullptr, y, nullptr,
                                    D_MOD, D_MOD);
    ln_kernel<1><<<N_TOK, 256>>>(y, ln1g, ln1b, x1);

    tc_gemm<2><<<gF, 256, SM_DYN>>>(x1, w1T, b1, nullptr, nullptr, act, nullptr,
                                    D_MOD, FF_D);
    tc_gemm<3><<<gD, 256, SM_DYN>>>(act, w2T, b2, nullptr, x1, y, nullptr,
                                    FF_D, D_MOD);
    ln_kernel<0><<<N_TOK, 256>>>(y, ln2g, ln2b, out);
}